// round 4
// baseline (speedup 1.0000x reference)
#include <cuda_runtime.h>
#include <math.h>
#include <stdint.h>

#define Bb 4
#define Ss 1024
#define Hh 1024
#define NHh 16
#define Dd 64
#define Pp 1024

#define INV_SCALE 0.07216878364870322f

/* ------------------------- scratch ------------------------- */
__device__ float g_Q[(size_t)Bb * NHh * Ss * Dd];
__device__ float g_K[(size_t)Bb * NHh * Ss * Dd];
__device__ float g_VT[(size_t)Bb * NHh * Dd * Ss];   /* [bh][d][s] */
__device__ float g_PK[(size_t)NHh * Pp * Dd];
__device__ float g_PQ[(size_t)NHh * Pp * Dd];
__device__ float g_CTX[(size_t)Bb * Ss * Hh];
__device__ float g_Y[(size_t)Bb * Ss * Hh];
__device__ float g_HS[(size_t)Bb * Ss * Hh];
__device__ float g_RE[(size_t)Pp * Hh];
__device__ float g_WINT[(size_t)3 * Hh * Hh];
__device__ float g_WPKT[(size_t)Hh * Hh];
__device__ float g_WPQT[(size_t)Hh * Hh];
__device__ float g_WOT[(size_t)Hh * Hh];

/* ------------------------- helpers ------------------------- */
__device__ __forceinline__ float tf32r(float x) {
    uint32_t u;
    asm("cvt.rna.tf32.f32 %0, %1;" : "=r"(u) : "f"(x));
    return __uint_as_float(u);
}
__device__ __forceinline__ void cp16(uint32_t dst, const void* src) {
    asm volatile("cp.async.cg.shared.global [%0], [%1], 16;" :: "r"(dst), "l"(src));
}
__device__ __forceinline__ void cp_commit() { asm volatile("cp.async.commit_group;"); }
template <int N> __device__ __forceinline__ void cp_wait() {
    asm volatile("cp.async.wait_group %0;" :: "n"(N));
}
__device__ __forceinline__ void ldsm4(uint32_t a[4], uint32_t addr) {
    asm volatile("ldmatrix.sync.aligned.m8n8.x4.shared.b16 {%0,%1,%2,%3}, [%4];"
                 : "=r"(a[0]), "=r"(a[1]), "=r"(a[2]), "=r"(a[3]) : "r"(addr));
}
__device__ __forceinline__ void ldsm2(uint32_t b[2], uint32_t addr) {
    asm volatile("ldmatrix.sync.aligned.m8n8.x2.shared.b16 {%0,%1}, [%2];"
                 : "=r"(b[0]), "=r"(b[1]) : "r"(addr));
}
__device__ __forceinline__ void mma8(float c[4], const uint32_t a[4], const uint32_t b[2]) {
    asm volatile(
        "mma.sync.aligned.m16n8k8.row.col.f32.tf32.tf32.f32 "
        "{%0,%1,%2,%3}, {%4,%5,%6,%7}, {%8,%9}, {%0,%1,%2,%3};"
        : "+f"(c[0]), "+f"(c[1]), "+f"(c[2]), "+f"(c[3])
        : "r"(a[0]), "r"(a[1]), "r"(a[2]), "r"(a[3]), "r"(b[0]), "r"(b[1]));
}

#define SW_OFF(row, c) ((((row) << 4) + (((c) & 8) | (((c) & 7) ^ ((row) & 7)))) << 4)

/* ------------------------- prep kernels (merged) ------------------------- */
__global__ void __launch_bounds__(256) k_round2(const float* __restrict__ hs,
                                                const float* __restrict__ re) {
    int bx = blockIdx.x;
    const float* src;
    float* dst;
    size_t i;
    if (bx < 4096) { src = hs; dst = g_HS; i = ((size_t)bx * 256 + threadIdx.x) * 4; }
    else { src = re; dst = g_RE; i = ((size_t)(bx - 4096) * 256 + threadIdx.x) * 4; }
    float4 v = *(const float4*)(src + i);
    v.x = tf32r(v.x); v.y = tf32r(v.y); v.z = tf32r(v.z); v.w = tf32r(v.w);
    *(float4*)(dst + i) = v;
}

/* src [K=1024][N] -> dst [N][1024] rounded; z picks the matrix/slice */
__global__ void __launch_bounds__(256) k_transp2(const float* __restrict__ w_in,
                                                 const float* __restrict__ w_pk,
                                                 const float* __restrict__ w_pq,
                                                 const float* __restrict__ w_o) {
    int z = blockIdx.z;
    const float* src;
    float* dst;
    int N, nbase;
    if (z < 3) { src = w_in; dst = g_WINT; N = 3072; nbase = z * 1024; }
    else if (z == 3) { src = w_pk; dst = g_WPKT; N = 1024; nbase = 0; }
    else if (z == 4) { src = w_pq; dst = g_WPQT; N = 1024; nbase = 0; }
    else { src = w_o; dst = g_WOT; N = 1024; nbase = 0; }
    __shared__ float s[32][33];
    int n0 = nbase + (blockIdx.x << 5), k0 = blockIdx.y << 5;
    int tx = threadIdx.x, ty = threadIdx.y;
#pragma unroll
    for (int j = 0; j < 4; j++)
        s[ty + j * 8][tx] = src[(size_t)(k0 + ty + j * 8) * N + n0 + tx];
    __syncthreads();
#pragma unroll
    for (int j = 0; j < 4; j++)
        dst[(size_t)(n0 + ty + j * 8) * 1024 + k0 + tx] = tf32r(s[tx][ty + j * 8]);
}

/* ------------------------- tf32 GEMM (modes 0,1,4) ------------------------- */
#define STAGE_B 49152u

template <int MODE>
__global__ void __launch_bounds__(256, 1) gemm_k(const float* __restrict__ x1,
                                                 const float* __restrict__ x2, int z) {
    constexpr int NS = 32;
    const float* A;
    const float* B;
    if (MODE == 0) { A = g_HS; B = g_WINT; }
    else if (MODE == 1) { A = g_RE; B = (z ? g_WPQT : g_WPKT); }
    else { A = g_CTX; B = g_WOT; }
    const int lda = 1024, ldb = 1024;

    extern __shared__ float smem[];
    uint32_t sbase = (uint32_t)__cvta_generic_to_shared(smem);

    int tid = threadIdx.x;
    int lane = tid & 31, wid = tid >> 5;
    int wm = wid & 1, wn = wid >> 1;
    int m0 = blockIdx.y << 7, n0 = blockIdx.x << 8;

    int kcopy = tid & 7, rsub = tid >> 3;
    const float* asrc0 = A + (size_t)(m0 + rsub) * lda + kcopy * 4;
    const float* bsrc0 = B + (size_t)(n0 + rsub) * ldb + kcopy * 4;

    float c[4][8][4];
#pragma unroll
    for (int i = 0; i < 4; i++)
#pragma unroll
        for (int j = 0; j < 8; j++)
#pragma unroll
            for (int r = 0; r < 4; r++) c[i][j][r] = 0.f;

#define STAGE_COPY(slot, kofs)                                                       \
    {                                                                                \
        uint32_t sb = sbase + (slot) * STAGE_B;                                      \
        _Pragma("unroll") for (int it = 0; it < 4; it++) {                           \
            int row = it * 32 + rsub;                                                \
            uint32_t d = sb + (((row << 3) + (kcopy ^ (row & 7))) << 4);             \
            cp16(d, asrc0 + (size_t)it * 32 * lda + (kofs));                         \
        }                                                                            \
        _Pragma("unroll") for (int it = 0; it < 8; it++) {                           \
            int row = it * 32 + rsub;                                                \
            uint32_t d = sb + 16384u + (((row << 3) + (kcopy ^ (row & 7))) << 4);    \
            cp16(d, bsrc0 + (size_t)it * 32 * ldb + (kofs));                         \
        }                                                                            \
        cp_commit();                                                                 \
    }

    STAGE_COPY(0, 0)

    int arow_l = wm * 64 + (lane & 15);
    int akhalf = lane >> 4;
    int brow_base = wn * 64 + (lane & 7);
    int bkhalf = (lane >> 3) & 1;

    for (int s = 0; s < NS; s++) {
        if (s + 1 < NS) { STAGE_COPY((s + 1) & 1, (s + 1) * 32) cp_wait<1>(); }
        else cp_wait<0>();
        __syncthreads();

        uint32_t sA = sbase + (s & 1) * STAGE_B;
        uint32_t sB = sA + 16384u;

#pragma unroll
        for (int kc = 0; kc < 4; kc++) {
            uint32_t bf[8][2];
#pragma unroll
            for (int nst = 0; nst < 8; nst++) {
                int row = brow_base + nst * 8;
                int col = kc * 2 + bkhalf;
                ldsm2(bf[nst], sB + (((row << 3) + (col ^ (row & 7))) << 4));
            }
#pragma unroll
            for (int st = 0; st < 4; st++) {
                uint32_t af[4];
                int row = arow_l + st * 16;
                int col = kc * 2 + akhalf;
                ldsm4(af, sA + (((row << 3) + (col ^ (row & 7))) << 4));
#pragma unroll
                for (int nst = 0; nst < 8; nst++) mma8(c[st][nst], af, bf[nst]);
            }
        }
        __syncthreads();
    }

    int g = lane >> 2, q2 = lane & 3;
    int mbt = m0 + wm * 64, nbt = n0 + wn * 64;
#pragma unroll
    for (int st = 0; st < 4; st++) {
#pragma unroll
        for (int nst = 0; nst < 8; nst++) {
#pragma unroll
            for (int half = 0; half < 2; half++) {
                int m = mbt + st * 16 + g + half * 8;
                int n = nbt + nst * 8 + q2 * 2;
                float v0 = c[st][nst][half * 2 + 0];
                float v1 = c[st][nst][half * 2 + 1];
                if (MODE == 0) {
                    int h = n / 192, rem = n - h * 192;
                    int t = rem >> 6, d = rem & 63;
                    int bq = m >> 10, srow = m & 1023;
                    size_t idx = (((size_t)(bq * 16 + h)) * 1024 + srow) * 64 + d;
                    if (t == 0) {
                        g_Q[idx] = tf32r((v0 + x1[h * 64 + d]) * INV_SCALE);
                        g_Q[idx + 1] = tf32r((v1 + x1[h * 64 + d + 1]) * INV_SCALE);
                    } else if (t == 1) {
                        g_K[idx] = tf32r(v0);
                        g_K[idx + 1] = tf32r(v1);
                    } else {
                        size_t vt = (((size_t)(bq * 16 + h)) * 64 + d) * 1024 + srow;
                        g_VT[vt] = tf32r(v0 + x2[h * 64 + d]);
                        g_VT[vt + 1024] = tf32r(v1 + x2[h * 64 + d + 1]);
                    }
                } else if (MODE == 1) {
                    int h = n >> 6, d = n & 63;
                    size_t idx = ((size_t)h * 1024 + m) * 64 + d;
                    if (z == 0) {
                        g_PK[idx] = tf32r(v0);
                        g_PK[idx + 1] = tf32r(v1);
                    } else {
                        g_PQ[idx] = tf32r((v0 + x1[n]) * INV_SCALE);
                        g_PQ[idx + 1] = tf32r((v1 + x1[n + 1]) * INV_SCALE);
                    }
                } else {
                    size_t o = (size_t)m * 1024 + n;
                    g_Y[o] = v0 + x1[n] + x2[o];
                    g_Y[o + 1] = v1 + x1[n + 1] + x2[o + 1];
                }
            }
        }
    }
#undef STAGE_COPY
}

/* ---------------- fused attention, pipelined + ring-buffered bands ----------------
 * 128 threads / 4 warps per 64-q-row tile.
 * SMEM bytes: Q@0(16K) K0@16K K1@32K V0@48K V1@64K B1ring@80K(32K) B2ring@112K(32K)
 *             P@144K(16K) C2res@160K(64*130*4) P2res(64*130*4). total 230400.
 */
#define TW 130
#define OFF_K0 16384u
#define OFF_K1 32768u
#define OFF_V0 49152u
#define OFF_V1 65536u
#define OFF_B1 81920u
#define OFF_B2 114688u
#define OFF_P  147456u
#define OFF_C2 163840u
#define OFF_P2 197120u

__global__ void __launch_bounds__(128, 1) k_attn2() {
    extern __shared__ float sm[];
    uint32_t sb = (uint32_t)__cvta_generic_to_shared(sm);
    const uint32_t uQ = sb;
    const uint32_t uB1 = sb + OFF_B1;
    const uint32_t uB2 = sb + OFF_B2;
    const uint32_t uP = sb + OFF_P;
    float* C2 = sm + OFF_C2 / 4;
    float* P2 = sm + OFF_P2 / 4;

    int tid = threadIdx.x, lane = tid & 31, wid = tid >> 5;
    int q0 = blockIdx.x << 6, bh = blockIdx.y;
    int b = bh >> 4, h = bh & 15;
    const float* Qg = g_Q + (size_t)bh * 65536;
    const float* Kg = g_K + (size_t)bh * 65536;
    const float* Vg = g_VT + (size_t)bh * 65536;
    const float* PKg = g_PK + (size_t)h * 65536;
    const float* PQg = g_PQ + (size_t)h * 65536;

    int lc = tid & 15, lr = tid >> 4;
    int g = lane >> 2, q2 = lane & 3;
    int wq0 = wid << 4;

    /* ---- preload: Q, K0, V0, full bands (one group) ---- */
#pragma unroll
    for (int i = 0; i < 4; i++) {
        int r = lr + 8 * i;
        cp16(uQ + SW_OFF(r, lc), Qg + (size_t)(q0 + r) * 64 + lc * 4);
        int r2 = r + 32;
        cp16(uQ + SW_OFF(r2, lc), Qg + (size_t)(q0 + r2) * 64 + lc * 4);
    }
#pragma unroll
    for (int i = 0; i < 8; i++) {
        int r = lr + 8 * i;
        cp16(sb + OFF_K0 + SW_OFF(r, lc), Kg + (size_t)r * 64 + lc * 4);
        cp16(sb + OFF_V0 + SW_OFF(r, lc), Vg + (size_t)r * 1024 + lc * 4);
    }
    {
        int w01 = q0 + 449;       /* c2p window base at kt=0 */
        int w02 = 449 - q0;       /* p2c window base at kt=0 */
#pragma unroll
        for (int i = 0; i < 16; i++) {
            int r = lr + 8 * i;
            int pv = w01 + r;
            int slot = pv & 127;
            int pr = min(max(pv, 0), 1023);
            cp16(uB1 + SW_OFF(slot, lc), PKg + (size_t)pr * 64 + lc * 4);
            int pv2 = w02 + r;
            int slot2 = pv2 & 127;
            int pr2 = min(max(pv2, 0), 1023);
            cp16(uB2 + SW_OFF(slot2, lc), PQg + (size_t)pr2 * 64 + lc * 4);
        }
    }
    cp_commit();

    float O[8][4];
#pragma unroll
    for (int i = 0; i < 8; i++)
#pragma unroll
        for (int j = 0; j < 4; j++) O[i][j] = 0.f;
    float mA = -1e30f, mB = -1e30f, lA = 0.f, lB = 0.f;

    for (int kt = 0; kt < 16; kt++) {
        int k0 = kt << 6;
        int w01 = q0 - k0 + 449;
        int w02 = k0 - q0 + 449;
        uint32_t uK = sb + ((kt & 1) ? OFF_K1 : OFF_K0);
        uint32_t uV = sb + ((kt & 1) ? OFF_V1 : OFF_V0);

        __syncthreads(); /* S0: prev PV / fixup done everywhere */

        if (kt < 15) { /* prefetch next K/V into alt buffers */
            uint32_t nK = sb + ((kt & 1) ? OFF_K0 : OFF_K1);
            uint32_t nV = sb + ((kt & 1) ? OFF_V0 : OFF_V1);
            int nk0 = k0 + 64;
#pragma unroll
            for (int i = 0; i < 8; i++) {
                int r = lr + 8 * i;
                cp16(nK + SW_OFF(r, lc), Kg + (size_t)(nk0 + r) * 64 + lc * 4);
                cp16(nV + SW_OFF(r, lc), Vg + (size_t)r * 1024 + nk0 + lc * 4);
            }
            cp_commit();
            cp_wait<1>();
        } else {
            cp_wait<0>();
        }
        __syncthreads(); /* S1: this kt's data visible */

        /* ---- c2p band mma ---- */
        float accA[16][4];
#pragma unroll
        for (int i = 0; i < 16; i++)
#pragma unroll
            for (int j = 0; j < 4; j++) accA[i][j] = 0.f;
#pragma unroll
        for (int ks = 0; ks < 8; ks++) {
            uint32_t a[4];
            ldsm4(a, uQ + SW_OFF(wq0 + (lane & 15), ks * 2 + (lane >> 4)));
#pragma unroll
            for (int np = 0; np < 8; np++) {
                uint32_t bq[4];
                int srow = np * 16 + (((lane >> 4) & 1) << 3) + (lane & 7);
                int slot = (w01 + srow) & 127;
                int sc = ks * 2 + ((lane >> 3) & 1);
                ldsm4(bq, uB1 + SW_OFF(slot, sc));
                mma8(accA[np * 2], a, bq);
                mma8(accA[np * 2 + 1], a, bq + 2);
            }
        }

        /* ---- p2c band mma ---- */
        float accB[16][4];
#pragma unroll
        for (int i = 0; i < 16; i++)
#pragma unroll
            for (int j = 0; j < 4; j++) accB[i][j] = 0.f;
#pragma unroll
        for (int ks = 0; ks < 8; ks++) {
            uint32_t a[4];
            ldsm4(a, uK + SW_OFF(wq0 + (lane & 15), ks * 2 + (lane >> 4)));
#pragma unroll
            for (int np = 0; np < 8; np++) {
                uint32_t bq[4];
                int srow = np * 16 + (((lane >> 4) & 1) << 3) + (lane & 7);
                int slot = (w02 + srow) & 127;
                int sc = ks * 2 + ((lane >> 3) & 1);
                ldsm4(bq, uB2 + SW_OFF(slot, sc));
                mma8(accB[np * 2], a, bq);
                mma8(accB[np * 2 + 1], a, bq + 2);
            }
        }

        /* ---- QK mma ---- */
        float sS[8][4];
#pragma unroll
        for (int i = 0; i < 8; i++)
#pragma unroll
            for (int j = 0; j < 4; j++) sS[i][j] = 0.f;
#pragma unroll
        for (int ks = 0; ks < 8; ks++) {
            uint32_t a[4];
            ldsm4(a, uQ + SW_OFF(wq0 + (lane & 15), ks * 2 + (lane >> 4)));
#pragma unroll
            for (int np = 0; np < 4; np++) {
                uint32_t bq[4];
                int srow = np * 16 + (((lane >> 4) & 1) << 3) + (lane & 7);
                int sc = ks * 2 + ((lane >> 3) & 1);
                ldsm4(bq, uK + SW_OFF(srow, sc));
                mma8(sS[np * 2], a, bq);
                mma8(sS[np * 2 + 1], a, bq + 2);
            }
        }

        __syncthreads(); /* S2: everyone done reading rings for kt */

        if (kt < 15) { /* refresh 64 new rows per band for kt+1 */
            int nw01 = w01 - 64;        /* new rows [nw01, nw01+64) */
            int nw02b = w02 + 128;      /* new rows [w02+128, w02+192) */
#pragma unroll
            for (int i = 0; i < 8; i++) {
                int r = lr + 8 * i;
                int pv = nw01 + r;
                int slot = pv & 127;
                int pr = min(max(pv, 0), 1023);
                cp16(uB1 + SW_OFF(slot, lc), PKg + (size_t)pr * 64 + lc * 4);
                int pv2 = nw02b + r;
                int slot2 = pv2 & 127;
                int pr2 = min(max(pv2, 0), 1023);
                cp16(uB2 + SW_OFF(slot2, lc), PQg + (size_t)pr2 * 64 + lc * 4);
            }
            cp_commit();
        }

        /* ---- store band results ---- */
#pragma unroll
        for (int f = 0; f < 16; f++) {
            int col = f * 8 + q2 * 2;
            *(float2*)&C2[(wq0 + g) * TW + col] = make_float2(accA[f][0], accA[f][1]);
            *(float2*)&C2[(wq0 + g + 8) * TW + col] = make_float2(accA[f][2], accA[f][3]);
            *(float2*)&P2[(wq0 + g) * TW + col] = make_float2(accB[f][0], accB[f][1]);
            *(float2*)&P2[(wq0 + g + 8) * TW + col] = make_float2(accB[f][2], accB[f][3]);
        }
        __syncthreads(); /* S3: band results visible */

        /* ---- fixup + online softmax ---- */
        int qiA = wq0 + g, qiB = qiA + 8;
#pragma unroll
        for (int nst = 0; nst < 8; nst++) {
            int kj = nst * 8 + q2 * 2;
            sS[nst][0] += C2[qiA * TW + 63 + qiA - kj] + P2[kj * TW + 63 + kj - qiA];
            sS[nst][1] += C2[qiA * TW + 62 + qiA - kj] + P2[(kj + 1) * TW + 64 + kj - qiA];
            sS[nst][2] += C2[qiB * TW + 63 + qiB - kj] + P2[kj * TW + 63 + kj - qiB];
            sS[nst][3] += C2[qiB * TW + 62 + qiB - kj] + P2[(kj + 1) * TW + 64 + kj - qiB];
        }
        float mxA = -1e30f, mxB = -1e30f;
#pragma unroll
        for (int nst = 0; nst < 8; nst++) {
            mxA = fmaxf(mxA, fmaxf(sS[nst][0], sS[nst][1]));
            mxB = fmaxf(mxB, fmaxf(sS[nst][2], sS[nst][3]));
        }
        mxA = fmaxf(mxA, __shfl_xor_sync(0xffffffffu, mxA, 1, 4));
        mxA = fmaxf(mxA, __shfl_xor_sync(0xffffffffu, mxA, 2, 4));
        mxB = fmaxf(mxB, __shfl_xor_sync(0xffffffffu, mxB, 1, 4));
        mxB = fmaxf(mxB, __shfl_xor_sync(0xffffffffu, mxB, 2, 4));
        float mnA = fmaxf(mA, mxA), mnB = fmaxf(mB, mxB);
        float aA = __expf(mA - mnA), aB = __expf(mB - mnB);
        float rsA = 0.f, rsB = 0.f;
#pragma unroll
        for (int nst = 0; nst < 8; nst++) {
            float p0 = tf32r(__expf(sS[nst][0] - mnA));
            float p1 = tf32r(__expf(sS[nst][1] - mnA));
            float p2v = tf32r(__expf(sS[nst][2] - mnB));
            float p3 = tf32r(__expf(sS[nst][3] - mnB));
            rsA += p0 + p1;
            rsB += p2v + p3;
            int col = nst * 8 + q2 * 2;
            int ch = col >> 2, wo = (col & 3) << 2;
            *(float2*)((char*)sm + OFF_P + SW_OFF(qiA, ch) + wo) = make_float2(p0, p1);
            *(float2*)((char*)sm + OFF_P + SW_OFF(qiB, ch) + wo) = make_float2(p2v, p3);
        }
        rsA += __shfl_xor_sync(0xffffffffu, rsA, 1, 4);
        rsA += __shfl_xor_sync(0xffffffffu, rsA, 2, 4);
        rsB += __shfl_xor_sync(0xffffffffu, rsB, 1, 4);
        rsB += __shfl_xor_sync(0xffffffffu, rsB, 2, 4);
        lA = lA * aA + rsA;
        lB = lB * aB + rsB;
        mA = mnA;
        mB = mnB;
#pragma unroll
        for (int i = 0; i < 8; i++) {
            O[i][0] *= aA; O[i][1] *= aA;
            O[i][2] *= aB; O[i][3] *= aB;
        }
        __syncwarp();

        /* ---- PV mma (own 16 q rows) ---- */
#pragma unroll
        for (int ks = 0; ks < 8; ks++) {
            uint32_t a[4];
            ldsm4(a, uP + SW_OFF(wq0 + (lane & 15), ks * 2 + (lane >> 4)));
#pragma unroll
            for (int np = 0; np < 4; np++) {
                uint32_t bq[4];
                int srow = np * 16 + (((lane >> 4) & 1) << 3) + (lane & 7);
                int sc = ks * 2 + ((lane >> 3) & 1);
                ldsm4(bq, uV + SW_OFF(srow, sc));
                mma8(O[np * 2], a, bq);
                mma8(O[np * 2 + 1], a, bq + 2);
            }
        }
    }

    /* ---- epilogue ---- */
    float invA = 1.f / lA, invB = 1.f / lB;
    int qA = q0 + wq0 + g, qB = qA + 8;
#pragma unroll
    for (int np = 0; np < 8; np++) {
        int d0 = h * 64 + np * 8 + q2 * 2;
        *(float2*)&g_CTX[((size_t)(b * 1024) + qA) * 1024 + d0] =
            make_float2(tf32r(O[np][0] * invA), tf32r(O[np][1] * invA));
        *(float2*)&g_CTX[((size_t)(b * 1024) + qB) * 1024 + d0] =
            make_float2(tf32r(O[np][2] * invB), tf32r(O[np][3] * invB));
    }
}

/* ---------------- LayerNorm ---------------- */
__global__ void __launch_bounds__(256) k_ln(const float* __restrict__ gam,
                                            const float* __restrict__ bet,
                                            float* __restrict__ out) {
    int m = blockIdx.x;
    int tid = threadIdx.x;
    const float* y = g_Y + (size_t)m * Hh;
    float4 v = *(const float4*)(y + (tid << 2));
    float s = v.x + v.y + v.z + v.w;
    float s2 = v.x * v.x + v.y * v.y + v.z * v.z + v.w * v.w;
#pragma unroll
    for (int o = 16; o; o >>= 1) {
        s += __shfl_xor_sync(0xffffffffu, s, o);
        s2 += __shfl_xor_sync(0xffffffffu, s2, o);
    }
    __shared__ float sh[8], sh2[8];
    int w = tid >> 5, ln = tid & 31;
    if (ln == 0) { sh[w] = s; sh2[w] = s2; }
    __syncthreads();
    s = 0.f; s2 = 0.f;
#pragma unroll
    for (int i = 0; i < 8; i++) { s += sh[i]; s2 += sh2[i]; }
    float mean = s * (1.0f / Hh);
    float var = s2 * (1.0f / Hh) - mean * mean;
    float inv = rsqrtf(var + 1e-7f);
    float4 g4 = *(const float4*)(gam + (tid << 2));
    float4 b4 = *(const float4*)(bet + (tid << 2));
    float4 o4;
    o4.x = g4.x * (v.x - mean) * inv + b4.x;
    o4.y = g4.y * (v.y - mean) * inv + b4.y;
    o4.z = g4.z * (v.z - mean) * inv + b4.z;
    o4.w = g4.w * (v.w - mean) * inv + b4.w;
    *(float4*)(out + (size_t)m * Hh + (tid << 2)) = o4;
}

/* ---------------- launch ---------------- */
extern "C" void kernel_launch(void* const* d_in, const int* in_sizes, int n_in,
                              void* d_out, int out_size) {
    const float* hs   = (const float*)d_in[0];
    const float* re   = (const float*)d_in[2];
    const float* w_in = (const float*)d_in[3];
    const float* qb   = (const float*)d_in[4];
    const float* vb   = (const float*)d_in[5];
    const float* w_pk = (const float*)d_in[6];
    const float* w_pq = (const float*)d_in[7];
    const float* b_pq = (const float*)d_in[8];
    const float* w_o  = (const float*)d_in[9];
    const float* b_o  = (const float*)d_in[10];
    const float* lng  = (const float*)d_in[11];
    const float* lnb  = (const float*)d_in[12];
    float* out = (float*)d_out;

    static int attr_set = 0;
    if (!attr_set) {
        cudaFuncSetAttribute(k_attn2, cudaFuncAttributeMaxDynamicSharedMemorySize, 230400);
        cudaFuncSetAttribute(gemm_k<0>, cudaFuncAttributeMaxDynamicSharedMemorySize, 98304);
        cudaFuncSetAttribute(gemm_k<1>, cudaFuncAttributeMaxDynamicSharedMemorySize, 98304);
        cudaFuncSetAttribute(gemm_k<4>, cudaFuncAttributeMaxDynamicSharedMemorySize, 98304);
        attr_set = 1;
    }

    k_round2<<<5120, 256>>>(hs, re);                                   /* 1 */
    k_transp2<<<dim3(32, 32, 6), dim3(32, 8)>>>(w_in, w_pk, w_pq, w_o);/* 2 */
    gemm_k<0><<<dim3(12, 32), 256, 98304>>>(qb, vb, 0);                /* 3 */
    gemm_k<1><<<dim3(4, 8), 256, 98304>>>(b_pq, nullptr, 0);           /* 4 */
    gemm_k<1><<<dim3(4, 8), 256, 98304>>>(b_pq, nullptr, 1);           /* 5 */
    k_attn2<<<dim3(16, 64), 128, 230400>>>();                          /* 6: profiled */
    gemm_k<4><<<dim3(4, 32), 256, 98304>>>(b_o, hs, 0);                /* 7 */
    k_ln<<<4096, 256>>>(lng, lnb, out);                                /* 8 */
}

// round 5
// speedup vs baseline: 1.1039x; 1.1039x over previous
#include <cuda_runtime.h>
#include <math.h>
#include <stdint.h>

#define Bb 4
#define Ss 1024
#define Hh 1024
#define NHh 16
#define Dd 64
#define Pp 1024

#define INV_SCALE 0.07216878364870322f

/* ------------------------- scratch ------------------------- */
__device__ float g_Q[(size_t)Bb * NHh * Ss * Dd];
__device__ float g_K[(size_t)Bb * NHh * Ss * Dd];
__device__ float g_VT[(size_t)Bb * NHh * Dd * Ss];   /* [bh][d][s] */
__device__ float g_PK[(size_t)NHh * Pp * Dd];
__device__ float g_PQ[(size_t)NHh * Pp * Dd];
__device__ float g_CTX[(size_t)Bb * Ss * Hh];
__device__ float g_Y[(size_t)Bb * Ss * Hh];
__device__ float g_HS[(size_t)Bb * Ss * Hh];
__device__ float g_RE[(size_t)Pp * Hh];
__device__ float g_WINT[(size_t)3 * Hh * Hh];
__device__ float g_WPKT[(size_t)Hh * Hh];
__device__ float g_WPQT[(size_t)Hh * Hh];
__device__ float g_WOT[(size_t)Hh * Hh];

/* ------------------------- helpers ------------------------- */
__device__ __forceinline__ float tf32r(float x) {
    uint32_t u;
    asm("cvt.rna.tf32.f32 %0, %1;" : "=r"(u) : "f"(x));
    return __uint_as_float(u);
}
__device__ __forceinline__ void cp16(uint32_t dst, const void* src) {
    asm volatile("cp.async.cg.shared.global [%0], [%1], 16;" :: "r"(dst), "l"(src));
}
__device__ __forceinline__ void cp_commit() { asm volatile("cp.async.commit_group;"); }
template <int N> __device__ __forceinline__ void cp_wait() {
    asm volatile("cp.async.wait_group %0;" :: "n"(N));
}
__device__ __forceinline__ void ldsm4(uint32_t a[4], uint32_t addr) {
    asm volatile("ldmatrix.sync.aligned.m8n8.x4.shared.b16 {%0,%1,%2,%3}, [%4];"
                 : "=r"(a[0]), "=r"(a[1]), "=r"(a[2]), "=r"(a[3]) : "r"(addr));
}
__device__ __forceinline__ void ldsm2(uint32_t b[2], uint32_t addr) {
    asm volatile("ldmatrix.sync.aligned.m8n8.x2.shared.b16 {%0,%1}, [%2];"
                 : "=r"(b[0]), "=r"(b[1]) : "r"(addr));
}
__device__ __forceinline__ void mma8(float c[4], const uint32_t a[4], const uint32_t b[2]) {
    asm volatile(
        "mma.sync.aligned.m16n8k8.row.col.f32.tf32.tf32.f32 "
        "{%0,%1,%2,%3}, {%4,%5,%6,%7}, {%8,%9}, {%0,%1,%2,%3};"
        : "+f"(c[0]), "+f"(c[1]), "+f"(c[2]), "+f"(c[3])
        : "r"(a[0]), "r"(a[1]), "r"(a[2]), "r"(a[3]), "r"(b[0]), "r"(b[1]));
}

#define SW_OFF(row, c) ((((row) << 4) + (((c) & 8) | (((c) & 7) ^ ((row) & 7)))) << 4)

/* ------------------------- prep kernels ------------------------- */
__global__ void __launch_bounds__(256) k_round2(const float* __restrict__ hs,
                                                const float* __restrict__ re) {
    int bx = blockIdx.x;
    const float* src;
    float* dst;
    size_t i;
    if (bx < 4096) { src = hs; dst = g_HS; i = ((size_t)bx * 256 + threadIdx.x) * 4; }
    else { src = re; dst = g_RE; i = ((size_t)(bx - 4096) * 256 + threadIdx.x) * 4; }
    float4 v = *(const float4*)(src + i);
    v.x = tf32r(v.x); v.y = tf32r(v.y); v.z = tf32r(v.z); v.w = tf32r(v.w);
    *(float4*)(dst + i) = v;
}

/* src [K=1024][N] -> dst [N][1024] rounded; (z0+z) picks matrix/slice */
__global__ void __launch_bounds__(256) k_transp2(const float* __restrict__ w_in,
                                                 const float* __restrict__ w_pk,
                                                 const float* __restrict__ w_pq,
                                                 const float* __restrict__ w_o, int z0) {
    int z = z0 + blockIdx.z;
    const float* src;
    float* dst;
    int N, nbase;
    if (z < 3) { src = w_in; dst = g_WINT; N = 3072; nbase = z * 1024; }
    else if (z == 3) { src = w_pk; dst = g_WPKT; N = 1024; nbase = 0; }
    else if (z == 4) { src = w_pq; dst = g_WPQT; N = 1024; nbase = 0; }
    else { src = w_o; dst = g_WOT; N = 1024; nbase = 0; }
    __shared__ float s[32][33];
    int n0 = nbase + (blockIdx.x << 5), k0 = blockIdx.y << 5;
    int tx = threadIdx.x, ty = threadIdx.y;
#pragma unroll
    for (int j = 0; j < 4; j++)
        s[ty + j * 8][tx] = src[(size_t)(k0 + ty + j * 8) * N + n0 + tx];
    __syncthreads();
#pragma unroll
    for (int j = 0; j < 4; j++)
        dst[(size_t)(n0 + ty + j * 8) * 1024 + k0 + tx] = tf32r(s[tx][ty + j * 8]);
}

/* ------------------------- tf32 GEMM (modes 0,1,4) ------------------------- */
#define STAGE_B 49152u

template <int MODE>
__global__ void __launch_bounds__(256, 1) gemm_k(const float* __restrict__ x1,
                                                 const float* __restrict__ x2) {
    constexpr int NS = 32;
    const float* A;
    const float* B;
    int z = blockIdx.z;
    if (MODE == 0) { A = g_HS; B = g_WINT; }
    else if (MODE == 1) { A = g_RE; B = (z ? g_WPQT : g_WPKT); }
    else { A = g_CTX; B = g_WOT; }
    const int lda = 1024, ldb = 1024;

    extern __shared__ float smem[];
    uint32_t sbase = (uint32_t)__cvta_generic_to_shared(smem);

    int tid = threadIdx.x;
    int lane = tid & 31, wid = tid >> 5;
    int wm = wid & 1, wn = wid >> 1;
    int m0 = blockIdx.y << 7, n0 = blockIdx.x << 8;

    int kcopy = tid & 7, rsub = tid >> 3;
    const float* asrc0 = A + (size_t)(m0 + rsub) * lda + kcopy * 4;
    const float* bsrc0 = B + (size_t)(n0 + rsub) * ldb + kcopy * 4;

    float c[4][8][4];
#pragma unroll
    for (int i = 0; i < 4; i++)
#pragma unroll
        for (int j = 0; j < 8; j++)
#pragma unroll
            for (int r = 0; r < 4; r++) c[i][j][r] = 0.f;

#define STAGE_COPY(slot, kofs)                                                       \
    {                                                                                \
        uint32_t sb = sbase + (slot) * STAGE_B;                                      \
        _Pragma("unroll") for (int it = 0; it < 4; it++) {                           \
            int row = it * 32 + rsub;                                                \
            uint32_t d = sb + (((row << 3) + (kcopy ^ (row & 7))) << 4);             \
            cp16(d, asrc0 + (size_t)it * 32 * lda + (kofs));                         \
        }                                                                            \
        _Pragma("unroll") for (int it = 0; it < 8; it++) {                           \
            int row = it * 32 + rsub;                                                \
            uint32_t d = sb + 16384u + (((row << 3) + (kcopy ^ (row & 7))) << 4);    \
            cp16(d, bsrc0 + (size_t)it * 32 * ldb + (kofs));                         \
        }                                                                            \
        cp_commit();                                                                 \
    }

    STAGE_COPY(0, 0)

    int arow_l = wm * 64 + (lane & 15);
    int akhalf = lane >> 4;
    int brow_base = wn * 64 + (lane & 7);
    int bkhalf = (lane >> 3) & 1;

    for (int s = 0; s < NS; s++) {
        if (s + 1 < NS) { STAGE_COPY((s + 1) & 1, (s + 1) * 32) cp_wait<1>(); }
        else cp_wait<0>();
        __syncthreads();

        uint32_t sA = sbase + (s & 1) * STAGE_B;
        uint32_t sB = sA + 16384u;

#pragma unroll
        for (int kc = 0; kc < 4; kc++) {
            uint32_t bf[8][2];
#pragma unroll
            for (int nst = 0; nst < 8; nst++) {
                int row = brow_base + nst * 8;
                int col = kc * 2 + bkhalf;
                ldsm2(bf[nst], sB + (((row << 3) + (col ^ (row & 7))) << 4));
            }
#pragma unroll
            for (int st = 0; st < 4; st++) {
                uint32_t af[4];
                int row = arow_l + st * 16;
                int col = kc * 2 + akhalf;
                ldsm4(af, sA + (((row << 3) + (col ^ (row & 7))) << 4));
#pragma unroll
                for (int nst = 0; nst < 8; nst++) mma8(c[st][nst], af, bf[nst]);
            }
        }
        __syncthreads();
    }

    int g = lane >> 2, q2 = lane & 3;
    int mbt = m0 + wm * 64, nbt = n0 + wn * 64;
#pragma unroll
    for (int st = 0; st < 4; st++) {
#pragma unroll
        for (int nst = 0; nst < 8; nst++) {
#pragma unroll
            for (int half = 0; half < 2; half++) {
                int m = mbt + st * 16 + g + half * 8;
                int n = nbt + nst * 8 + q2 * 2;
                float v0 = c[st][nst][half * 2 + 0];
                float v1 = c[st][nst][half * 2 + 1];
                if (MODE == 0) {
                    int h = n / 192, rem = n - h * 192;
                    int t = rem >> 6, d = rem & 63;
                    int bq = m >> 10, srow = m & 1023;
                    size_t idx = (((size_t)(bq * 16 + h)) * 1024 + srow) * 64 + d;
                    if (t == 0) {
                        g_Q[idx] = tf32r((v0 + x1[h * 64 + d]) * INV_SCALE);
                        g_Q[idx + 1] = tf32r((v1 + x1[h * 64 + d + 1]) * INV_SCALE);
                    } else if (t == 1) {
                        g_K[idx] = tf32r(v0);
                        g_K[idx + 1] = tf32r(v1);
                    } else {
                        size_t vt = (((size_t)(bq * 16 + h)) * 64 + d) * 1024 + srow;
                        g_VT[vt] = tf32r(v0 + x2[h * 64 + d]);
                        g_VT[vt + 1024] = tf32r(v1 + x2[h * 64 + d + 1]);
                    }
                } else if (MODE == 1) {
                    int h = n >> 6, d = n & 63;
                    size_t idx = ((size_t)h * 1024 + m) * 64 + d;
                    if (z == 0) {
                        g_PK[idx] = tf32r(v0);
                        g_PK[idx + 1] = tf32r(v1);
                    } else {
                        g_PQ[idx] = tf32r((v0 + x1[n]) * INV_SCALE);
                        g_PQ[idx + 1] = tf32r((v1 + x1[n + 1]) * INV_SCALE);
                    }
                } else {
                    size_t o = (size_t)m * 1024 + n;
                    g_Y[o] = v0 + x1[n] + x2[o];
                    g_Y[o + 1] = v1 + x1[n + 1] + x2[o + 1];
                }
            }
        }
    }
#undef STAGE_COPY
}

/* ---------------- fused attention: pipelined, ring bands, low reg pressure ----------------
 * 128 threads / 4 warps; block = 64 q rows of one (b,h).
 * SMEM: Q@0(16K) K0@16K K1@32K V0@48K V1@64K B1ring@80K(32K) B2ring@112K(32K)
 *       P@144K(16K) C2@160K(64*130*4) P2@192.5K(64*130*4). total 230400 B.
 */
#define TW 130
#define OFF_K0 16384u
#define OFF_K1 32768u
#define OFF_V0 49152u
#define OFF_V1 65536u
#define OFF_B1 81920u
#define OFF_B2 114688u
#define OFF_P  147456u
#define OFF_C2 163840u
#define OFF_P2 197120u

__global__ void __launch_bounds__(128, 1) k_attn2() {
    extern __shared__ float sm[];
    uint32_t sb = (uint32_t)__cvta_generic_to_shared(sm);
    const uint32_t uQ = sb;
    const uint32_t uB1 = sb + OFF_B1;
    const uint32_t uB2 = sb + OFF_B2;
    const uint32_t uP = sb + OFF_P;
    float* C2 = sm + OFF_C2 / 4;
    float* P2 = sm + OFF_P2 / 4;

    int tid = threadIdx.x, lane = tid & 31, wid = tid >> 5;
    int q0 = blockIdx.x << 6, bh = blockIdx.y;
    int b = bh >> 4, h = bh & 15;
    const float* Qg = g_Q + (size_t)bh * 65536;
    const float* Kg = g_K + (size_t)bh * 65536;
    const float* Vg = g_VT + (size_t)bh * 65536;
    const float* PKg = g_PK + (size_t)h * 65536;
    const float* PQg = g_PQ + (size_t)h * 65536;

    int lc = tid & 15, lr = tid >> 4;
    int g = lane >> 2, q2 = lane & 3;
    int wq0 = wid << 4;

    /* ---- preload G0: Q + K0 + V0 ---- */
#pragma unroll
    for (int i = 0; i < 4; i++) {
        int r = lr + 8 * i;
        cp16(uQ + SW_OFF(r, lc), Qg + (size_t)(q0 + r) * 64 + lc * 4);
        int r2 = r + 32;
        cp16(uQ + SW_OFF(r2, lc), Qg + (size_t)(q0 + r2) * 64 + lc * 4);
    }
#pragma unroll
    for (int i = 0; i < 8; i++) {
        int r = lr + 8 * i;
        cp16(sb + OFF_K0 + SW_OFF(r, lc), Kg + (size_t)r * 64 + lc * 4);
        cp16(sb + OFF_V0 + SW_OFF(r, lc), Vg + (size_t)r * 1024 + lc * 4);
    }
    cp_commit();
    /* ---- preload G1: both bands for kt=0 ---- */
    {
        int w01 = q0 + 449, w02 = 449 - q0;
#pragma unroll
        for (int i = 0; i < 16; i++) {
            int r = lr + 8 * i;
            int pv = w01 + r;
            cp16(uB1 + SW_OFF(pv & 127, lc), PKg + (size_t)min(max(pv, 0), 1023) * 64 + lc * 4);
            int pv2 = w02 + r;
            cp16(uB2 + SW_OFF(pv2 & 127, lc), PQg + (size_t)min(max(pv2, 0), 1023) * 64 + lc * 4);
        }
    }
    cp_commit();

    float O[8][4];
#pragma unroll
    for (int i = 0; i < 8; i++)
#pragma unroll
        for (int j = 0; j < 4; j++) O[i][j] = 0.f;
    float mA = -1e30f, mB = -1e30f, lA = 0.f, lB = 0.f;

    for (int kt = 0; kt < 16; kt++) {
        int k0 = kt << 6;
        int w01 = q0 - k0 + 449;
        int w02 = k0 - q0 + 449;
        uint32_t uK = sb + ((kt & 1) ? OFF_K1 : OFF_K0);
        uint32_t uV = sb + ((kt & 1) ? OFF_V1 : OFF_V0);

        __syncthreads(); /* S0: prev iter's PV done -> alt K/V buffers free */

        if (kt < 15) {
            uint32_t nK = sb + ((kt & 1) ? OFF_K0 : OFF_K1);
            uint32_t nV = sb + ((kt & 1) ? OFF_V0 : OFF_V1);
            int nk0 = k0 + 64;
#pragma unroll
            for (int i = 0; i < 8; i++) {
                int r = lr + 8 * i;
                cp16(nK + SW_OFF(r, lc), Kg + (size_t)(nk0 + r) * 64 + lc * 4);
                cp16(nV + SW_OFF(r, lc), Vg + (size_t)r * 1024 + nk0 + lc * 4);
            }
            cp_commit();
            cp_wait<1>();
        } else {
            cp_wait<0>();
        }
        __syncthreads(); /* S1: this kt's K/V + bands visible */

        /* ---- c2p band mma (acc) ---- */
        {
            float acc[16][4];
#pragma unroll
            for (int i = 0; i < 16; i++)
#pragma unroll
                for (int j = 0; j < 4; j++) acc[i][j] = 0.f;
#pragma unroll
            for (int ks = 0; ks < 8; ks++) {
                uint32_t a[4];
                ldsm4(a, uQ + SW_OFF(wq0 + (lane & 15), ks * 2 + (lane >> 4)));
#pragma unroll
                for (int np = 0; np < 8; np++) {
                    uint32_t bq[4];
                    int srow = np * 16 + (((lane >> 4) & 1) << 3) + (lane & 7);
                    int slot = (w01 + srow) & 127;
                    int sc = ks * 2 + ((lane >> 3) & 1);
                    ldsm4(bq, uB1 + SW_OFF(slot, sc));
                    mma8(acc[np * 2], a, bq);
                    mma8(acc[np * 2 + 1], a, bq + 2);
                }
            }
#pragma unroll
            for (int f = 0; f < 16; f++) {
                int col = f * 8 + q2 * 2;
                *(float2*)&C2[(wq0 + g) * TW + col] = make_float2(acc[f][0], acc[f][1]);
                *(float2*)&C2[(wq0 + g + 8) * TW + col] = make_float2(acc[f][2], acc[f][3]);
            }
        }

        /* ---- p2c band mma (acc reused) ---- */
        {
            float acc[16][4];
#pragma unroll
            for (int i = 0; i < 16; i++)
#pragma unroll
                for (int j = 0; j < 4; j++) acc[i][j] = 0.f;
#pragma unroll
            for (int ks = 0; ks < 8; ks++) {
                uint32_t a[4];
                ldsm4(a, uK + SW_OFF(wq0 + (lane & 15), ks * 2 + (lane >> 4)));
#pragma unroll
                for (int np = 0; np < 8; np++) {
                    uint32_t bq[4];
                    int srow = np * 16 + (((lane >> 4) & 1) << 3) + (lane & 7);
                    int slot = (w02 + srow) & 127;
                    int sc = ks * 2 + ((lane >> 3) & 1);
                    ldsm4(bq, uB2 + SW_OFF(slot, sc));
                    mma8(acc[np * 2], a, bq);
                    mma8(acc[np * 2 + 1], a, bq + 2);
                }
            }
#pragma unroll
            for (int f = 0; f < 16; f++) {
                int col = f * 8 + q2 * 2;
                *(float2*)&P2[(wq0 + g) * TW + col] = make_float2(acc[f][0], acc[f][1]);
                *(float2*)&P2[(wq0 + g + 8) * TW + col] = make_float2(acc[f][2], acc[f][3]);
            }
        }

        /* ---- QK mma ---- */
        float sS[8][4];
#pragma unroll
        for (int i = 0; i < 8; i++)
#pragma unroll
            for (int j = 0; j < 4; j++) sS[i][j] = 0.f;
#pragma unroll
        for (int ks = 0; ks < 8; ks++) {
            uint32_t a[4];
            ldsm4(a, uQ + SW_OFF(wq0 + (lane & 15), ks * 2 + (lane >> 4)));
#pragma unroll
            for (int np = 0; np < 4; np++) {
                uint32_t bq[4];
                int srow = np * 16 + (((lane >> 4) & 1) << 3) + (lane & 7);
                int sc = ks * 2 + ((lane >> 3) & 1);
                ldsm4(bq, uK + SW_OFF(srow, sc));
                mma8(sS[np * 2], a, bq);
                mma8(sS[np * 2 + 1], a, bq + 2);
            }
        }

        __syncthreads(); /* S2: band reads + result stores done everywhere */

        if (kt < 15) { /* refill 64 new ring rows per band for kt+1 */
            int nw01 = w01 - 64;
            int nw02b = w02 + 128;
#pragma unroll
            for (int i = 0; i < 8; i++) {
                int r = lr + 8 * i;
                int pv = nw01 + r;
                cp16(uB1 + SW_OFF(pv & 127, lc), PKg + (size_t)min(max(pv, 0), 1023) * 64 + lc * 4);
                int pv2 = nw02b + r;
                cp16(uB2 + SW_OFF(pv2 & 127, lc), PQg + (size_t)min(max(pv2, 0), 1023) * 64 + lc * 4);
            }
            cp_commit();
        }

        /* ---- fixup + online softmax ---- */
        int qiA = wq0 + g, qiB = qiA + 8;
#pragma unroll
        for (int nst = 0; nst < 8; nst++) {
            int kj = nst * 8 + q2 * 2;
            sS[nst][0] += C2[qiA * TW + 63 + qiA - kj] + P2[kj * TW + 63 + kj - qiA];
            sS[nst][1] += C2[qiA * TW + 62 + qiA - kj] + P2[(kj + 1) * TW + 64 + kj - qiA];
            sS[nst][2] += C2[qiB * TW + 63 + qiB - kj] + P2[kj * TW + 63 + kj - qiB];
            sS[nst][3] += C2[qiB * TW + 62 + qiB - kj] + P2[(kj + 1) * TW + 64 + kj - qiB];
        }
        float mxA = -1e30f, mxB = -1e30f;
#pragma unroll
        for (int nst = 0; nst < 8; nst++) {
            mxA = fmaxf(mxA, fmaxf(sS[nst][0], sS[nst][1]));
            mxB = fmaxf(mxB, fmaxf(sS[nst][2], sS[nst][3]));
        }
        mxA = fmaxf(mxA, __shfl_xor_sync(0xffffffffu, mxA, 1, 4));
        mxA = fmaxf(mxA, __shfl_xor_sync(0xffffffffu, mxA, 2, 4));
        mxB = fmaxf(mxB, __shfl_xor_sync(0xffffffffu, mxB, 1, 4));
        mxB = fmaxf(mxB, __shfl_xor_sync(0xffffffffu, mxB, 2, 4));
        float mnA = fmaxf(mA, mxA), mnB = fmaxf(mB, mxB);
        float aA = __expf(mA - mnA), aB = __expf(mB - mnB);
        float rsA = 0.f, rsB = 0.f;
#pragma unroll
        for (int nst = 0; nst < 8; nst++) {
            float p0 = tf32r(__expf(sS[nst][0] - mnA));
            float p1 = tf32r(__expf(sS[nst][1] - mnA));
            float p2v = tf32r(__expf(sS[nst][2] - mnB));
            float p3 = tf32r(__expf(sS[nst][3] - mnB));
            rsA += p0 + p1;
            rsB += p2v + p3;
            int col = nst * 8 + q2 * 2;
            int ch = col >> 2, wo = (col & 3) << 2;
            *(float2*)((char*)sm + OFF_P + SW_OFF(qiA, ch) + wo) = make_float2(p0, p1);
            *(float2*)((char*)sm + OFF_P + SW_OFF(qiB, ch) + wo) = make_float2(p2v, p3);
        }
        rsA += __shfl_xor_sync(0xffffffffu, rsA, 1, 4);
        rsA += __shfl_xor_sync(0xffffffffu, rsA, 2, 4);
        rsB += __shfl_xor_sync(0xffffffffu, rsB, 1, 4);
        rsB += __shfl_xor_sync(0xffffffffu, rsB, 2, 4);
        lA = lA * aA + rsA;
        lB = lB * aB + rsB;
        mA = mnA;
        mB = mnB;
#pragma unroll
        for (int i = 0; i < 8; i++) {
            O[i][0] *= aA; O[i][1] *= aA;
            O[i][2] *= aB; O[i][3] *= aB;
        }
        __syncwarp();

        /* ---- PV mma (own 16 q rows) ---- */
#pragma unroll
        for (int ks = 0; ks < 8; ks++) {
            uint32_t a[4];
            ldsm4(a, uP + SW_OFF(wq0 + (lane & 15), ks * 2 + (lane >> 4)));
#pragma unroll
            for (int np = 0; np < 4; np++) {
                uint32_t bq[4];
                int srow = np * 16 + (((lane >> 4) & 1) << 3) + (lane & 7);
                int sc = ks * 2 + ((lane >> 3) & 1);
                ldsm4(bq, uV + SW_OFF(srow, sc));
                mma8(O[np * 2], a, bq);
                mma8(O[np * 2 + 1], a, bq + 2);
            }
        }
    }

    /* ---- epilogue ---- */
    float invA = 1.f / lA, invB = 1.f / lB;
    int qA = q0 + wq0 + g, qB = qA + 8;
#pragma unroll
    for (int np = 0; np < 8; np++) {
        int d0 = h * 64 + np * 8 + q2 * 2;
        *(float2*)&g_CTX[((size_t)(b * 1024) + qA) * 1024 + d0] =
            make_float2(tf32r(O[np][0] * invA), tf32r(O[np][1] * invA));
        *(float2*)&g_CTX[((size_t)(b * 1024) + qB) * 1024 + d0] =
            make_float2(tf32r(O[np][2] * invB), tf32r(O[np][3] * invB));
    }
}

/* ---------------- LayerNorm ---------------- */
__global__ void __launch_bounds__(256) k_ln(const float* __restrict__ gam,
                                            const float* __restrict__ bet,
                                            float* __restrict__ out) {
    int m = blockIdx.x;
    int tid = threadIdx.x;
    const float* y = g_Y + (size_t)m * Hh;
    float4 v = *(const float4*)(y + (tid << 2));
    float s = v.x + v.y + v.z + v.w;
    float s2 = v.x * v.x + v.y * v.y + v.z * v.z + v.w * v.w;
#pragma unroll
    for (int o = 16; o; o >>= 1) {
        s += __shfl_xor_sync(0xffffffffu, s, o);
        s2 += __shfl_xor_sync(0xffffffffu, s2, o);
    }
    __shared__ float sh[8], sh2[8];
    int w = tid >> 5, ln = tid & 31;
    if (ln == 0) { sh[w] = s; sh2[w] = s2; }
    __syncthreads();
    s = 0.f; s2 = 0.f;
#pragma unroll
    for (int i = 0; i < 8; i++) { s += sh[i]; s2 += sh2[i]; }
    float mean = s * (1.0f / Hh);
    float var = s2 * (1.0f / Hh) - mean * mean;
    float inv = rsqrtf(var + 1e-7f);
    float4 g4 = *(const float4*)(gam + (tid << 2));
    float4 b4 = *(const float4*)(bet + (tid << 2));
    float4 o4;
    o4.x = g4.x * (v.x - mean) * inv + b4.x;
    o4.y = g4.y * (v.y - mean) * inv + b4.y;
    o4.z = g4.z * (v.z - mean) * inv + b4.z;
    o4.w = g4.w * (v.w - mean) * inv + b4.w;
    *(float4*)(out + (size_t)m * Hh + (tid << 2)) = o4;
}

/* ---------------- launch ---------------- */
extern "C" void kernel_launch(void* const* d_in, const int* in_sizes, int n_in,
                              void* d_out, int out_size) {
    const float* hs   = (const float*)d_in[0];
    const float* re   = (const float*)d_in[2];
    const float* w_in = (const float*)d_in[3];
    const float* qb   = (const float*)d_in[4];
    const float* vb   = (const float*)d_in[5];
    const float* w_pk = (const float*)d_in[6];
    const float* w_pq = (const float*)d_in[7];
    const float* b_pq = (const float*)d_in[8];
    const float* w_o  = (const float*)d_in[9];
    const float* b_o  = (const float*)d_in[10];
    const float* lng  = (const float*)d_in[11];
    const float* lnb  = (const float*)d_in[12];
    float* out = (float*)d_out;

    static int attr_set = 0;
    if (!attr_set) {
        cudaFuncSetAttribute(k_attn2, cudaFuncAttributeMaxDynamicSharedMemorySize, 230400);
        cudaFuncSetAttribute(gemm_k<0>, cudaFuncAttributeMaxDynamicSharedMemorySize, 98304);
        cudaFuncSetAttribute(gemm_k<1>, cudaFuncAttributeMaxDynamicSharedMemorySize, 98304);
        cudaFuncSetAttribute(gemm_k<4>, cudaFuncAttributeMaxDynamicSharedMemorySize, 98304);
        attr_set = 1;
    }

    k_round2<<<5120, 256>>>(hs, re);                                        /* 1 */
    k_transp2<<<dim3(32, 32, 3), dim3(32, 8)>>>(w_in, w_pk, w_pq, w_o, 0);  /* 2 */
    k_transp2<<<dim3(32, 32, 3), dim3(32, 8)>>>(w_in, w_pk, w_pq, w_o, 3);  /* 3 */
    gemm_k<0><<<dim3(12, 32), 256, 98304>>>(qb, vb);                        /* 4 */
    gemm_k<1><<<dim3(4, 8, 2), 256, 98304>>>(b_pq, nullptr);                /* 5 */
    k_attn2<<<dim3(16, 64), 128, 230400>>>();                               /* 6: profiled */
    gemm_k<4><<<dim3(4, 32), 256, 98304>>>(b_o, hs);                        /* 7 */
    k_ln<<<4096, 256>>>(lng, lnb, out);                                     /* 8 */
}

// round 6
// speedup vs baseline: 1.6633x; 1.5068x over previous
#include <cuda_runtime.h>
#include <cuda_fp16.h>
#include <math.h>
#include <stdint.h>

#define Bb 4
#define Ss 1024
#define Hh 1024
#define NHh 16
#define Dd 64
#define Pp 1024

#define INV_SCALE 0.07216878364870322f

/* ------------------------- scratch (fp16 operands) ------------------------- */
__device__ __half g_Q[(size_t)Bb * NHh * Ss * Dd];
__device__ __half g_K[(size_t)Bb * NHh * Ss * Dd];
__device__ __half g_VT[(size_t)Bb * NHh * Dd * Ss];   /* [bh][d][s] */
__device__ __half g_PK[(size_t)NHh * Pp * Dd];
__device__ __half g_PQ[(size_t)NHh * Pp * Dd];
__device__ __half g_CTX[(size_t)Bb * Ss * Hh];
__device__ float  g_Y[(size_t)Bb * Ss * Hh];
__device__ __half g_HS[(size_t)Bb * Ss * Hh];
__device__ __half g_RE[(size_t)Pp * Hh];
__device__ __half g_WINT[(size_t)3 * Hh * Hh];
__device__ __half g_WPKT[(size_t)Hh * Hh];
__device__ __half g_WPQT[(size_t)Hh * Hh];
__device__ __half g_WOT[(size_t)Hh * Hh];

/* ------------------------- helpers ------------------------- */
__device__ __forceinline__ void cp16(uint32_t dst, const void* src) {
    asm volatile("cp.async.cg.shared.global [%0], [%1], 16;" :: "r"(dst), "l"(src));
}
__device__ __forceinline__ void cp_commit() { asm volatile("cp.async.commit_group;"); }
template <int N> __device__ __forceinline__ void cp_wait() {
    asm volatile("cp.async.wait_group %0;" :: "n"(N));
}
__device__ __forceinline__ void ldsm4(uint32_t a[4], uint32_t addr) {
    asm volatile("ldmatrix.sync.aligned.m8n8.x4.shared.b16 {%0,%1,%2,%3}, [%4];"
                 : "=r"(a[0]), "=r"(a[1]), "=r"(a[2]), "=r"(a[3]) : "r"(addr));
}
__device__ __forceinline__ void ldsm2(uint32_t b[2], uint32_t addr) {
    asm volatile("ldmatrix.sync.aligned.m8n8.x2.shared.b16 {%0,%1}, [%2];"
                 : "=r"(b[0]), "=r"(b[1]) : "r"(addr));
}
/* m16n8k16 fp16 mma, fp32 accumulate */
__device__ __forceinline__ void mma16(float c[4], const uint32_t a[4], const uint32_t b[2]) {
    asm volatile(
        "mma.sync.aligned.m16n8k16.row.col.f32.f16.f16.f32 "
        "{%0,%1,%2,%3}, {%4,%5,%6,%7}, {%8,%9}, {%0,%1,%2,%3};"
        : "+f"(c[0]), "+f"(c[1]), "+f"(c[2]), "+f"(c[3])
        : "r"(a[0]), "r"(a[1]), "r"(a[2]), "r"(a[3]), "r"(b[0]), "r"(b[1]));
}

/* swizzled tile: row = 8 chunks of 16B (64 halves / 128B per row) */
#define SW_OFF(row, c) ((((row) << 3) + ((c) ^ ((row) & 7))) << 4)

/* ------------------------- prep kernels ------------------------- */
__global__ void __launch_bounds__(256) k_round2(const float* __restrict__ hs,
                                                const float* __restrict__ re) {
    int bx = blockIdx.x;
    const float* src;
    __half* dst;
    size_t i;
    if (bx < 4096) { src = hs; dst = g_HS; i = ((size_t)bx * 256 + threadIdx.x) * 4; }
    else { src = re; dst = g_RE; i = ((size_t)(bx - 4096) * 256 + threadIdx.x) * 4; }
    float4 v = *(const float4*)(src + i);
    __half2 h01 = __floats2half2_rn(v.x, v.y);
    __half2 h23 = __floats2half2_rn(v.z, v.w);
    *(__half2*)(dst + i) = h01;
    *(__half2*)(dst + i + 2) = h23;
}

/* src [K=1024][N] -> dst [N][1024] fp16; (z0+z) picks matrix/slice */
__global__ void __launch_bounds__(256) k_transp2(const float* __restrict__ w_in,
                                                 const float* __restrict__ w_pk,
                                                 const float* __restrict__ w_pq,
                                                 const float* __restrict__ w_o, int z0) {
    int z = z0 + blockIdx.z;
    const float* src;
    __half* dst;
    int N, nbase;
    if (z < 3) { src = w_in; dst = g_WINT; N = 3072; nbase = z * 1024; }
    else if (z == 3) { src = w_pk; dst = g_WPKT; N = 1024; nbase = 0; }
    else if (z == 4) { src = w_pq; dst = g_WPQT; N = 1024; nbase = 0; }
    else { src = w_o; dst = g_WOT; N = 1024; nbase = 0; }
    __shared__ float s[32][33];
    int n0 = nbase + (blockIdx.x << 5), k0 = blockIdx.y << 5;
    int tx = threadIdx.x, ty = threadIdx.y;
#pragma unroll
    for (int j = 0; j < 4; j++)
        s[ty + j * 8][tx] = src[(size_t)(k0 + ty + j * 8) * N + n0 + tx];
    __syncthreads();
#pragma unroll
    for (int j = 0; j < 4; j++)
        dst[(size_t)(n0 + ty + j * 8) * 1024 + k0 + tx] = __float2half_rn(s[tx][ty + j * 8]);
}

/* ------------------------- fp16 GEMM (modes 0,1,4) -------------------------
 * Block 128x256, K-stage 64 halves, 8 warps, warp tile 64x64. NS=16.
 */
#define STAGE_B 49152u  /* (128+256) rows * 128B */

template <int MODE>
__global__ void __launch_bounds__(256, 1) gemm_k(const float* __restrict__ x1,
                                                 const float* __restrict__ x2) {
    constexpr int NS = 16;
    const __half* A;
    const __half* B;
    int z = blockIdx.z;
    if (MODE == 0) { A = g_HS; B = g_WINT; }
    else if (MODE == 1) { A = g_RE; B = (z ? g_WPQT : g_WPKT); }
    else { A = g_CTX; B = g_WOT; }

    extern __shared__ char smemc[];
    uint32_t sbase = (uint32_t)__cvta_generic_to_shared(smemc);

    int tid = threadIdx.x;
    int lane = tid & 31, wid = tid >> 5;
    int wm = wid & 1, wn = wid >> 1;
    int m0 = blockIdx.y << 7, n0 = blockIdx.x << 8;

    int kcopy = tid & 7, rsub = tid >> 3;   /* chunk 0-7, row 0-31 */
    const __half* asrc0 = A + (size_t)(m0 + rsub) * 1024 + kcopy * 8;
    const __half* bsrc0 = B + (size_t)(n0 + rsub) * 1024 + kcopy * 8;

    float c[4][8][4];
#pragma unroll
    for (int i = 0; i < 4; i++)
#pragma unroll
        for (int j = 0; j < 8; j++)
#pragma unroll
            for (int r = 0; r < 4; r++) c[i][j][r] = 0.f;

#define STAGE_COPY(slot, kofs)                                                       \
    {                                                                                \
        uint32_t sb = sbase + (slot) * STAGE_B;                                      \
        _Pragma("unroll") for (int it = 0; it < 4; it++) {                           \
            int row = it * 32 + rsub;                                                \
            cp16(sb + SW_OFF(row, kcopy), asrc0 + (size_t)it * 32 * 1024 + (kofs));  \
        }                                                                            \
        _Pragma("unroll") for (int it = 0; it < 8; it++) {                           \
            int row = it * 32 + rsub;                                                \
            cp16(sb + 16384u + SW_OFF(row, kcopy),                                   \
                 bsrc0 + (size_t)it * 32 * 1024 + (kofs));                           \
        }                                                                            \
        cp_commit();                                                                 \
    }

    STAGE_COPY(0, 0)

    int arow_l = wm * 64 + (lane & 15);
    int akhalf = lane >> 4;
    int brow_base = wn * 64 + (lane & 7);
    int bkhalf = (lane >> 3) & 1;

    for (int s = 0; s < NS; s++) {
        if (s + 1 < NS) { STAGE_COPY((s + 1) & 1, (s + 1) * 64) cp_wait<1>(); }
        else cp_wait<0>();
        __syncthreads();

        uint32_t sA = sbase + (s & 1) * STAGE_B;
        uint32_t sB = sA + 16384u;

#pragma unroll
        for (int kc = 0; kc < 4; kc++) {  /* 4 x k16 */
            uint32_t bf[8][2];
#pragma unroll
            for (int nst = 0; nst < 8; nst++) {
                int row = brow_base + nst * 8;
                ldsm2(bf[nst], sB + SW_OFF(row, kc * 2 + bkhalf));
            }
#pragma unroll
            for (int st = 0; st < 4; st++) {
                uint32_t af[4];
                int row = arow_l + st * 16;
                ldsm4(af, sA + SW_OFF(row, kc * 2 + akhalf));
#pragma unroll
                for (int nst = 0; nst < 8; nst++) mma16(c[st][nst], af, bf[nst]);
            }
        }
        __syncthreads();
    }

    int g = lane >> 2, q2 = lane & 3;
    int mbt = m0 + wm * 64, nbt = n0 + wn * 64;
#pragma unroll
    for (int st = 0; st < 4; st++) {
#pragma unroll
        for (int nst = 0; nst < 8; nst++) {
#pragma unroll
            for (int half = 0; half < 2; half++) {
                int m = mbt + st * 16 + g + half * 8;
                int n = nbt + nst * 8 + q2 * 2;
                float v0 = c[st][nst][half * 2 + 0];
                float v1 = c[st][nst][half * 2 + 1];
                if (MODE == 0) {
                    int h = n / 192, rem = n - h * 192;
                    int t = rem >> 6, d = rem & 63;
                    int bq = m >> 10, srow = m & 1023;
                    size_t idx = (((size_t)(bq * 16 + h)) * 1024 + srow) * 64 + d;
                    if (t == 0) {
                        *(__half2*)&g_Q[idx] = __floats2half2_rn(
                            (v0 + x1[h * 64 + d]) * INV_SCALE,
                            (v1 + x1[h * 64 + d + 1]) * INV_SCALE);
                    } else if (t == 1) {
                        *(__half2*)&g_K[idx] = __floats2half2_rn(v0, v1);
                    } else {
                        size_t vt = (((size_t)(bq * 16 + h)) * 64 + d) * 1024 + srow;
                        g_VT[vt] = __float2half_rn(v0 + x2[h * 64 + d]);
                        g_VT[vt + 1024] = __float2half_rn(v1 + x2[h * 64 + d + 1]);
                    }
                } else if (MODE == 1) {
                    int h = n >> 6, d = n & 63;
                    size_t idx = ((size_t)h * 1024 + m) * 64 + d;
                    if (z == 0) {
                        *(__half2*)&g_PK[idx] = __floats2half2_rn(v0, v1);
                    } else {
                        *(__half2*)&g_PQ[idx] = __floats2half2_rn(
                            (v0 + x1[n]) * INV_SCALE, (v1 + x1[n + 1]) * INV_SCALE);
                    }
                } else {
                    size_t o = (size_t)m * 1024 + n;
                    g_Y[o] = v0 + x1[n] + x2[o];
                    g_Y[o + 1] = v1 + x1[n + 1] + x2[o + 1];
                }
            }
        }
    }
#undef STAGE_COPY
}

/* ---------------- fused attention (fp16 operands, fp32 accum) ----------------
 * 128 threads / 4 warps; block = 64 q rows of one (b,h).
 * SMEM bytes: Q@0(8K) K0@8K K1@16K V0@24K V1@32K B1ring@40K(16K) B2ring@56K(16K)
 *             P@72K(8K) C2@80K(33280) P2@112.5K(33280). total 148480.
 */
#define TW 130
#define OFF_K0 8192u
#define OFF_K1 16384u
#define OFF_V0 24576u
#define OFF_V1 32768u
#define OFF_B1 40960u
#define OFF_B2 57344u
#define OFF_P  73728u
#define OFF_C2 81920u
#define OFF_P2 115200u

__global__ void __launch_bounds__(128, 1) k_attn2() {
    extern __shared__ char smc[];
    float* sm = (float*)smc;
    uint32_t sb = (uint32_t)__cvta_generic_to_shared(smc);
    const uint32_t uQ = sb;
    const uint32_t uB1 = sb + OFF_B1;
    const uint32_t uB2 = sb + OFF_B2;
    const uint32_t uP = sb + OFF_P;
    float* C2 = sm + OFF_C2 / 4;
    float* P2 = sm + OFF_P2 / 4;

    int tid = threadIdx.x, lane = tid & 31, wid = tid >> 5;
    int q0 = blockIdx.x << 6, bh = blockIdx.y;
    int b = bh >> 4, h = bh & 15;
    const __half* Qg = g_Q + (size_t)bh * 65536;
    const __half* Kg = g_K + (size_t)bh * 65536;
    const __half* Vg = g_VT + (size_t)bh * 65536;
    const __half* PKg = g_PK + (size_t)h * 65536;
    const __half* PQg = g_PQ + (size_t)h * 65536;

    int lc = tid & 7, lr = tid >> 3;     /* chunk 0-7, row 0-15 */
    int g = lane >> 2, q2 = lane & 3;
    int wq0 = wid << 4;

    /* ---- preload G0: Q + K0 + V0 (64 rows each) ---- */
#pragma unroll
    for (int i = 0; i < 4; i++) {
        int r = lr + 16 * i;
        cp16(uQ + SW_OFF(r, lc), Qg + (size_t)(q0 + r) * 64 + lc * 8);
        cp16(sb + OFF_K0 + SW_OFF(r, lc), Kg + (size_t)r * 64 + lc * 8);
        cp16(sb + OFF_V0 + SW_OFF(r, lc), Vg + (size_t)r * 1024 + lc * 8);
    }
    cp_commit();
    /* ---- preload G1: both 128-row bands for kt=0 ---- */
    {
        int w01 = q0 + 449, w02 = 449 - q0;
#pragma unroll
        for (int i = 0; i < 8; i++) {
            int r = lr + 16 * i;
            int pv = w01 + r;
            cp16(uB1 + SW_OFF(pv & 127, lc), PKg + (size_t)min(max(pv, 0), 1023) * 64 + lc * 8);
            int pv2 = w02 + r;
            cp16(uB2 + SW_OFF(pv2 & 127, lc), PQg + (size_t)min(max(pv2, 0), 1023) * 64 + lc * 8);
        }
    }
    cp_commit();

    float O[8][4];
#pragma unroll
    for (int i = 0; i < 8; i++)
#pragma unroll
        for (int j = 0; j < 4; j++) O[i][j] = 0.f;
    float mA = -1e30f, mB = -1e30f, lA = 0.f, lB = 0.f;

    for (int kt = 0; kt < 16; kt++) {
        int k0 = kt << 6;
        int w01 = q0 - k0 + 449;
        int w02 = k0 - q0 + 449;
        uint32_t uK = sb + ((kt & 1) ? OFF_K1 : OFF_K0);
        uint32_t uV = sb + ((kt & 1) ? OFF_V1 : OFF_V0);

        __syncthreads(); /* S0: prev PV done -> alt K/V free */

        if (kt < 15) {
            uint32_t nK = sb + ((kt & 1) ? OFF_K0 : OFF_K1);
            uint32_t nV = sb + ((kt & 1) ? OFF_V0 : OFF_V1);
            int nk0 = k0 + 64;
#pragma unroll
            for (int i = 0; i < 4; i++) {
                int r = lr + 16 * i;
                cp16(nK + SW_OFF(r, lc), Kg + (size_t)(nk0 + r) * 64 + lc * 8);
                cp16(nV + SW_OFF(r, lc), Vg + (size_t)r * 1024 + nk0 + lc * 8);
            }
            cp_commit();
            cp_wait<1>();
        } else {
            cp_wait<0>();
        }
        __syncthreads(); /* S1: this kt's K/V + bands visible */

        /* ---- c2p band mma ---- */
        {
            float acc[16][4];
#pragma unroll
            for (int i = 0; i < 16; i++)
#pragma unroll
                for (int j = 0; j < 4; j++) acc[i][j] = 0.f;
#pragma unroll
            for (int ks = 0; ks < 4; ks++) {
                uint32_t a[4];
                ldsm4(a, uQ + SW_OFF(wq0 + (lane & 15), ks * 2 + (lane >> 4)));
#pragma unroll
                for (int np = 0; np < 8; np++) {
                    uint32_t bq[4];
                    int srow = np * 16 + (((lane >> 4) & 1) << 3) + (lane & 7);
                    int slot = (w01 + srow) & 127;
                    int sc = ks * 2 + ((lane >> 3) & 1);
                    ldsm4(bq, uB1 + SW_OFF(slot, sc));
                    mma16(acc[np * 2], a, bq);
                    mma16(acc[np * 2 + 1], a, bq + 2);
                }
            }
#pragma unroll
            for (int f = 0; f < 16; f++) {
                int col = f * 8 + q2 * 2;
                *(float2*)&C2[(wq0 + g) * TW + col] = make_float2(acc[f][0], acc[f][1]);
                *(float2*)&C2[(wq0 + g + 8) * TW + col] = make_float2(acc[f][2], acc[f][3]);
            }
        }

        /* ---- p2c band mma ---- */
        {
            float acc[16][4];
#pragma unroll
            for (int i = 0; i < 16; i++)
#pragma unroll
                for (int j = 0; j < 4; j++) acc[i][j] = 0.f;
#pragma unroll
            for (int ks = 0; ks < 4; ks++) {
                uint32_t a[4];
                ldsm4(a, uK + SW_OFF(wq0 + (lane & 15), ks * 2 + (lane >> 4)));
#pragma unroll
                for (int np = 0; np < 8; np++) {
                    uint32_t bq[4];
                    int srow = np * 16 + (((lane >> 4) & 1) << 3) + (lane & 7);
                    int slot = (w02 + srow) & 127;
                    int sc = ks * 2 + ((lane >> 3) & 1);
                    ldsm4(bq, uB2 + SW_OFF(slot, sc));
                    mma16(acc[np * 2], a, bq);
                    mma16(acc[np * 2 + 1], a, bq + 2);
                }
            }
#pragma unroll
            for (int f = 0; f < 16; f++) {
                int col = f * 8 + q2 * 2;
                *(float2*)&P2[(wq0 + g) * TW + col] = make_float2(acc[f][0], acc[f][1]);
                *(float2*)&P2[(wq0 + g + 8) * TW + col] = make_float2(acc[f][2], acc[f][3]);
            }
        }

        /* ---- QK mma ---- */
        float sS[8][4];
#pragma unroll
        for (int i = 0; i < 8; i++)
#pragma unroll
            for (int j = 0; j < 4; j++) sS[i][j] = 0.f;
#pragma unroll
        for (int ks = 0; ks < 4; ks++) {
            uint32_t a[4];
            ldsm4(a, uQ + SW_OFF(wq0 + (lane & 15), ks * 2 + (lane >> 4)));
#pragma unroll
            for (int np = 0; np < 4; np++) {
                uint32_t bq[4];
                int srow = np * 16 + (((lane >> 4) & 1) << 3) + (lane & 7);
                int sc = ks * 2 + ((lane >> 3) & 1);
                ldsm4(bq, uK + SW_OFF(srow, sc));
                mma16(sS[np * 2], a, bq);
                mma16(sS[np * 2 + 1], a, bq + 2);
            }
        }

        __syncthreads(); /* S2: ring reads + band stores done */

        if (kt < 15) { /* refill 64 new ring rows per band */
            int nw01 = w01 - 64;
            int nw02b = w02 + 128;
#pragma unroll
            for (int i = 0; i < 4; i++) {
                int r = lr + 16 * i;
                int pv = nw01 + r;
                cp16(uB1 + SW_OFF(pv & 127, lc), PKg + (size_t)min(max(pv, 0), 1023) * 64 + lc * 8);
                int pv2 = nw02b + r;
                cp16(uB2 + SW_OFF(pv2 & 127, lc), PQg + (size_t)min(max(pv2, 0), 1023) * 64 + lc * 8);
            }
            cp_commit();
        }

        /* ---- fixup + online softmax ---- */
        int qiA = wq0 + g, qiB = qiA + 8;
#pragma unroll
        for (int nst = 0; nst < 8; nst++) {
            int kj = nst * 8 + q2 * 2;
            sS[nst][0] += C2[qiA * TW + 63 + qiA - kj] + P2[kj * TW + 63 + kj - qiA];
            sS[nst][1] += C2[qiA * TW + 62 + qiA - kj] + P2[(kj + 1) * TW + 64 + kj - qiA];
            sS[nst][2] += C2[qiB * TW + 63 + qiB - kj] + P2[kj * TW + 63 + kj - qiB];
            sS[nst][3] += C2[qiB * TW + 62 + qiB - kj] + P2[(kj + 1) * TW + 64 + kj - qiB];
        }
        float mxA = -1e30f, mxB = -1e30f;
#pragma unroll
        for (int nst = 0; nst < 8; nst++) {
            mxA = fmaxf(mxA, fmaxf(sS[nst][0], sS[nst][1]));
            mxB = fmaxf(mxB, fmaxf(sS[nst][2], sS[nst][3]));
        }
        mxA = fmaxf(mxA, __shfl_xor_sync(0xffffffffu, mxA, 1, 4));
        mxA = fmaxf(mxA, __shfl_xor_sync(0xffffffffu, mxA, 2, 4));
        mxB = fmaxf(mxB, __shfl_xor_sync(0xffffffffu, mxB, 1, 4));
        mxB = fmaxf(mxB, __shfl_xor_sync(0xffffffffu, mxB, 2, 4));
        float mnA = fmaxf(mA, mxA), mnB = fmaxf(mB, mxB);
        float aA = __expf(mA - mnA), aB = __expf(mB - mnB);
        float rsA = 0.f, rsB = 0.f;
#pragma unroll
        for (int nst = 0; nst < 8; nst++) {
            float p0 = __expf(sS[nst][0] - mnA);
            float p1 = __expf(sS[nst][1] - mnA);
            float p2v = __expf(sS[nst][2] - mnB);
            float p3 = __expf(sS[nst][3] - mnB);
            rsA += p0 + p1;
            rsB += p2v + p3;
            /* store P as fp16: col = nst*8+q2*2 -> chunk nst, byte off q2*4 */
            *(__half2*)(smc + OFF_P + SW_OFF(qiA, nst) + q2 * 4) = __floats2half2_rn(p0, p1);
            *(__half2*)(smc + OFF_P + SW_OFF(qiB, nst) + q2 * 4) = __floats2half2_rn(p2v, p3);
        }
        rsA += __shfl_xor_sync(0xffffffffu, rsA, 1, 4);
        rsA += __shfl_xor_sync(0xffffffffu, rsA, 2, 4);
        rsB += __shfl_xor_sync(0xffffffffu, rsB, 1, 4);
        rsB += __shfl_xor_sync(0xffffffffu, rsB, 2, 4);
        lA = lA * aA + rsA;
        lB = lB * aB + rsB;
        mA = mnA;
        mB = mnB;
#pragma unroll
        for (int i = 0; i < 8; i++) {
            O[i][0] *= aA; O[i][1] *= aA;
            O[i][2] *= aB; O[i][3] *= aB;
        }
        __syncwarp();

        /* ---- PV mma (own 16 q rows) ---- */
#pragma unroll
        for (int ks = 0; ks < 4; ks++) {
            uint32_t a[4];
            ldsm4(a, uP + SW_OFF(wq0 + (lane & 15), ks * 2 + (lane >> 4)));
#pragma unroll
            for (int np = 0; np < 4; np++) {
                uint32_t bq[4];
                int srow = np * 16 + (((lane >> 4) & 1) << 3) + (lane & 7);
                int sc = ks * 2 + ((lane >> 3) & 1);
                ldsm4(bq, uV + SW_OFF(srow, sc));
                mma16(O[np * 2], a, bq);
                mma16(O[np * 2 + 1], a, bq + 2);
            }
        }
    }

    /* ---- epilogue: ctx as fp16 ---- */
    float invA = 1.f / lA, invB = 1.f / lB;
    int qA = q0 + wq0 + g, qB = qA + 8;
#pragma unroll
    for (int np = 0; np < 8; np++) {
        int d0 = h * 64 + np * 8 + q2 * 2;
        *(__half2*)&g_CTX[((size_t)(b * 1024) + qA) * 1024 + d0] =
            __floats2half2_rn(O[np][0] * invA, O[np][1] * invA);
        *(__half2*)&g_CTX[((size_t)(b * 1024) + qB) * 1024 + d0] =
            __floats2half2_rn(O[np][2] * invB, O[np][3] * invB);
    }
}

/* ---------------- LayerNorm ---------------- */
__global__ void __launch_bounds__(256) k_ln(const float* __restrict__ gam,
                                            const float* __restrict__ bet,
                                            float* __restrict__ out) {
    int m = blockIdx.x;
    int tid = threadIdx.x;
    const float* y = g_Y + (size_t)m * Hh;
    float4 v = *(const float4*)(y + (tid << 2));
    float s = v.x + v.y + v.z + v.w;
    float s2 = v.x * v.x + v.y * v.y + v.z * v.z + v.w * v.w;
#pragma unroll
    for (int o = 16; o; o >>= 1) {
        s += __shfl_xor_sync(0xffffffffu, s, o);
        s2 += __shfl_xor_sync(0xffffffffu, s2, o);
    }
    __shared__ float sh[8], sh2[8];
    int w = tid >> 5, ln = tid & 31;
    if (ln == 0) { sh[w] = s; sh2[w] = s2; }
    __syncthreads();
    s = 0.f; s2 = 0.f;
#pragma unroll
    for (int i = 0; i < 8; i++) { s += sh[i]; s2 += sh2[i]; }
    float mean = s * (1.0f / Hh);
    float var = s2 * (1.0f / Hh) - mean * mean;
    float inv = rsqrtf(var + 1e-7f);
    float4 g4 = *(const float4*)(gam + (tid << 2));
    float4 b4 = *(const float4*)(bet + (tid << 2));
    float4 o4;
    o4.x = g4.x * (v.x - mean) * inv + b4.x;
    o4.y = g4.y * (v.y - mean) * inv + b4.y;
    o4.z = g4.z * (v.z - mean) * inv + b4.z;
    o4.w = g4.w * (v.w - mean) * inv + b4.w;
    *(float4*)(out + (size_t)m * Hh + (tid << 2)) = o4;
}

/* ---------------- launch ---------------- */
extern "C" void kernel_launch(void* const* d_in, const int* in_sizes, int n_in,
                              void* d_out, int out_size) {
    const float* hs   = (const float*)d_in[0];
    const float* re   = (const float*)d_in[2];
    const float* w_in = (const float*)d_in[3];
    const float* qb   = (const float*)d_in[4];
    const float* vb   = (const float*)d_in[5];
    const float* w_pk = (const float*)d_in[6];
    const float* w_pq = (const float*)d_in[7];
    const float* b_pq = (const float*)d_in[8];
    const float* w_o  = (const float*)d_in[9];
    const float* b_o  = (const float*)d_in[10];
    const float* lng  = (const float*)d_in[11];
    const float* lnb  = (const float*)d_in[12];
    float* out = (float*)d_out;

    static int attr_set = 0;
    if (!attr_set) {
        cudaFuncSetAttribute(k_attn2, cudaFuncAttributeMaxDynamicSharedMemorySize, 148480);
        cudaFuncSetAttribute(gemm_k<0>, cudaFuncAttributeMaxDynamicSharedMemorySize, 98304);
        cudaFuncSetAttribute(gemm_k<1>, cudaFuncAttributeMaxDynamicSharedMemorySize, 98304);
        cudaFuncSetAttribute(gemm_k<4>, cudaFuncAttributeMaxDynamicSharedMemorySize, 98304);
        attr_set = 1;
    }

    k_round2<<<5120, 256>>>(hs, re);                                        /* 1 */
    k_transp2<<<dim3(32, 32, 3), dim3(32, 8)>>>(w_in, w_pk, w_pq, w_o, 0);  /* 2 */
    k_transp2<<<dim3(32, 32, 3), dim3(32, 8)>>>(w_in, w_pk, w_pq, w_o, 3);  /* 3 */
    gemm_k<0><<<dim3(12, 32), 256, 98304>>>(qb, vb);                        /* 4 */
    gemm_k<1><<<dim3(4, 8, 2), 256, 98304>>>(b_pq, nullptr);                /* 5 */
    k_attn2<<<dim3(16, 64), 128, 148480>>>();                               /* 6: profiled */
    gemm_k<4><<<dim3(4, 32), 256, 98304>>>(b_o, hs);                        /* 7 */
    k_ln<<<4096, 256>>>(lng, lnb, out);                                     /* 8 */
}

// round 7
// speedup vs baseline: 2.1816x; 1.3116x over previous
#include <cuda_runtime.h>
#include <cuda_fp16.h>
#include <math.h>
#include <stdint.h>

#define Bb 4
#define Ss 1024
#define Hh 1024
#define NHh 16
#define Dd 64
#define Pp 1024

#define INV_SCALE 0.07216878364870322f

/* ------------------------- scratch (fp16 operands) ------------------------- */
__device__ __half g_Q[(size_t)Bb * NHh * Ss * Dd];
__device__ __half g_K[(size_t)Bb * NHh * Ss * Dd];
__device__ __half g_VT[(size_t)Bb * NHh * Dd * Ss];   /* [bh][d][s] */
__device__ __half g_PK[(size_t)NHh * Pp * Dd];
__device__ __half g_PQ[(size_t)NHh * Pp * Dd];
__device__ __half g_CTX[(size_t)Bb * Ss * Hh];
__device__ float  g_Y[(size_t)Bb * Ss * Hh];
__device__ __half g_HS[(size_t)Bb * Ss * Hh];
__device__ __half g_RE[(size_t)Pp * Hh];
__device__ __half g_WINT[(size_t)3 * Hh * Hh];
__device__ __half g_WPKT[(size_t)Hh * Hh];
__device__ __half g_WPQT[(size_t)Hh * Hh];
__device__ __half g_WOT[(size_t)Hh * Hh];

/* ------------------------- helpers ------------------------- */
__device__ __forceinline__ void cp16(uint32_t dst, const void* src) {
    asm volatile("cp.async.cg.shared.global [%0], [%1], 16;" :: "r"(dst), "l"(src));
}
__device__ __forceinline__ void cp_commit() { asm volatile("cp.async.commit_group;"); }
template <int N> __device__ __forceinline__ void cp_wait() {
    asm volatile("cp.async.wait_group %0;" :: "n"(N));
}
__device__ __forceinline__ void ldsm4(uint32_t a[4], uint32_t addr) {
    asm volatile("ldmatrix.sync.aligned.m8n8.x4.shared.b16 {%0,%1,%2,%3}, [%4];"
                 : "=r"(a[0]), "=r"(a[1]), "=r"(a[2]), "=r"(a[3]) : "r"(addr));
}
__device__ __forceinline__ void ldsm2(uint32_t b[2], uint32_t addr) {
    asm volatile("ldmatrix.sync.aligned.m8n8.x2.shared.b16 {%0,%1}, [%2];"
                 : "=r"(b[0]), "=r"(b[1]) : "r"(addr));
}
__device__ __forceinline__ void mma16(float c[4], const uint32_t a[4], const uint32_t b[2]) {
    asm volatile(
        "mma.sync.aligned.m16n8k16.row.col.f32.f16.f16.f32 "
        "{%0,%1,%2,%3}, {%4,%5,%6,%7}, {%8,%9}, {%0,%1,%2,%3};"
        : "+f"(c[0]), "+f"(c[1]), "+f"(c[2]), "+f"(c[3])
        : "r"(a[0]), "r"(a[1]), "r"(a[2]), "r"(a[3]), "r"(b[0]), "r"(b[1]));
}

/* swizzled tile: row = 8 chunks of 16B (64 halves / 128B per row) */
#define SW_OFF(row, c) ((((row) << 3) + ((c) ^ ((row) & 7))) << 4)

/* ------------------------- prep kernels ------------------------- */
__global__ void __launch_bounds__(256) k_round2(const float* __restrict__ hs,
                                                const float* __restrict__ re) {
    int bx = blockIdx.x;
    const float* src;
    __half* dst;
    size_t i;
    if (bx < 4096) { src = hs; dst = g_HS; i = ((size_t)bx * 256 + threadIdx.x) * 4; }
    else { src = re; dst = g_RE; i = ((size_t)(bx - 4096) * 256 + threadIdx.x) * 4; }
    float4 v = *(const float4*)(src + i);
    *(__half2*)(dst + i) = __floats2half2_rn(v.x, v.y);
    *(__half2*)(dst + i + 2) = __floats2half2_rn(v.z, v.w);
}

__global__ void __launch_bounds__(256) k_transp2(const float* __restrict__ w_in,
                                                 const float* __restrict__ w_pk,
                                                 const float* __restrict__ w_pq,
                                                 const float* __restrict__ w_o, int z0) {
    int z = z0 + blockIdx.z;
    const float* src;
    __half* dst;
    int N, nbase;
    if (z < 3) { src = w_in; dst = g_WINT; N = 3072; nbase = z * 1024; }
    else if (z == 3) { src = w_pk; dst = g_WPKT; N = 1024; nbase = 0; }
    else if (z == 4) { src = w_pq; dst = g_WPQT; N = 1024; nbase = 0; }
    else { src = w_o; dst = g_WOT; N = 1024; nbase = 0; }
    __shared__ float s[32][33];
    int n0 = nbase + (blockIdx.x << 5), k0 = blockIdx.y << 5;
    int tx = threadIdx.x & 31, ty = threadIdx.x >> 5;
#pragma unroll
    for (int j = 0; j < 4; j++)
        s[ty + j * 8][tx] = src[(size_t)(k0 + ty + j * 8) * N + n0 + tx];
    __syncthreads();
#pragma unroll
    for (int j = 0; j < 4; j++)
        dst[(size_t)(n0 + ty + j * 8) * 1024 + k0 + tx] = __float2half_rn(s[tx][ty + j * 8]);
}

__global__ void k_nop() {}

/* ------------------------- fp16 GEMM (all dense modes) -------------------------
 * Block 128x256, K-stage 64 halves, 8 warps, warp tile 64x64, NS=16.
 * which==0: bx<384 -> qkv tile; bx>=384 -> pos tile (z from bx)
 * which==4: out-proj tile, grid 128
 */
#define STAGE_B 49152u

__global__ void __launch_bounds__(256, 1) gemm_all(int which,
                                                   const float* __restrict__ qb,
                                                   const float* __restrict__ vb,
                                                   const float* __restrict__ bpq,
                                                   const float* __restrict__ bo,
                                                   const float* __restrict__ hs) {
    constexpr int NS = 16;
    int bx = blockIdx.x;
    int mode, z = 0, m0, n0;
    const __half *A, *B;
    if (which == 4) {
        mode = 4; A = g_CTX; B = g_WOT;
        n0 = (bx & 3) << 8; m0 = (bx >> 2) << 7;
    } else if (bx < 384) {
        mode = 0; A = g_HS; B = g_WINT;
        n0 = (bx % 12) << 8; m0 = (bx / 12) << 7;
    } else {
        mode = 1; int i = bx - 384; z = i >> 5; int j = i & 31;
        A = g_RE; B = z ? g_WPQT : g_WPKT;
        n0 = (j & 3) << 8; m0 = (j >> 2) << 7;
    }

    extern __shared__ char smemc[];
    uint32_t sbase = (uint32_t)__cvta_generic_to_shared(smemc);

    int tid = threadIdx.x;
    int lane = tid & 31, wid = tid >> 5;
    int wm = wid & 1, wn = wid >> 1;

    int kcopy = tid & 7, rsub = tid >> 3;
    const __half* asrc0 = A + (size_t)(m0 + rsub) * 1024 + kcopy * 8;
    const __half* bsrc0 = B + (size_t)(n0 + rsub) * 1024 + kcopy * 8;

    float c[4][8][4];
#pragma unroll
    for (int i = 0; i < 4; i++)
#pragma unroll
        for (int j = 0; j < 8; j++)
#pragma unroll
            for (int r = 0; r < 4; r++) c[i][j][r] = 0.f;

#define STAGE_COPY(slot, kofs)                                                       \
    {                                                                                \
        uint32_t sb = sbase + (slot) * STAGE_B;                                      \
        _Pragma("unroll") for (int it = 0; it < 4; it++) {                           \
            int row = it * 32 + rsub;                                                \
            cp16(sb + SW_OFF(row, kcopy), asrc0 + (size_t)it * 32 * 1024 + (kofs));  \
        }                                                                            \
        _Pragma("unroll") for (int it = 0; it < 8; it++) {                           \
            int row = it * 32 + rsub;                                                \
            cp16(sb + 16384u + SW_OFF(row, kcopy),                                   \
                 bsrc0 + (size_t)it * 32 * 1024 + (kofs));                           \
        }                                                                            \
        cp_commit();                                                                 \
    }

    STAGE_COPY(0, 0)

    int arow_l = wm * 64 + (lane & 15);
    int akhalf = lane >> 4;
    int brow_base = wn * 64 + (lane & 7);
    int bkhalf = (lane >> 3) & 1;

    for (int s = 0; s < NS; s++) {
        if (s + 1 < NS) { STAGE_COPY((s + 1) & 1, (s + 1) * 64) cp_wait<1>(); }
        else cp_wait<0>();
        __syncthreads();

        uint32_t sA = sbase + (s & 1) * STAGE_B;
        uint32_t sB = sA + 16384u;

#pragma unroll
        for (int kc = 0; kc < 4; kc++) {
            uint32_t bf[8][2];
#pragma unroll
            for (int nst = 0; nst < 8; nst++) {
                int row = brow_base + nst * 8;
                ldsm2(bf[nst], sB + SW_OFF(row, kc * 2 + bkhalf));
            }
#pragma unroll
            for (int st = 0; st < 4; st++) {
                uint32_t af[4];
                int row = arow_l + st * 16;
                ldsm4(af, sA + SW_OFF(row, kc * 2 + akhalf));
#pragma unroll
                for (int nst = 0; nst < 8; nst++) mma16(c[st][nst], af, bf[nst]);
            }
        }
        __syncthreads();
    }

    int g = lane >> 2, q2 = lane & 3;
    int mbt = m0 + wm * 64, nbt = n0 + wn * 64;
#pragma unroll
    for (int st = 0; st < 4; st++) {
#pragma unroll
        for (int nst = 0; nst < 8; nst++) {
#pragma unroll
            for (int half = 0; half < 2; half++) {
                int m = mbt + st * 16 + g + half * 8;
                int n = nbt + nst * 8 + q2 * 2;
                float v0 = c[st][nst][half * 2 + 0];
                float v1 = c[st][nst][half * 2 + 1];
                if (mode == 0) {
                    int h = n / 192, rem = n - h * 192;
                    int t = rem >> 6, d = rem & 63;
                    int bq = m >> 10, srow = m & 1023;
                    size_t idx = (((size_t)(bq * 16 + h)) * 1024 + srow) * 64 + d;
                    if (t == 0) {
                        *(__half2*)&g_Q[idx] = __floats2half2_rn(
                            (v0 + qb[h * 64 + d]) * INV_SCALE,
                            (v1 + qb[h * 64 + d + 1]) * INV_SCALE);
                    } else if (t == 1) {
                        *(__half2*)&g_K[idx] = __floats2half2_rn(v0, v1);
                    } else {
                        size_t vt = (((size_t)(bq * 16 + h)) * 64 + d) * 1024 + srow;
                        g_VT[vt] = __float2half_rn(v0 + vb[h * 64 + d]);
                        g_VT[vt + 1024] = __float2half_rn(v1 + vb[h * 64 + d + 1]);
                    }
                } else if (mode == 1) {
                    int h = n >> 6, d = n & 63;
                    size_t idx = ((size_t)h * 1024 + m) * 64 + d;
                    if (z == 0) {
                        *(__half2*)&g_PK[idx] = __floats2half2_rn(v0, v1);
                    } else {
                        *(__half2*)&g_PQ[idx] = __floats2half2_rn(
                            (v0 + bpq[n]) * INV_SCALE, (v1 + bpq[n + 1]) * INV_SCALE);
                    }
                } else {
                    size_t o = (size_t)m * 1024 + n;
                    g_Y[o] = v0 + bo[n] + hs[o];
                    g_Y[o + 1] = v1 + bo[n + 1] + hs[o + 1];
                }
            }
        }
    }
#undef STAGE_COPY
}

/* ---------------- fused attention: 4 warps, 2 CTAs/SM, compact fp16 band results ----
 * SMEM: Q@0(8K) K0@8K K1@16K V0@24K V1@32K B1@40K(16K) B2@56K(16K) P@72K(8K)
 *       C2@80K(64*72*2=9216) P2@89K(9216).  Total 100352 B -> 2 CTAs/SM.
 */
#define CW 72
#define OFF_K0 8192u
#define OFF_K1 16384u
#define OFF_V0 24576u
#define OFF_V1 32768u
#define OFF_B1 40960u
#define OFF_B2 57344u
#define OFF_P  73728u
#define OFF_C2 81920u
#define OFF_P2 91136u
#define ATTN_SMEM 100352

__global__ void __launch_bounds__(128, 2) k_attn2() {
    extern __shared__ char smc[];
    uint32_t sb = (uint32_t)__cvta_generic_to_shared(smc);
    const uint32_t uQ = sb;
    const uint32_t uB1 = sb + OFF_B1;
    const uint32_t uB2 = sb + OFF_B2;
    const uint32_t uP = sb + OFF_P;
    __half* C2h = (__half*)(smc + OFF_C2);
    __half* P2h = (__half*)(smc + OFF_P2);

    int tid = threadIdx.x, lane = tid & 31, wid = tid >> 5;
    int q0 = blockIdx.x << 6, bh = blockIdx.y;
    int b = bh >> 4, h = bh & 15;
    const __half* Qg = g_Q + (size_t)bh * 65536;
    const __half* Kg = g_K + (size_t)bh * 65536;
    const __half* Vg = g_VT + (size_t)bh * 65536;
    const __half* PKg = g_PK + (size_t)h * 65536;
    const __half* PQg = g_PQ + (size_t)h * 65536;

    int lc = tid & 7, lr = tid >> 3;
    int g = lane >> 2, q2 = lane & 3;
    int wq0 = wid << 4;

    /* ---- preload G0: Q + K0 + V0 ---- */
#pragma unroll
    for (int i = 0; i < 4; i++) {
        int r = lr + 16 * i;
        cp16(uQ + SW_OFF(r, lc), Qg + (size_t)(q0 + r) * 64 + lc * 8);
        cp16(sb + OFF_K0 + SW_OFF(r, lc), Kg + (size_t)r * 64 + lc * 8);
        cp16(sb + OFF_V0 + SW_OFF(r, lc), Vg + (size_t)r * 1024 + lc * 8);
    }
    cp_commit();
    /* ---- preload G1: both 128-row bands for kt=0 ---- */
    {
        int w01 = q0 + 449, w02 = 449 - q0;
#pragma unroll
        for (int i = 0; i < 8; i++) {
            int r = lr + 16 * i;
            int pv = w01 + r;
            cp16(uB1 + SW_OFF(pv & 127, lc), PKg + (size_t)min(max(pv, 0), 1023) * 64 + lc * 8);
            int pv2 = w02 + r;
            cp16(uB2 + SW_OFF(pv2 & 127, lc), PQg + (size_t)min(max(pv2, 0), 1023) * 64 + lc * 8);
        }
    }
    cp_commit();

    float O[8][4];
#pragma unroll
    for (int i = 0; i < 8; i++)
#pragma unroll
        for (int j = 0; j < 4; j++) O[i][j] = 0.f;
    float mA = -1e30f, mB = -1e30f, lA = 0.f, lB = 0.f;

    int qiA = wq0 + g, qiB = qiA + 8;

    for (int kt = 0; kt < 16; kt++) {
        int k0 = kt << 6;
        int w01 = q0 - k0 + 449;
        int w02 = k0 - q0 + 449;
        uint32_t uK = sb + ((kt & 1) ? OFF_K1 : OFF_K0);
        uint32_t uV = sb + ((kt & 1) ? OFF_V1 : OFF_V0);

        __syncthreads(); /* S0 */

        if (kt < 15) {
            uint32_t nK = sb + ((kt & 1) ? OFF_K0 : OFF_K1);
            uint32_t nV = sb + ((kt & 1) ? OFF_V0 : OFF_V1);
            int nk0 = k0 + 64;
#pragma unroll
            for (int i = 0; i < 4; i++) {
                int r = lr + 16 * i;
                cp16(nK + SW_OFF(r, lc), Kg + (size_t)(nk0 + r) * 64 + lc * 8);
                cp16(nV + SW_OFF(r, lc), Vg + (size_t)r * 1024 + nk0 + lc * 8);
            }
            cp_commit();
            cp_wait<1>();
        } else {
            cp_wait<0>();
        }
        __syncthreads(); /* S1 */

        /* ---- c2p band mma -> compact fp16 C2 ---- */
        {
            float acc[16][4];
#pragma unroll
            for (int i = 0; i < 16; i++)
#pragma unroll
                for (int j = 0; j < 4; j++) acc[i][j] = 0.f;
#pragma unroll
            for (int ks = 0; ks < 4; ks++) {
                uint32_t a[4];
                ldsm4(a, uQ + SW_OFF(wq0 + (lane & 15), ks * 2 + (lane >> 4)));
#pragma unroll
                for (int np = 0; np < 8; np++) {
                    uint32_t bq[4];
                    int srow = np * 16 + (((lane >> 4) & 1) << 3) + (lane & 7);
                    int slot = (w01 + srow) & 127;
                    int sc = ks * 2 + ((lane >> 3) & 1);
                    ldsm4(bq, uB1 + SW_OFF(slot, sc));
                    mma16(acc[np * 2], a, bq);
                    mma16(acc[np * 2 + 1], a, bq + 2);
                }
            }
#pragma unroll
            for (int f = 0; f < 16; f++) {
                int col = f * 8 + q2 * 2;
                int cA = col - qiA, cB = col - qiB;
                if ((unsigned)cA < 64u) C2h[qiA * CW + cA] = __float2half_rn(acc[f][0]);
                if ((unsigned)(cA + 1) < 64u) C2h[qiA * CW + cA + 1] = __float2half_rn(acc[f][1]);
                if ((unsigned)cB < 64u) C2h[qiB * CW + cB] = __float2half_rn(acc[f][2]);
                if ((unsigned)(cB + 1) < 64u) C2h[qiB * CW + cB + 1] = __float2half_rn(acc[f][3]);
            }
        }

        /* ---- p2c band mma -> compact fp16 P2 ---- */
        {
            float acc[16][4];
#pragma unroll
            for (int i = 0; i < 16; i++)
#pragma unroll
                for (int j = 0; j < 4; j++) acc[i][j] = 0.f;
#pragma unroll
            for (int ks = 0; ks < 4; ks++) {
                uint32_t a[4];
                ldsm4(a, uK + SW_OFF(wq0 + (lane & 15), ks * 2 + (lane >> 4)));
#pragma unroll
                for (int np = 0; np < 8; np++) {
                    uint32_t bq[4];
                    int srow = np * 16 + (((lane >> 4) & 1) << 3) + (lane & 7);
                    int slot = (w02 + srow) & 127;
                    int sc = ks * 2 + ((lane >> 3) & 1);
                    ldsm4(bq, uB2 + SW_OFF(slot, sc));
                    mma16(acc[np * 2], a, bq);
                    mma16(acc[np * 2 + 1], a, bq + 2);
                }
            }
#pragma unroll
            for (int f = 0; f < 16; f++) {
                int col = f * 8 + q2 * 2;
                int cA = col - qiA, cB = col - qiB;
                if ((unsigned)cA < 64u) P2h[qiA * CW + cA] = __float2half_rn(acc[f][0]);
                if ((unsigned)(cA + 1) < 64u) P2h[qiA * CW + cA + 1] = __float2half_rn(acc[f][1]);
                if ((unsigned)cB < 64u) P2h[qiB * CW + cB] = __float2half_rn(acc[f][2]);
                if ((unsigned)(cB + 1) < 64u) P2h[qiB * CW + cB + 1] = __float2half_rn(acc[f][3]);
            }
        }

        /* ---- QK mma ---- */
        float sS[8][4];
#pragma unroll
        for (int i = 0; i < 8; i++)
#pragma unroll
            for (int j = 0; j < 4; j++) sS[i][j] = 0.f;
#pragma unroll
        for (int ks = 0; ks < 4; ks++) {
            uint32_t a[4];
            ldsm4(a, uQ + SW_OFF(wq0 + (lane & 15), ks * 2 + (lane >> 4)));
#pragma unroll
            for (int np = 0; np < 4; np++) {
                uint32_t bq[4];
                int srow = np * 16 + (((lane >> 4) & 1) << 3) + (lane & 7);
                int sc = ks * 2 + ((lane >> 3) & 1);
                ldsm4(bq, uK + SW_OFF(srow, sc));
                mma16(sS[np * 2], a, bq);
                mma16(sS[np * 2 + 1], a, bq + 2);
            }
        }

        __syncthreads(); /* S2: ring reads + band stores done */

        if (kt < 15) { /* refill 64 new ring rows per band */
            int nw01 = w01 - 64;
            int nw02b = w02 + 128;
#pragma unroll
            for (int i = 0; i < 4; i++) {
                int r = lr + 16 * i;
                int pv = nw01 + r;
                cp16(uB1 + SW_OFF(pv & 127, lc), PKg + (size_t)min(max(pv, 0), 1023) * 64 + lc * 8);
                int pv2 = nw02b + r;
                cp16(uB2 + SW_OFF(pv2 & 127, lc), PQg + (size_t)min(max(pv2, 0), 1023) * 64 + lc * 8);
            }
            cp_commit();
        }

        /* ---- fixup (compact reads) + online softmax ---- */
#pragma unroll
        for (int nst = 0; nst < 8; nst++) {
            int kj = nst * 8 + q2 * 2;
            __half2 ca = *(__half2*)&C2h[qiA * CW + 62 - kj];
            __half2 cb = *(__half2*)&C2h[qiB * CW + 62 - kj];
            float2 caf = __half22float2(ca);
            float2 cbf = __half22float2(cb);
            sS[nst][0] += caf.y + __half2float(P2h[kj * CW + 63 - qiA]);
            sS[nst][1] += caf.x + __half2float(P2h[(kj + 1) * CW + 63 - qiA]);
            sS[nst][2] += cbf.y + __half2float(P2h[kj * CW + 63 - qiB]);
            sS[nst][3] += cbf.x + __half2float(P2h[(kj + 1) * CW + 63 - qiB]);
        }
        float mxA = -1e30f, mxB = -1e30f;
#pragma unroll
        for (int nst = 0; nst < 8; nst++) {
            mxA = fmaxf(mxA, fmaxf(sS[nst][0], sS[nst][1]));
            mxB = fmaxf(mxB, fmaxf(sS[nst][2], sS[nst][3]));
        }
        mxA = fmaxf(mxA, __shfl_xor_sync(0xffffffffu, mxA, 1, 4));
        mxA = fmaxf(mxA, __shfl_xor_sync(0xffffffffu, mxA, 2, 4));
        mxB = fmaxf(mxB, __shfl_xor_sync(0xffffffffu, mxB, 1, 4));
        mxB = fmaxf(mxB, __shfl_xor_sync(0xffffffffu, mxB, 2, 4));
        float mnA = fmaxf(mA, mxA), mnB = fmaxf(mB, mxB);
        float aA = __expf(mA - mnA), aB = __expf(mB - mnB);
        float rsA = 0.f, rsB = 0.f;
#pragma unroll
        for (int nst = 0; nst < 8; nst++) {
            float p0 = __expf(sS[nst][0] - mnA);
            float p1 = __expf(sS[nst][1] - mnA);
            float p2v = __expf(sS[nst][2] - mnB);
            float p3 = __expf(sS[nst][3] - mnB);
            rsA += p0 + p1;
            rsB += p2v + p3;
            *(__half2*)(smc + OFF_P + SW_OFF(qiA, nst) + q2 * 4) = __floats2half2_rn(p0, p1);
            *(__half2*)(smc + OFF_P + SW_OFF(qiB, nst) + q2 * 4) = __floats2half2_rn(p2v, p3);
        }
        rsA += __shfl_xor_sync(0xffffffffu, rsA, 1, 4);
        rsA += __shfl_xor_sync(0xffffffffu, rsA, 2, 4);
        rsB += __shfl_xor_sync(0xffffffffu, rsB, 1, 4);
        rsB += __shfl_xor_sync(0xffffffffu, rsB, 2, 4);
        lA = lA * aA + rsA;
        lB = lB * aB + rsB;
        mA = mnA;
        mB = mnB;
#pragma unroll
        for (int i = 0; i < 8; i++) {
            O[i][0] *= aA; O[i][1] *= aA;
            O[i][2] *= aB; O[i][3] *= aB;
        }
        __syncwarp();

        /* ---- PV mma ---- */
#pragma unroll
        for (int ks = 0; ks < 4; ks++) {
            uint32_t a[4];
            ldsm4(a, uP + SW_OFF(wq0 + (lane & 15), ks * 2 + (lane >> 4)));
#pragma unroll
            for (int np = 0; np < 4; np++) {
                uint32_t bq[4];
                int srow = np * 16 + (((lane >> 4) & 1) << 3) + (lane & 7);
                int sc = ks * 2 + ((lane >> 3) & 1);
                ldsm4(bq, uV + SW_OFF(srow, sc));
                mma16(O[np * 2], a, bq);
                mma16(O[np * 2 + 1], a, bq + 2);
            }
        }
    }

    /* ---- epilogue ---- */
    float invA = 1.f / lA, invB = 1.f / lB;
    int qA = q0 + qiA, qB = q0 + qiB;
#pragma unroll
    for (int np = 0; np < 8; np++) {
        int d0 = h * 64 + np * 8 + q2 * 2;
        *(__half2*)&g_CTX[((size_t)(b * 1024) + qA) * 1024 + d0] =
            __floats2half2_rn(O[np][0] * invA, O[np][1] * invA);
        *(__half2*)&g_CTX[((size_t)(b * 1024) + qB) * 1024 + d0] =
            __floats2half2_rn(O[np][2] * invB, O[np][3] * invB);
    }
}

/* ---------------- LayerNorm ---------------- */
__global__ void __launch_bounds__(256) k_ln(const float* __restrict__ gam,
                                            const float* __restrict__ bet,
                                            float* __restrict__ out) {
    int m = blockIdx.x;
    int tid = threadIdx.x;
    const float* y = g_Y + (size_t)m * Hh;
    float4 v = *(const float4*)(y + (tid << 2));
    float s = v.x + v.y + v.z + v.w;
    float s2 = v.x * v.x + v.y * v.y + v.z * v.z + v.w * v.w;
#pragma unroll
    for (int o = 16; o; o >>= 1) {
        s += __shfl_xor_sync(0xffffffffu, s, o);
        s2 += __shfl_xor_sync(0xffffffffu, s2, o);
    }
    __shared__ float sh[8], sh2[8];
    int w = tid >> 5, ln = tid & 31;
    if (ln == 0) { sh[w] = s; sh2[w] = s2; }
    __syncthreads();
    s = 0.f; s2 = 0.f;
#pragma unroll
    for (int i = 0; i < 8; i++) { s += sh[i]; s2 += sh2[i]; }
    float mean = s * (1.0f / Hh);
    float var = s2 * (1.0f / Hh) - mean * mean;
    float inv = rsqrtf(var + 1e-7f);
    float4 g4 = *(const float4*)(gam + (tid << 2));
    float4 b4 = *(const float4*)(bet + (tid << 2));
    float4 o4;
    o4.x = g4.x * (v.x - mean) * inv + b4.x;
    o4.y = g4.y * (v.y - mean) * inv + b4.y;
    o4.z = g4.z * (v.z - mean) * inv + b4.z;
    o4.w = g4.w * (v.w - mean) * inv + b4.w;
    *(float4*)(out + (size_t)m * Hh + (tid << 2)) = o4;
}

/* ---------------- launch ---------------- */
extern "C" void kernel_launch(void* const* d_in, const int* in_sizes, int n_in,
                              void* d_out, int out_size) {
    const float* hs   = (const float*)d_in[0];
    const float* re   = (const float*)d_in[2];
    const float* w_in = (const float*)d_in[3];
    const float* qb   = (const float*)d_in[4];
    const float* vb   = (const float*)d_in[5];
    const float* w_pk = (const float*)d_in[6];
    const float* w_pq = (const float*)d_in[7];
    const float* b_pq = (const float*)d_in[8];
    const float* w_o  = (const float*)d_in[9];
    const float* b_o  = (const float*)d_in[10];
    const float* lng  = (const float*)d_in[11];
    const float* lnb  = (const float*)d_in[12];
    float* out = (float*)d_out;

    static int attr_set = 0;
    if (!attr_set) {
        cudaFuncSetAttribute(k_attn2, cudaFuncAttributeMaxDynamicSharedMemorySize, ATTN_SMEM);
        cudaFuncSetAttribute(gemm_all, cudaFuncAttributeMaxDynamicSharedMemorySize, 98304);
        attr_set = 1;
    }

    k_round2<<<5120, 256>>>(hs, re);                                        /* 1 */
    k_transp2<<<dim3(32, 32, 3), 256>>>(w_in, w_pk, w_pq, w_o, 0);          /* 2 */
    k_transp2<<<dim3(32, 32, 3), 256>>>(w_in, w_pk, w_pq, w_o, 3);          /* 3 */
    gemm_all<<<448, 256, 98304>>>(0, qb, vb, b_pq, b_o, hs);                /* 4 */
    k_nop<<<1, 32>>>();                                                     /* 5 */
    k_attn2<<<dim3(16, 64), 128, ATTN_SMEM>>>();                            /* 6: profiled */
    gemm_all<<<128, 256, 98304>>>(4, qb, vb, b_pq, b_o, hs);                /* 7 */
    k_ln<<<4096, 256>>>(lng, lnb, out);                                     /* 8 */
}

// round 8
// speedup vs baseline: 2.4420x; 1.1194x over previous
#include <cuda_runtime.h>
#include <cuda_fp16.h>
#include <math.h>
#include <stdint.h>

#define Bb 4
#define Ss 1024
#define Hh 1024
#define NHh 16
#define Dd 64
#define Pp 1024

#define INV_SCALE 0.07216878364870322f
#define L2E 1.4426950408889634f

/* ------------------------- scratch (fp16 operands) ------------------------- */
__device__ __half g_Q[(size_t)Bb * NHh * Ss * Dd];
__device__ __half g_K[(size_t)Bb * NHh * Ss * Dd];
__device__ __half g_VT[(size_t)Bb * NHh * Dd * Ss];
__device__ __half g_PK[(size_t)NHh * Pp * Dd];
__device__ __half g_PQ[(size_t)NHh * Pp * Dd];
__device__ __half g_CTX[(size_t)Bb * Ss * Hh];
__device__ float  g_Y[(size_t)Bb * Ss * Hh];
__device__ __half g_HS[(size_t)Bb * Ss * Hh];
__device__ __half g_RE[(size_t)Pp * Hh];
__device__ __half g_WINT[(size_t)3 * Hh * Hh];
__device__ __half g_WPKT[(size_t)Hh * Hh];
__device__ __half g_WPQT[(size_t)Hh * Hh];
__device__ __half g_WOT[(size_t)Hh * Hh];

/* ------------------------- helpers ------------------------- */
__device__ __forceinline__ void cp16(uint32_t dst, const void* src) {
    asm volatile("cp.async.cg.shared.global [%0], [%1], 16;" :: "r"(dst), "l"(src));
}
__device__ __forceinline__ void cp_commit() { asm volatile("cp.async.commit_group;"); }
template <int N> __device__ __forceinline__ void cp_wait() {
    asm volatile("cp.async.wait_group %0;" :: "n"(N));
}
__device__ __forceinline__ void ldsm4(uint32_t a[4], uint32_t addr) {
    asm volatile("ldmatrix.sync.aligned.m8n8.x4.shared.b16 {%0,%1,%2,%3}, [%4];"
                 : "=r"(a[0]), "=r"(a[1]), "=r"(a[2]), "=r"(a[3]) : "r"(addr));
}
__device__ __forceinline__ void ldsm2(uint32_t b[2], uint32_t addr) {
    asm volatile("ldmatrix.sync.aligned.m8n8.x2.shared.b16 {%0,%1}, [%2];"
                 : "=r"(b[0]), "=r"(b[1]) : "r"(addr));
}
__device__ __forceinline__ void mma16(float c[4], const uint32_t a[4], const uint32_t b[2]) {
    asm volatile(
        "mma.sync.aligned.m16n8k16.row.col.f32.f16.f16.f32 "
        "{%0,%1,%2,%3}, {%4,%5,%6,%7}, {%8,%9}, {%0,%1,%2,%3};"
        : "+f"(c[0]), "+f"(c[1]), "+f"(c[2]), "+f"(c[3])
        : "r"(a[0]), "r"(a[1]), "r"(a[2]), "r"(a[3]), "r"(b[0]), "r"(b[1]));
}
__device__ __forceinline__ uint32_t ex2h2(float e0, float e1) {
    __half2 h = __floats2half2_rn(e0, e1);
    uint32_t u = *(uint32_t*)&h, o;
    asm("ex2.approx.f16x2 %0, %1;" : "=r"(o) : "r"(u));
    return o;
}

#define SW_OFF(row, c) ((((row) << 3) + ((c) ^ ((row) & 7))) << 4)

/* ------------------------- prep kernels ------------------------- */
__global__ void __launch_bounds__(256) k_round2(const float* __restrict__ hs,
                                                const float* __restrict__ re) {
    int bx = blockIdx.x;
    const float* src;
    __half* dst;
    size_t i;
    if (bx < 4096) { src = hs; dst = g_HS; i = ((size_t)bx * 256 + threadIdx.x) * 4; }
    else { src = re; dst = g_RE; i = ((size_t)(bx - 4096) * 256 + threadIdx.x) * 4; }
    float4 v = *(const float4*)(src + i);
    *(__half2*)(dst + i) = __floats2half2_rn(v.x, v.y);
    *(__half2*)(dst + i + 2) = __floats2half2_rn(v.z, v.w);
}

__global__ void __launch_bounds__(256) k_transp2(const float* __restrict__ w_in,
                                                 const float* __restrict__ w_pk,
                                                 const float* __restrict__ w_pq,
                                                 const float* __restrict__ w_o, int z0) {
    int z = z0 + blockIdx.z;
    const float* src;
    __half* dst;
    int N, nbase;
    if (z < 3) { src = w_in; dst = g_WINT; N = 3072; nbase = z * 1024; }
    else if (z == 3) { src = w_pk; dst = g_WPKT; N = 1024; nbase = 0; }
    else if (z == 4) { src = w_pq; dst = g_WPQT; N = 1024; nbase = 0; }
    else { src = w_o; dst = g_WOT; N = 1024; nbase = 0; }
    __shared__ float s[32][33];
    int n0 = nbase + (blockIdx.x << 5), k0 = blockIdx.y << 5;
    int tx = threadIdx.x & 31, ty = threadIdx.x >> 5;
#pragma unroll
    for (int j = 0; j < 4; j++)
        s[ty + j * 8][tx] = src[(size_t)(k0 + ty + j * 8) * N + n0 + tx];
    __syncthreads();
#pragma unroll
    for (int j = 0; j < 4; j++)
        dst[(size_t)(n0 + ty + j * 8) * 1024 + k0 + tx] = __float2half_rn(s[tx][ty + j * 8]);
}

__global__ void k_nop() {}

/* ------------------------- fp16 GEMM, 128x128 block, 2 CTAs/SM -------------------------
 * 8 warps, warp tile 64x32, K-stage 64 halves, NS=16, <=128 regs.
 * which==0: bx<768 qkv (24n x 32m); bx>=768 pos (z, 8n x 8m). which==4: out 8n x 32m.
 */
#define STAGE_B 32768u

__global__ void __launch_bounds__(256, 2) gemm_all(int which,
                                                   const float* __restrict__ qb,
                                                   const float* __restrict__ vb,
                                                   const float* __restrict__ bpq,
                                                   const float* __restrict__ bo,
                                                   const float* __restrict__ hs) {
    constexpr int NS = 16;
    int bx = blockIdx.x;
    int mode, z = 0, m0, n0;
    const __half *A, *B;
    if (which == 4) {
        mode = 4; A = g_CTX; B = g_WOT;
        n0 = (bx & 7) << 7; m0 = (bx >> 3) << 7;
    } else if (bx < 768) {
        mode = 0; A = g_HS; B = g_WINT;
        n0 = (bx % 24) << 7; m0 = (bx / 24) << 7;
    } else {
        mode = 1; int i = bx - 768; z = i >> 6; int j = i & 63;
        A = g_RE; B = z ? g_WPQT : g_WPKT;
        n0 = (j & 7) << 7; m0 = (j >> 3) << 7;
    }

    extern __shared__ char smemc[];
    uint32_t sbase = (uint32_t)__cvta_generic_to_shared(smemc);

    int tid = threadIdx.x;
    int lane = tid & 31, wid = tid >> 5;
    int wm = wid & 1, wn = wid >> 1;   /* 2 x 64 M, 4 x 32 N */

    int kcopy = tid & 7, rsub = tid >> 3;
    const __half* asrc0 = A + (size_t)(m0 + rsub) * 1024 + kcopy * 8;
    const __half* bsrc0 = B + (size_t)(n0 + rsub) * 1024 + kcopy * 8;

    float c[4][4][4];
#pragma unroll
    for (int i = 0; i < 4; i++)
#pragma unroll
        for (int j = 0; j < 4; j++)
#pragma unroll
            for (int r = 0; r < 4; r++) c[i][j][r] = 0.f;

#define STAGE_COPY(slot, kofs)                                                       \
    {                                                                                \
        uint32_t sb = sbase + (slot) * STAGE_B;                                      \
        _Pragma("unroll") for (int it = 0; it < 4; it++) {                           \
            int row = it * 32 + rsub;                                                \
            cp16(sb + SW_OFF(row, kcopy), asrc0 + (size_t)it * 32 * 1024 + (kofs));  \
        }                                                                            \
        _Pragma("unroll") for (int it = 0; it < 4; it++) {                           \
            int row = it * 32 + rsub;                                                \
            cp16(sb + 16384u + SW_OFF(row, kcopy),                                   \
                 bsrc0 + (size_t)it * 32 * 1024 + (kofs));                           \
        }                                                                            \
        cp_commit();                                                                 \
    }

    STAGE_COPY(0, 0)

    int arow_l = wm * 64 + (lane & 15);
    int akhalf = lane >> 4;
    int brow_base = wn * 32 + (lane & 7);
    int bkhalf = (lane >> 3) & 1;

    for (int s = 0; s < NS; s++) {
        if (s + 1 < NS) { STAGE_COPY((s + 1) & 1, (s + 1) * 64) cp_wait<1>(); }
        else cp_wait<0>();
        __syncthreads();

        uint32_t sA = sbase + (s & 1) * STAGE_B;
        uint32_t sB = sA + 16384u;

#pragma unroll
        for (int kc = 0; kc < 4; kc++) {
            uint32_t bf[4][2];
#pragma unroll
            for (int nst = 0; nst < 4; nst++)
                ldsm2(bf[nst], sB + SW_OFF(brow_base + nst * 8, kc * 2 + bkhalf));
#pragma unroll
            for (int st = 0; st < 4; st++) {
                uint32_t af[4];
                ldsm4(af, sA + SW_OFF(arow_l + st * 16, kc * 2 + akhalf));
#pragma unroll
                for (int nst = 0; nst < 4; nst++) mma16(c[st][nst], af, bf[nst]);
            }
        }
        __syncthreads();
    }

    int g = lane >> 2, q2 = lane & 3;
    int mbt = m0 + wm * 64, nbt = n0 + wn * 32;
#pragma unroll
    for (int st = 0; st < 4; st++) {
#pragma unroll
        for (int nst = 0; nst < 4; nst++) {
#pragma unroll
            for (int half = 0; half < 2; half++) {
                int m = mbt + st * 16 + g + half * 8;
                int n = nbt + nst * 8 + q2 * 2;
                float v0 = c[st][nst][half * 2 + 0];
                float v1 = c[st][nst][half * 2 + 1];
                if (mode == 0) {
                    int h = n / 192, rem = n - h * 192;
                    int t = rem >> 6, d = rem & 63;
                    int bq = m >> 10, srow = m & 1023;
                    size_t idx = (((size_t)(bq * 16 + h)) * 1024 + srow) * 64 + d;
                    if (t == 0) {
                        *(__half2*)&g_Q[idx] = __floats2half2_rn(
                            (v0 + qb[h * 64 + d]) * INV_SCALE,
                            (v1 + qb[h * 64 + d + 1]) * INV_SCALE);
                    } else if (t == 1) {
                        *(__half2*)&g_K[idx] = __floats2half2_rn(v0, v1);
                    } else {
                        size_t vt = (((size_t)(bq * 16 + h)) * 64 + d) * 1024 + srow;
                        g_VT[vt] = __float2half_rn(v0 + vb[h * 64 + d]);
                        g_VT[vt + 1024] = __float2half_rn(v1 + vb[h * 64 + d + 1]);
                    }
                } else if (mode == 1) {
                    int h = n >> 6, d = n & 63;
                    size_t idx = ((size_t)h * 1024 + m) * 64 + d;
                    if (z == 0) {
                        *(__half2*)&g_PK[idx] = __floats2half2_rn(v0, v1);
                    } else {
                        *(__half2*)&g_PQ[idx] = __floats2half2_rn(
                            (v0 + bpq[n]) * INV_SCALE, (v1 + bpq[n + 1]) * INV_SCALE);
                    }
                } else {
                    size_t o = (size_t)m * 1024 + n;
                    g_Y[o] = v0 + bo[n] + hs[o];
                    g_Y[o + 1] = v1 + bo[n + 1] + hs[o + 1];
                }
            }
        }
    }
#undef STAGE_COPY
}

/* ---------------- fused attention: c2p ring reuse, ex2.f16x2, 2 CTAs/SM ----
 * SMEM: Q@0(8K) K0@8K K1@16K V0@24K V1@32K B1@40K(16K) B2@56K(16K) P@72K(8K)
 *       C2ring@80K(64*136*2=17408) P2@99328(64*72*2=9216). total 108544.
 */
#define CW 72
#define CRW 136
#define OFF_K0 8192u
#define OFF_K1 16384u
#define OFF_V0 24576u
#define OFF_V1 32768u
#define OFF_B1 40960u
#define OFF_B2 57344u
#define OFF_P  73728u
#define OFF_C2 81920u
#define OFF_P2 99328u
#define ATTN_SMEM 108544

__global__ void __launch_bounds__(128, 2) k_attn2() {
    extern __shared__ char smc[];
    uint32_t sb = (uint32_t)__cvta_generic_to_shared(smc);
    const uint32_t uQ = sb;
    const uint32_t uB1 = sb + OFF_B1;
    const uint32_t uB2 = sb + OFF_B2;
    const uint32_t uP = sb + OFF_P;
    __half* C2r = (__half*)(smc + OFF_C2);
    __half* P2h = (__half*)(smc + OFF_P2);

    int tid = threadIdx.x, lane = tid & 31, wid = tid >> 5;
    int q0 = blockIdx.x << 6, bh = blockIdx.y;
    int b = bh >> 4, h = bh & 15;
    const __half* Qg = g_Q + (size_t)bh * 65536;
    const __half* Kg = g_K + (size_t)bh * 65536;
    const __half* Vg = g_VT + (size_t)bh * 65536;
    const __half* PKg = g_PK + (size_t)h * 65536;
    const __half* PQg = g_PQ + (size_t)h * 65536;

    int lc = tid & 7, lr = tid >> 3;
    int g = lane >> 2, q2 = lane & 3;
    int wq0 = wid << 4;
    int qiA = wq0 + g, qiB = qiA + 8;

    /* preload G0: Q + K0 + V0 */
#pragma unroll
    for (int i = 0; i < 4; i++) {
        int r = lr + 16 * i;
        cp16(uQ + SW_OFF(r, lc), Qg + (size_t)(q0 + r) * 64 + lc * 8);
        cp16(sb + OFF_K0 + SW_OFF(r, lc), Kg + (size_t)r * 64 + lc * 8);
        cp16(sb + OFF_V0 + SW_OFF(r, lc), Vg + (size_t)r * 1024 + lc * 8);
    }
    cp_commit();
    /* preload G1: both 128-row bands for kt=0 */
    {
        int w01 = q0 + 449, w02 = 449 - q0;
#pragma unroll
        for (int i = 0; i < 8; i++) {
            int r = lr + 16 * i;
            int pv = w01 + r;
            cp16(uB1 + SW_OFF(pv & 127, lc), PKg + (size_t)min(max(pv, 0), 1023) * 64 + lc * 8);
            int pv2 = w02 + r;
            cp16(uB2 + SW_OFF(pv2 & 127, lc), PQg + (size_t)min(max(pv2, 0), 1023) * 64 + lc * 8);
        }
    }
    cp_commit();

    float O[8][4];
#pragma unroll
    for (int i = 0; i < 8; i++)
#pragma unroll
        for (int j = 0; j < 4; j++) O[i][j] = 0.f;
    float mA = -1e30f, mB = -1e30f, lA = 0.f, lB = 0.f;

    for (int kt = 0; kt < 16; kt++) {
        int k0 = kt << 6;
        int w01 = q0 - k0 + 449;
        int w02 = k0 - q0 + 449;
        uint32_t uK = sb + ((kt & 1) ? OFF_K1 : OFF_K0);
        uint32_t uV = sb + ((kt & 1) ? OFF_V1 : OFF_V0);

        __syncthreads(); /* S0 */

        if (kt < 15) {
            uint32_t nK = sb + ((kt & 1) ? OFF_K0 : OFF_K1);
            uint32_t nV = sb + ((kt & 1) ? OFF_V0 : OFF_V1);
            int nk0 = k0 + 64;
#pragma unroll
            for (int i = 0; i < 4; i++) {
                int r = lr + 16 * i;
                cp16(nK + SW_OFF(r, lc), Kg + (size_t)(nk0 + r) * 64 + lc * 8);
                cp16(nV + SW_OFF(r, lc), Vg + (size_t)r * 1024 + nk0 + lc * 8);
            }
            cp_commit();
            cp_wait<1>();
        } else {
            cp_wait<0>();
        }
        __syncthreads(); /* S1 */

        /* ---- c2p band mma: only 64 NEW columns (128 at kt==0) ---- */
        if (kt == 0) {
            float acc[16][4];
#pragma unroll
            for (int i = 0; i < 16; i++)
#pragma unroll
                for (int j = 0; j < 4; j++) acc[i][j] = 0.f;
#pragma unroll
            for (int ks = 0; ks < 4; ks++) {
                uint32_t a[4];
                ldsm4(a, uQ + SW_OFF(wq0 + (lane & 15), ks * 2 + (lane >> 4)));
#pragma unroll
                for (int np = 0; np < 8; np++) {
                    uint32_t bq[4];
                    int srow = np * 16 + (((lane >> 4) & 1) << 3) + (lane & 7);
                    int slot = (w01 + srow) & 127;
                    ldsm4(bq, uB1 + SW_OFF(slot, ks * 2 + ((lane >> 3) & 1)));
                    mma16(acc[np * 2], a, bq);
                    mma16(acc[np * 2 + 1], a, bq + 2);
                }
            }
#pragma unroll
            for (int f = 0; f < 16; f++) {
                int col = f * 8 + q2 * 2;
                int s0 = (w01 + col) & 127, s1 = (w01 + col + 1) & 127;
                C2r[qiA * CRW + s0] = __float2half_rn(acc[f][0]);
                C2r[qiA * CRW + s1] = __float2half_rn(acc[f][1]);
                C2r[qiB * CRW + s0] = __float2half_rn(acc[f][2]);
                C2r[qiB * CRW + s1] = __float2half_rn(acc[f][3]);
            }
        } else {
            float acc[8][4];
#pragma unroll
            for (int i = 0; i < 8; i++)
#pragma unroll
                for (int j = 0; j < 4; j++) acc[i][j] = 0.f;
#pragma unroll
            for (int ks = 0; ks < 4; ks++) {
                uint32_t a[4];
                ldsm4(a, uQ + SW_OFF(wq0 + (lane & 15), ks * 2 + (lane >> 4)));
#pragma unroll
                for (int np = 0; np < 4; np++) {
                    uint32_t bq[4];
                    int srow = np * 16 + (((lane >> 4) & 1) << 3) + (lane & 7);
                    int slot = (w01 + srow) & 127;
                    ldsm4(bq, uB1 + SW_OFF(slot, ks * 2 + ((lane >> 3) & 1)));
                    mma16(acc[np * 2], a, bq);
                    mma16(acc[np * 2 + 1], a, bq + 2);
                }
            }
#pragma unroll
            for (int f = 0; f < 8; f++) {
                int col = f * 8 + q2 * 2;
                int s0 = (w01 + col) & 127, s1 = (w01 + col + 1) & 127;
                C2r[qiA * CRW + s0] = __float2half_rn(acc[f][0]);
                C2r[qiA * CRW + s1] = __float2half_rn(acc[f][1]);
                C2r[qiB * CRW + s0] = __float2half_rn(acc[f][2]);
                C2r[qiB * CRW + s1] = __float2half_rn(acc[f][3]);
            }
        }

        /* ---- p2c band mma -> compact fp16 P2 (no reuse possible) ---- */
        {
            float acc[16][4];
#pragma unroll
            for (int i = 0; i < 16; i++)
#pragma unroll
                for (int j = 0; j < 4; j++) acc[i][j] = 0.f;
#pragma unroll
            for (int ks = 0; ks < 4; ks++) {
                uint32_t a[4];
                ldsm4(a, uK + SW_OFF(wq0 + (lane & 15), ks * 2 + (lane >> 4)));
#pragma unroll
                for (int np = 0; np < 8; np++) {
                    uint32_t bq[4];
                    int srow = np * 16 + (((lane >> 4) & 1) << 3) + (lane & 7);
                    int slot = (w02 + srow) & 127;
                    ldsm4(bq, uB2 + SW_OFF(slot, ks * 2 + ((lane >> 3) & 1)));
                    mma16(acc[np * 2], a, bq);
                    mma16(acc[np * 2 + 1], a, bq + 2);
                }
            }
#pragma unroll
            for (int f = 0; f < 16; f++) {
                int col = f * 8 + q2 * 2;
                int cA = col - qiA, cB = col - qiB;
                if ((unsigned)cA < 64u) P2h[qiA * CW + cA] = __float2half_rn(acc[f][0]);
                if ((unsigned)(cA + 1) < 64u) P2h[qiA * CW + cA + 1] = __float2half_rn(acc[f][1]);
                if ((unsigned)cB < 64u) P2h[qiB * CW + cB] = __float2half_rn(acc[f][2]);
                if ((unsigned)(cB + 1) < 64u) P2h[qiB * CW + cB + 1] = __float2half_rn(acc[f][3]);
            }
        }

        /* ---- QK mma ---- */
        float sS[8][4];
#pragma unroll
        for (int i = 0; i < 8; i++)
#pragma unroll
            for (int j = 0; j < 4; j++) sS[i][j] = 0.f;
#pragma unroll
        for (int ks = 0; ks < 4; ks++) {
            uint32_t a[4];
            ldsm4(a, uQ + SW_OFF(wq0 + (lane & 15), ks * 2 + (lane >> 4)));
#pragma unroll
            for (int np = 0; np < 4; np++) {
                uint32_t bq[4];
                int srow = np * 16 + (((lane >> 4) & 1) << 3) + (lane & 7);
                ldsm4(bq, uK + SW_OFF(srow, ks * 2 + ((lane >> 3) & 1)));
                mma16(sS[np * 2], a, bq);
                mma16(sS[np * 2 + 1], a, bq + 2);
            }
        }

        __syncthreads(); /* S2: ring reads + P2 stores done */

        if (kt < 15) { /* refill 64 new ring rows per band */
            int nw01 = w01 - 64;
            int nw02b = w02 + 128;
#pragma unroll
            for (int i = 0; i < 4; i++) {
                int r = lr + 16 * i;
                int pv = nw01 + r;
                cp16(uB1 + SW_OFF(pv & 127, lc), PKg + (size_t)min(max(pv, 0), 1023) * 64 + lc * 8);
                int pv2 = nw02b + r;
                cp16(uB2 + SW_OFF(pv2 & 127, lc), PQg + (size_t)min(max(pv2, 0), 1023) * 64 + lc * 8);
            }
            cp_commit();
        }

        /* ---- fixup + online softmax (ex2.f16x2) ---- */
#pragma unroll
        for (int nst = 0; nst < 8; nst++) {
            int kj = nst * 8 + q2 * 2;
            int bA = w01 + 63 + qiA - kj;
            int bB = w01 + 63 + qiB - kj;
            sS[nst][0] += __half2float(C2r[qiA * CRW + (bA & 127)]) +
                          __half2float(P2h[kj * CW + 63 - qiA]);
            sS[nst][1] += __half2float(C2r[qiA * CRW + ((bA - 1) & 127)]) +
                          __half2float(P2h[(kj + 1) * CW + 63 - qiA]);
            sS[nst][2] += __half2float(C2r[qiB * CRW + (bB & 127)]) +
                          __half2float(P2h[kj * CW + 63 - qiB]);
            sS[nst][3] += __half2float(C2r[qiB * CRW + ((bB - 1) & 127)]) +
                          __half2float(P2h[(kj + 1) * CW + 63 - qiB]);
        }
        float mxA = -1e30f, mxB = -1e30f;
#pragma unroll
        for (int nst = 0; nst < 8; nst++) {
            mxA = fmaxf(mxA, fmaxf(sS[nst][0], sS[nst][1]));
            mxB = fmaxf(mxB, fmaxf(sS[nst][2], sS[nst][3]));
        }
        mxA = fmaxf(mxA, __shfl_xor_sync(0xffffffffu, mxA, 1, 4));
        mxA = fmaxf(mxA, __shfl_xor_sync(0xffffffffu, mxA, 2, 4));
        mxB = fmaxf(mxB, __shfl_xor_sync(0xffffffffu, mxB, 1, 4));
        mxB = fmaxf(mxB, __shfl_xor_sync(0xffffffffu, mxB, 2, 4));
        float mnA = fmaxf(mA, mxA), mnB = fmaxf(mB, mxB);
        float aA = __expf(mA - mnA), aB = __expf(mB - mnB);
        float rsA = 0.f, rsB = 0.f;
#pragma unroll
        for (int nst = 0; nst < 8; nst++) {
            uint32_t pa = ex2h2((sS[nst][0] - mnA) * L2E, (sS[nst][1] - mnA) * L2E);
            uint32_t pb = ex2h2((sS[nst][2] - mnB) * L2E, (sS[nst][3] - mnB) * L2E);
            float2 fa = __half22float2(*(__half2*)&pa);
            float2 fb = __half22float2(*(__half2*)&pb);
            rsA += fa.x + fa.y;
            rsB += fb.x + fb.y;
            *(uint32_t*)(smc + OFF_P + SW_OFF(qiA, nst) + q2 * 4) = pa;
            *(uint32_t*)(smc + OFF_P + SW_OFF(qiB, nst) + q2 * 4) = pb;
        }
        rsA += __shfl_xor_sync(0xffffffffu, rsA, 1, 4);
        rsA += __shfl_xor_sync(0xffffffffu, rsA, 2, 4);
        rsB += __shfl_xor_sync(0xffffffffu, rsB, 1, 4);
        rsB += __shfl_xor_sync(0xffffffffu, rsB, 2, 4);
        lA = lA * aA + rsA;
        lB = lB * aB + rsB;
        mA = mnA;
        mB = mnB;
#pragma unroll
        for (int i = 0; i < 8; i++) {
            O[i][0] *= aA; O[i][1] *= aA;
            O[i][2] *= aB; O[i][3] *= aB;
        }
        __syncwarp();

        /* ---- PV mma ---- */
#pragma unroll
        for (int ks = 0; ks < 4; ks++) {
            uint32_t a[4];
            ldsm4(a, uP + SW_OFF(wq0 + (lane & 15), ks * 2 + (lane >> 4)));
#pragma unroll
            for (int np = 0; np < 4; np++) {
                uint32_t bq[4];
                int srow = np * 16 + (((lane >> 4) & 1) << 3) + (lane & 7);
                ldsm4(bq, uV + SW_OFF(srow, ks * 2 + ((lane >> 3) & 1)));
                mma16(O[np * 2], a, bq);
                mma16(O[np * 2 + 1], a, bq + 2);
            }
        }
    }

    /* ---- epilogue ---- */
    float invA = 1.f / lA, invB = 1.f / lB;
    int qA = q0 + qiA, qB = q0 + qiB;
#pragma unroll
    for (int np = 0; np < 8; np++) {
        int d0 = h * 64 + np * 8 + q2 * 2;
        *(__half2*)&g_CTX[((size_t)(b * 1024) + qA) * 1024 + d0] =
            __floats2half2_rn(O[np][0] * invA, O[np][1] * invA);
        *(__half2*)&g_CTX[((size_t)(b * 1024) + qB) * 1024 + d0] =
            __floats2half2_rn(O[np][2] * invB, O[np][3] * invB);
    }
}

/* ---------------- LayerNorm ---------------- */
__global__ void __launch_bounds__(256) k_ln(const float* __restrict__ gam,
                                            const float* __restrict__ bet,
                                            float* __restrict__ out) {
    int m = blockIdx.x;
    int tid = threadIdx.x;
    const float* y = g_Y + (size_t)m * Hh;
    float4 v = *(const float4*)(y + (tid << 2));
    float s = v.x + v.y + v.z + v.w;
    float s2 = v.x * v.x + v.y * v.y + v.z * v.z + v.w * v.w;
#pragma unroll
    for (int o = 16; o; o >>= 1) {
        s += __shfl_xor_sync(0xffffffffu, s, o);
        s2 += __shfl_xor_sync(0xffffffffu, s2, o);
    }
    __shared__ float sh[8], sh2[8];
    int w = tid >> 5, ln = tid & 31;
    if (ln == 0) { sh[w] = s; sh2[w] = s2; }
    __syncthreads();
    s = 0.f; s2 = 0.f;
#pragma unroll
    for (int i = 0; i < 8; i++) { s += sh[i]; s2 += sh2[i]; }
    float mean = s * (1.0f / Hh);
    float var = s2 * (1.0f / Hh) - mean * mean;
    float inv = rsqrtf(var + 1e-7f);
    float4 g4 = *(const float4*)(gam + (tid << 2));
    float4 b4 = *(const float4*)(bet + (tid << 2));
    float4 o4;
    o4.x = g4.x * (v.x - mean) * inv + b4.x;
    o4.y = g4.y * (v.y - mean) * inv + b4.y;
    o4.z = g4.z * (v.z - mean) * inv + b4.z;
    o4.w = g4.w * (v.w - mean) * inv + b4.w;
    *(float4*)(out + (size_t)m * Hh + (tid << 2)) = o4;
}

/* ---------------- launch ---------------- */
extern "C" void kernel_launch(void* const* d_in, const int* in_sizes, int n_in,
                              void* d_out, int out_size) {
    const float* hs   = (const float*)d_in[0];
    const float* re   = (const float*)d_in[2];
    const float* w_in = (const float*)d_in[3];
    const float* qb   = (const float*)d_in[4];
    const float* vb   = (const float*)d_in[5];
    const float* w_pk = (const float*)d_in[6];
    const float* w_pq = (const float*)d_in[7];
    const float* b_pq = (const float*)d_in[8];
    const float* w_o  = (const float*)d_in[9];
    const float* b_o  = (const float*)d_in[10];
    const float* lng  = (const float*)d_in[11];
    const float* lnb  = (const float*)d_in[12];
    float* out = (float*)d_out;

    static int attr_set = 0;
    if (!attr_set) {
        cudaFuncSetAttribute(k_attn2, cudaFuncAttributeMaxDynamicSharedMemorySize, ATTN_SMEM);
        cudaFuncSetAttribute(gemm_all, cudaFuncAttributeMaxDynamicSharedMemorySize, 65536);
        attr_set = 1;
    }

    k_round2<<<5120, 256>>>(hs, re);                                        /* 1 */
    k_transp2<<<dim3(32, 32, 3), 256>>>(w_in, w_pk, w_pq, w_o, 0);          /* 2 */
    k_transp2<<<dim3(32, 32, 3), 256>>>(w_in, w_pk, w_pq, w_o, 3);          /* 3 */
    gemm_all<<<896, 256, 65536>>>(0, qb, vb, b_pq, b_o, hs);                /* 4 */
    k_nop<<<1, 32>>>();                                                     /* 5 */
    k_attn2<<<dim3(16, 64), 128, ATTN_SMEM>>>();                            /* 6: profiled */
    gemm_all<<<256, 256, 65536>>>(4, qb, vb, b_pq, b_o, hs);                /* 7 */
    k_ln<<<4096, 256>>>(lng, lnb, out);                                     /* 8 */
}

// round 9
// speedup vs baseline: 2.8000x; 1.1466x over previous
#include <cuda_runtime.h>
#include <cuda_fp16.h>
#include <math.h>
#include <stdint.h>

#define Bb 4
#define Ss 1024
#define Hh 1024
#define NHh 16
#define Dd 64
#define Pp 1024

#define INV_SCALE 0.07216878364870322f
#define L2E 1.4426950408889634f

/* ------------------------- scratch (fp16 operands) ------------------------- */
__device__ __half g_Q[(size_t)Bb * NHh * Ss * Dd];
__device__ __half g_K[(size_t)Bb * NHh * Ss * Dd];
__device__ __half g_VT[(size_t)Bb * NHh * Dd * Ss];
__device__ __half g_PK[(size_t)NHh * Pp * Dd];
__device__ __half g_PQ[(size_t)NHh * Pp * Dd];
__device__ __half g_CTX[(size_t)Bb * Ss * Hh];
__device__ float  g_Y[(size_t)Bb * Ss * Hh];
__device__ __half g_HS[(size_t)Bb * Ss * Hh];
__device__ __half g_RE[(size_t)Pp * Hh];
__device__ __half g_WINT[(size_t)3 * Hh * Hh];
__device__ __half g_WPKT[(size_t)Hh * Hh];
__device__ __half g_WPQT[(size_t)Hh * Hh];
__device__ __half g_WOT[(size_t)Hh * Hh];

/* ------------------------- helpers ------------------------- */
__device__ __forceinline__ void cp16(uint32_t dst, const void* src) {
    asm volatile("cp.async.cg.shared.global [%0], [%1], 16;" :: "r"(dst), "l"(src));
}
__device__ __forceinline__ void cp_commit() { asm volatile("cp.async.commit_group;"); }
template <int N> __device__ __forceinline__ void cp_wait() {
    asm volatile("cp.async.wait_group %0;" :: "n"(N));
}
__device__ __forceinline__ void ldsm4(uint32_t a[4], uint32_t addr) {
    asm volatile("ldmatrix.sync.aligned.m8n8.x4.shared.b16 {%0,%1,%2,%3}, [%4];"
                 : "=r"(a[0]), "=r"(a[1]), "=r"(a[2]), "=r"(a[3]) : "r"(addr));
}
__device__ __forceinline__ void ldsm2(uint32_t b[2], uint32_t addr) {
    asm volatile("ldmatrix.sync.aligned.m8n8.x2.shared.b16 {%0,%1}, [%2];"
                 : "=r"(b[0]), "=r"(b[1]) : "r"(addr));
}
__device__ __forceinline__ void mma16(float c[4], const uint32_t a[4], const uint32_t b[2]) {
    asm volatile(
        "mma.sync.aligned.m16n8k16.row.col.f32.f16.f16.f32 "
        "{%0,%1,%2,%3}, {%4,%5,%6,%7}, {%8,%9}, {%0,%1,%2,%3};"
        : "+f"(c[0]), "+f"(c[1]), "+f"(c[2]), "+f"(c[3])
        : "r"(a[0]), "r"(a[1]), "r"(a[2]), "r"(a[3]), "r"(b[0]), "r"(b[1]));
}
__device__ __forceinline__ uint32_t ex2h2(float e0, float e1) {
    __half2 h = __floats2half2_rn(e0, e1);
    uint32_t u = *(uint32_t*)&h, o;
    asm("ex2.approx.f16x2 %0, %1;" : "=r"(o) : "r"(u));
    return o;
}

#define SW_OFF(row, c) ((((row) << 3) + ((c) ^ ((row) & 7))) << 4)

/* ------------------------- prep kernels ------------------------- */
__global__ void __launch_bounds__(256) k_round2(const float* __restrict__ hs,
                                                const float* __restrict__ re) {
    int bx = blockIdx.x;
    const float* src;
    __half* dst;
    size_t i;
    if (bx < 4096) { src = hs; dst = g_HS; i = ((size_t)bx * 256 + threadIdx.x) * 4; }
    else { src = re; dst = g_RE; i = ((size_t)(bx - 4096) * 256 + threadIdx.x) * 4; }
    float4 v = *(const float4*)(src + i);
    *(__half2*)(dst + i) = __floats2half2_rn(v.x, v.y);
    *(__half2*)(dst + i + 2) = __floats2half2_rn(v.z, v.w);
}

__global__ void __launch_bounds__(256) k_transp2(const float* __restrict__ w_in,
                                                 const float* __restrict__ w_pk,
                                                 const float* __restrict__ w_pq,
                                                 const float* __restrict__ w_o, int z0) {
    int z = z0 + blockIdx.z;
    const float* src;
    __half* dst;
    int N, nbase;
    if (z < 3) { src = w_in; dst = g_WINT; N = 3072; nbase = z * 1024; }
    else if (z == 3) { src = w_pk; dst = g_WPKT; N = 1024; nbase = 0; }
    else if (z == 4) { src = w_pq; dst = g_WPQT; N = 1024; nbase = 0; }
    else { src = w_o; dst = g_WOT; N = 1024; nbase = 0; }
    __shared__ float s[32][33];
    int n0 = nbase + (blockIdx.x << 5), k0 = blockIdx.y << 5;
    int tx = threadIdx.x & 31, ty = threadIdx.x >> 5;
#pragma unroll
    for (int j = 0; j < 4; j++)
        s[ty + j * 8][tx] = src[(size_t)(k0 + ty + j * 8) * N + n0 + tx];
    __syncthreads();
#pragma unroll
    for (int j = 0; j < 4; j++)
        dst[(size_t)(n0 + ty + j * 8) * 1024 + k0 + tx] = __float2half_rn(s[tx][ty + j * 8]);
}

/* ------------------------- fp16 GEMM, 128x128 block, 2 CTAs/SM ------------------------- */
#define STAGE_B 32768u

__global__ void __launch_bounds__(256, 2) gemm_all(int which,
                                                   const float* __restrict__ qb,
                                                   const float* __restrict__ vb,
                                                   const float* __restrict__ bpq,
                                                   const float* __restrict__ bo,
                                                   const float* __restrict__ hs) {
    constexpr int NS = 16;
    int bx = blockIdx.x;
    int mode, z = 0, m0, n0;
    const __half *A, *B;
    if (which == 4) {
        mode = 4; A = g_CTX; B = g_WOT;
        n0 = (bx & 7) << 7; m0 = (bx >> 3) << 7;
    } else if (bx < 768) {
        mode = 0; A = g_HS; B = g_WINT;
        n0 = (bx % 24) << 7; m0 = (bx / 24) << 7;
    } else {
        mode = 1; int i = bx - 768; z = i >> 6; int j = i & 63;
        A = g_RE; B = z ? g_WPQT : g_WPKT;
        n0 = (j & 7) << 7; m0 = (j >> 3) << 7;
    }

    extern __shared__ char smemc[];
    uint32_t sbase = (uint32_t)__cvta_generic_to_shared(smemc);

    int tid = threadIdx.x;
    int lane = tid & 31, wid = tid >> 5;
    int wm = wid & 1, wn = wid >> 1;

    int kcopy = tid & 7, rsub = tid >> 3;
    const __half* asrc0 = A + (size_t)(m0 + rsub) * 1024 + kcopy * 8;
    const __half* bsrc0 = B + (size_t)(n0 + rsub) * 1024 + kcopy * 8;

    float c[4][4][4];
#pragma unroll
    for (int i = 0; i < 4; i++)
#pragma unroll
        for (int j = 0; j < 4; j++)
#pragma unroll
            for (int r = 0; r < 4; r++) c[i][j][r] = 0.f;

#define STAGE_COPY(slot, kofs)                                                       \
    {                                                                                \
        uint32_t sb = sbase + (slot) * STAGE_B;                                      \
        _Pragma("unroll") for (int it = 0; it < 4; it++) {                           \
            int row = it * 32 + rsub;                                                \
            cp16(sb + SW_OFF(row, kcopy), asrc0 + (size_t)it * 32 * 1024 + (kofs));  \
        }                                                                            \
        _Pragma("unroll") for (int it = 0; it < 4; it++) {                           \
            int row = it * 32 + rsub;                                                \
            cp16(sb + 16384u + SW_OFF(row, kcopy),                                   \
                 bsrc0 + (size_t)it * 32 * 1024 + (kofs));                           \
        }                                                                            \
        cp_commit();                                                                 \
    }

    STAGE_COPY(0, 0)

    int arow_l = wm * 64 + (lane & 15);
    int akhalf = lane >> 4;
    int brow_base = wn * 32 + (lane & 7);
    int bkhalf = (lane >> 3) & 1;

    for (int s = 0; s < NS; s++) {
        if (s + 1 < NS) { STAGE_COPY((s + 1) & 1, (s + 1) * 64) cp_wait<1>(); }
        else cp_wait<0>();
        __syncthreads();

        uint32_t sA = sbase + (s & 1) * STAGE_B;
        uint32_t sB = sA + 16384u;

#pragma unroll
        for (int kc = 0; kc < 4; kc++) {
            uint32_t bf[4][2];
#pragma unroll
            for (int nst = 0; nst < 4; nst++)
                ldsm2(bf[nst], sB + SW_OFF(brow_base + nst * 8, kc * 2 + bkhalf));
#pragma unroll
            for (int st = 0; st < 4; st++) {
                uint32_t af[4];
                ldsm4(af, sA + SW_OFF(arow_l + st * 16, kc * 2 + akhalf));
#pragma unroll
                for (int nst = 0; nst < 4; nst++) mma16(c[st][nst], af, bf[nst]);
            }
        }
        __syncthreads();
    }

    int g = lane >> 2, q2 = lane & 3;
    int mbt = m0 + wm * 64, nbt = n0 + wn * 32;
#pragma unroll
    for (int st = 0; st < 4; st++) {
#pragma unroll
        for (int nst = 0; nst < 4; nst++) {
#pragma unroll
            for (int half = 0; half < 2; half++) {
                int m = mbt + st * 16 + g + half * 8;
                int n = nbt + nst * 8 + q2 * 2;
                float v0 = c[st][nst][half * 2 + 0];
                float v1 = c[st][nst][half * 2 + 1];
                if (mode == 0) {
                    int h = n / 192, rem = n - h * 192;
                    int t = rem >> 6, d = rem & 63;
                    int bq = m >> 10, srow = m & 1023;
                    size_t idx = (((size_t)(bq * 16 + h)) * 1024 + srow) * 64 + d;
                    if (t == 0) {
                        *(__half2*)&g_Q[idx] = __floats2half2_rn(
                            (v0 + qb[h * 64 + d]) * INV_SCALE,
                            (v1 + qb[h * 64 + d + 1]) * INV_SCALE);
                    } else if (t == 1) {
                        *(__half2*)&g_K[idx] = __floats2half2_rn(v0, v1);
                    } else {
                        size_t vt = (((size_t)(bq * 16 + h)) * 64 + d) * 1024 + srow;
                        g_VT[vt] = __float2half_rn(v0 + vb[h * 64 + d]);
                        g_VT[vt + 1024] = __float2half_rn(v1 + vb[h * 64 + d + 1]);
                    }
                } else if (mode == 1) {
                    int h = n >> 6, d = n & 63;
                    size_t idx = ((size_t)h * 1024 + m) * 64 + d;
                    if (z == 0) {
                        *(__half2*)&g_PK[idx] = __floats2half2_rn(v0, v1);
                    } else {
                        *(__half2*)&g_PQ[idx] = __floats2half2_rn(
                            (v0 + bpq[n]) * INV_SCALE, (v1 + bpq[n + 1]) * INV_SCALE);
                    }
                } else {
                    size_t o = (size_t)m * 1024 + n;
                    g_Y[o] = v0 + bo[n] + hs[o];
                    g_Y[o + 1] = v1 + bo[n + 1] + hs[o + 1];
                }
            }
        }
    }
#undef STAGE_COPY
}

/* ---------------- fused attention: k-keyed C2 ring, transposed P2, trimmed p2c ----
 * SMEM: Q@0(8K) K0@8K K1@16K V0@24K V1@32K B1@40K(16K) B2@56K(16K) P@72K(8K)
 *       C2k@80K(64*136*2=17408) P2t@99328(64*72*2=9216). total 108544.
 */
#define CW 72
#define CRW 136
#define OFF_K0 8192u
#define OFF_K1 16384u
#define OFF_V0 24576u
#define OFF_V1 32768u
#define OFF_B1 40960u
#define OFF_B2 57344u
#define OFF_P  73728u
#define OFF_C2 81920u
#define OFF_P2 99328u
#define ATTN_SMEM 108544

__global__ void __launch_bounds__(128, 2) k_attn2() {
    extern __shared__ char smc[];
    uint32_t sb = (uint32_t)__cvta_generic_to_shared(smc);
    const uint32_t uQ = sb;
    const uint32_t uB1 = sb + OFF_B1;
    const uint32_t uB2 = sb + OFF_B2;
    const uint32_t uP = sb + OFF_P;
    __half* C2k = (__half*)(smc + OFF_C2);   /* [q row][k&127] */
    __half* P2t = (__half*)(smc + OFF_P2);   /* [63-q][k row]  */

    int tid = threadIdx.x, lane = tid & 31, wid = tid >> 5;
    int q0 = blockIdx.x << 6, bh = blockIdx.y;
    int b = bh >> 4, h = bh & 15;
    const __half* Qg = g_Q + (size_t)bh * 65536;
    const __half* Kg = g_K + (size_t)bh * 65536;
    const __half* Vg = g_VT + (size_t)bh * 65536;
    const __half* PKg = g_PK + (size_t)h * 65536;
    const __half* PQg = g_PQ + (size_t)h * 65536;

    int lc = tid & 7, lr = tid >> 3;
    int g = lane >> 2, q2 = lane & 3;
    int wq0 = wid << 4;
    int qiA = wq0 + g, qiB = qiA + 8;

    /* preload G0: Q + K0 + V0 */
#pragma unroll
    for (int i = 0; i < 4; i++) {
        int r = lr + 16 * i;
        cp16(uQ + SW_OFF(r, lc), Qg + (size_t)(q0 + r) * 64 + lc * 8);
        cp16(sb + OFF_K0 + SW_OFF(r, lc), Kg + (size_t)r * 64 + lc * 8);
        cp16(sb + OFF_V0 + SW_OFF(r, lc), Vg + (size_t)r * 1024 + lc * 8);
    }
    cp_commit();
    /* preload G1: both 128-row bands for kt=0 */
    {
        int w01 = q0 + 449, w02 = 449 - q0;
#pragma unroll
        for (int i = 0; i < 8; i++) {
            int r = lr + 16 * i;
            int pv = w01 + r;
            cp16(uB1 + SW_OFF(pv & 127, lc), PKg + (size_t)min(max(pv, 0), 1023) * 64 + lc * 8);
            int pv2 = w02 + r;
            cp16(uB2 + SW_OFF(pv2 & 127, lc), PQg + (size_t)min(max(pv2, 0), 1023) * 64 + lc * 8);
        }
    }
    cp_commit();

    float O[8][4];
#pragma unroll
    for (int i = 0; i < 8; i++)
#pragma unroll
        for (int j = 0; j < 4; j++) O[i][j] = 0.f;
    float mA = -1e30f, mB = -1e30f, lA = 0.f, lB = 0.f;

    for (int kt = 0; kt < 16; kt++) {
        int k0 = kt << 6;
        int w01 = q0 - k0 + 449;
        int w02 = k0 - q0 + 449;
        uint32_t uK = sb + ((kt & 1) ? OFF_K1 : OFF_K0);
        uint32_t uV = sb + ((kt & 1) ? OFF_V1 : OFF_V0);

        __syncthreads(); /* S0 */

        if (kt < 15) {
            uint32_t nK = sb + ((kt & 1) ? OFF_K0 : OFF_K1);
            uint32_t nV = sb + ((kt & 1) ? OFF_V0 : OFF_V1);
            int nk0 = k0 + 64;
#pragma unroll
            for (int i = 0; i < 4; i++) {
                int r = lr + 16 * i;
                cp16(nK + SW_OFF(r, lc), Kg + (size_t)(nk0 + r) * 64 + lc * 8);
                cp16(nV + SW_OFF(r, lc), Vg + (size_t)r * 1024 + nk0 + lc * 8);
            }
            cp_commit();
            cp_wait<1>();
        } else {
            cp_wait<0>();
        }
        __syncthreads(); /* S1 */

        /* ---- c2p band mma: 64 new cols (128 at kt==0), stores keyed by global k ---- */
        if (kt == 0) {
            float acc[16][4];
#pragma unroll
            for (int i = 0; i < 16; i++)
#pragma unroll
                for (int j = 0; j < 4; j++) acc[i][j] = 0.f;
#pragma unroll
            for (int ks = 0; ks < 4; ks++) {
                uint32_t a[4];
                ldsm4(a, uQ + SW_OFF(wq0 + (lane & 15), ks * 2 + (lane >> 4)));
#pragma unroll
                for (int np = 0; np < 8; np++) {
                    uint32_t bq[4];
                    int srow = np * 16 + (((lane >> 4) & 1) << 3) + (lane & 7);
                    int slot = (w01 + srow) & 127;
                    ldsm4(bq, uB1 + SW_OFF(slot, ks * 2 + ((lane >> 3) & 1)));
                    mma16(acc[np * 2], a, bq);
                    mma16(acc[np * 2 + 1], a, bq + 2);
                }
            }
#pragma unroll
            for (int f = 0; f < 16; f++) {
                int col = f * 8 + q2 * 2;
                C2k[qiA * CRW + ((63 + qiA - col) & 127)] = __float2half_rn(acc[f][0]);
                C2k[qiA * CRW + ((62 + qiA - col) & 127)] = __float2half_rn(acc[f][1]);
                C2k[qiB * CRW + ((63 + qiB - col) & 127)] = __float2half_rn(acc[f][2]);
                C2k[qiB * CRW + ((62 + qiB - col) & 127)] = __float2half_rn(acc[f][3]);
            }
        } else {
            float acc[8][4];
#pragma unroll
            for (int i = 0; i < 8; i++)
#pragma unroll
                for (int j = 0; j < 4; j++) acc[i][j] = 0.f;
#pragma unroll
            for (int ks = 0; ks < 4; ks++) {
                uint32_t a[4];
                ldsm4(a, uQ + SW_OFF(wq0 + (lane & 15), ks * 2 + (lane >> 4)));
#pragma unroll
                for (int np = 0; np < 4; np++) {
                    uint32_t bq[4];
                    int srow = np * 16 + (((lane >> 4) & 1) << 3) + (lane & 7);
                    int slot = (w01 + srow) & 127;
                    ldsm4(bq, uB1 + SW_OFF(slot, ks * 2 + ((lane >> 3) & 1)));
                    mma16(acc[np * 2], a, bq);
                    mma16(acc[np * 2 + 1], a, bq + 2);
                }
            }
#pragma unroll
            for (int f = 0; f < 8; f++) {
                int col = f * 8 + q2 * 2;
                C2k[qiA * CRW + ((k0 + 63 + qiA - col) & 127)] = __float2half_rn(acc[f][0]);
                C2k[qiA * CRW + ((k0 + 62 + qiA - col) & 127)] = __float2half_rn(acc[f][1]);
                C2k[qiB * CRW + ((k0 + 63 + qiB - col) & 127)] = __float2half_rn(acc[f][2]);
                C2k[qiB * CRW + ((k0 + 62 + qiB - col) & 127)] = __float2half_rn(acc[f][3]);
            }
        }

        /* ---- p2c band mma: only 5 needed ring groups; store transposed ---- */
        {
            float acc[10][4];
#pragma unroll
            for (int i = 0; i < 10; i++)
#pragma unroll
                for (int j = 0; j < 4; j++) acc[i][j] = 0.f;
#pragma unroll
            for (int ks = 0; ks < 4; ks++) {
                uint32_t a[4];
                ldsm4(a, uK + SW_OFF(wq0 + (lane & 15), ks * 2 + (lane >> 4)));
#pragma unroll
                for (int j = 0; j < 5; j++) {
                    uint32_t bq[4];
                    int srow = wq0 + j * 16 + (((lane >> 4) & 1) << 3) + (lane & 7);
                    int slot = (w02 + srow) & 127;
                    ldsm4(bq, uB2 + SW_OFF(slot, ks * 2 + ((lane >> 3) & 1)));
                    mma16(acc[j * 2], a, bq);
                    mma16(acc[j * 2 + 1], a, bq + 2);
                }
            }
#pragma unroll
            for (int f = 0; f < 10; f++) {
                int col = wq0 + (f >> 1) * 16 + (f & 1) * 8 + q2 * 2;
                int cA = col - qiA, cB = col - qiB;
                if ((unsigned)cA < 64u) P2t[cA * CW + qiA] = __float2half_rn(acc[f][0]);
                if ((unsigned)(cA + 1) < 64u) P2t[(cA + 1) * CW + qiA] = __float2half_rn(acc[f][1]);
                if ((unsigned)cB < 64u) P2t[cB * CW + qiB] = __float2half_rn(acc[f][2]);
                if ((unsigned)(cB + 1) < 64u) P2t[(cB + 1) * CW + qiB] = __float2half_rn(acc[f][3]);
            }
        }

        /* ---- QK mma ---- */
        float sS[8][4];
#pragma unroll
        for (int i = 0; i < 8; i++)
#pragma unroll
            for (int j = 0; j < 4; j++) sS[i][j] = 0.f;
#pragma unroll
        for (int ks = 0; ks < 4; ks++) {
            uint32_t a[4];
            ldsm4(a, uQ + SW_OFF(wq0 + (lane & 15), ks * 2 + (lane >> 4)));
#pragma unroll
            for (int np = 0; np < 4; np++) {
                uint32_t bq[4];
                int srow = np * 16 + (((lane >> 4) & 1) << 3) + (lane & 7);
                ldsm4(bq, uK + SW_OFF(srow, ks * 2 + ((lane >> 3) & 1)));
                mma16(sS[np * 2], a, bq);
                mma16(sS[np * 2 + 1], a, bq + 2);
            }
        }

        __syncthreads(); /* S2: ring reads + band stores visible */

        if (kt < 15) { /* refill 64 new ring rows per band */
            int nw01 = w01 - 64;
            int nw02b = w02 + 128;
#pragma unroll
            for (int i = 0; i < 4; i++) {
                int r = lr + 16 * i;
                int pv = nw01 + r;
                cp16(uB1 + SW_OFF(pv & 127, lc), PKg + (size_t)min(max(pv, 0), 1023) * 64 + lc * 8);
                int pv2 = nw02b + r;
                cp16(uB2 + SW_OFF(pv2 & 127, lc), PQg + (size_t)min(max(pv2, 0), 1023) * 64 + lc * 8);
            }
            cp_commit();
        }

        /* ---- fixup (vectorized half2 reads) + online softmax ---- */
#pragma unroll
        for (int nst = 0; nst < 8; nst++) {
            int kj = nst * 8 + q2 * 2;
            float2 caf = __half22float2(*(__half2*)&C2k[qiA * CRW + ((k0 + kj) & 127)]);
            float2 cbf = __half22float2(*(__half2*)&C2k[qiB * CRW + ((k0 + kj) & 127)]);
            float2 paf = __half22float2(*(__half2*)&P2t[(63 - qiA) * CW + kj]);
            float2 pbf = __half22float2(*(__half2*)&P2t[(63 - qiB) * CW + kj]);
            sS[nst][0] += caf.x + paf.x;
            sS[nst][1] += caf.y + paf.y;
            sS[nst][2] += cbf.x + pbf.x;
            sS[nst][3] += cbf.y + pbf.y;
        }
        float mxA = -1e30f, mxB = -1e30f;
#pragma unroll
        for (int nst = 0; nst < 8; nst++) {
            mxA = fmaxf(mxA, fmaxf(sS[nst][0], sS[nst][1]));
            mxB = fmaxf(mxB, fmaxf(sS[nst][2], sS[nst][3]));
        }
        mxA = fmaxf(mxA, __shfl_xor_sync(0xffffffffu, mxA, 1, 4));
        mxA = fmaxf(mxA, __shfl_xor_sync(0xffffffffu, mxA, 2, 4));
        mxB = fmaxf(mxB, __shfl_xor_sync(0xffffffffu, mxB, 1, 4));
        mxB = fmaxf(mxB, __shfl_xor_sync(0xffffffffu, mxB, 2, 4));
        float mnA = fmaxf(mA, mxA), mnB = fmaxf(mB, mxB);
        float aA = __expf(mA - mnA), aB = __expf(mB - mnB);
        float rsA = 0.f, rsB = 0.f;
#pragma unroll
        for (int nst = 0; nst < 8; nst++) {
            uint32_t pa = ex2h2((sS[nst][0] - mnA) * L2E, (sS[nst][1] - mnA) * L2E);
            uint32_t pb = ex2h2((sS[nst][2] - mnB) * L2E, (sS[nst][3] - mnB) * L2E);
            float2 fa = __half22float2(*(__half2*)&pa);
            float2 fb = __half22float2(*(__half2*)&pb);
            rsA += fa.x + fa.y;
            rsB += fb.x + fb.y;
            *(uint32_t*)(smc + OFF_P + SW_OFF(qiA, nst) + q2 * 4) = pa;
            *(uint32_t*)(smc + OFF_P + SW_OFF(qiB, nst) + q2 * 4) = pb;
        }
        rsA += __shfl_xor_sync(0xffffffffu, rsA, 1, 4);
        rsA += __shfl_xor_sync(0xffffffffu, rsA, 2, 4);
        rsB += __shfl_xor_sync(0xffffffffu, rsB, 1, 4);
        rsB += __shfl_xor_sync(0xffffffffu, rsB, 2, 4);
        lA = lA * aA + rsA;
        lB = lB * aB + rsB;
        mA = mnA;
        mB = mnB;
#pragma unroll
        for (int i = 0; i < 8; i++) {
            O[i][0] *= aA; O[i][1] *= aA;
            O[i][2] *= aB; O[i][3] *= aB;
        }
        __syncwarp();

        /* ---- PV mma ---- */
#pragma unroll
        for (int ks = 0; ks < 4; ks++) {
            uint32_t a[4];
            ldsm4(a, uP + SW_OFF(wq0 + (lane & 15), ks * 2 + (lane >> 4)));
#pragma unroll
            for (int np = 0; np < 4; np++) {
                uint32_t bq[4];
                int srow = np * 16 + (((lane >> 4) & 1) << 3) + (lane & 7);
                ldsm4(bq, uV + SW_OFF(srow, ks * 2 + ((lane >> 3) & 1)));
                mma16(O[np * 2], a, bq);
                mma16(O[np * 2 + 1], a, bq + 2);
            }
        }
    }

    /* ---- epilogue ---- */
    float invA = 1.f / lA, invB = 1.f / lB;
    int qA = q0 + qiA, qB = q0 + qiB;
#pragma unroll
    for (int np = 0; np < 8; np++) {
        int d0 = h * 64 + np * 8 + q2 * 2;
        *(__half2*)&g_CTX[((size_t)(b * 1024) + qA) * 1024 + d0] =
            __floats2half2_rn(O[np][0] * invA, O[np][1] * invA);
        *(__half2*)&g_CTX[((size_t)(b * 1024) + qB) * 1024 + d0] =
            __floats2half2_rn(O[np][2] * invB, O[np][3] * invB);
    }
}

/* ---------------- LayerNorm ---------------- */
__global__ void __launch_bounds__(256) k_ln(const float* __restrict__ gam,
                                            const float* __restrict__ bet,
                                            float* __restrict__ out) {
    int m = blockIdx.x;
    int tid = threadIdx.x;
    const float* y = g_Y + (size_t)m * Hh;
    float4 v = *(const float4*)(y + (tid << 2));
    float s = v.x + v.y + v.z + v.w;
    float s2 = v.x * v.x + v.y * v.y + v.z * v.z + v.w * v.w;
#pragma unroll
    for (int o = 16; o; o >>= 1) {
        s += __shfl_xor_sync(0xffffffffu, s, o);
        s2 += __shfl_xor_sync(0xffffffffu, s2, o);
    }
    __shared__ float sh[8], sh2[8];
    int w = tid >> 5, ln = tid & 31;
    if (ln == 0) { sh[w] = s; sh2[w] = s2; }
    __syncthreads();
    s = 0.f; s2 = 0.f;
#pragma unroll
    for (int i = 0; i < 8; i++) { s += sh[i]; s2 += sh2[i]; }
    float mean = s * (1.0f / Hh);
    float var = s2 * (1.0f / Hh) - mean * mean;
    float inv = rsqrtf(var + 1e-7f);
    float4 g4 = *(const float4*)(gam + (tid << 2));
    float4 b4 = *(const float4*)(bet + (tid << 2));
    float4 o4;
    o4.x = g4.x * (v.x - mean) * inv + b4.x;
    o4.y = g4.y * (v.y - mean) * inv + b4.y;
    o4.z = g4.z * (v.z - mean) * inv + b4.z;
    o4.w = g4.w * (v.w - mean) * inv + b4.w;
    *(float4*)(out + (size_t)m * Hh + (tid << 2)) = o4;
}

/* ---------------- launch ---------------- */
extern "C" void kernel_launch(void* const* d_in, const int* in_sizes, int n_in,
                              void* d_out, int out_size) {
    const float* hs   = (const float*)d_in[0];
    const float* re   = (const float*)d_in[2];
    const float* w_in = (const float*)d_in[3];
    const float* qb   = (const float*)d_in[4];
    const float* vb   = (const float*)d_in[5];
    const float* w_pk = (const float*)d_in[6];
    const float* w_pq = (const float*)d_in[7];
    const float* b_pq = (const float*)d_in[8];
    const float* w_o  = (const float*)d_in[9];
    const float* b_o  = (const float*)d_in[10];
    const float* lng  = (const float*)d_in[11];
    const float* lnb  = (const float*)d_in[12];
    float* out = (float*)d_out;

    static int attr_set = 0;
    if (!attr_set) {
        cudaFuncSetAttribute(k_attn2, cudaFuncAttributeMaxDynamicSharedMemorySize, ATTN_SMEM);
        cudaFuncSetAttribute(gemm_all, cudaFuncAttributeMaxDynamicSharedMemorySize, 65536);
        attr_set = 1;
    }

    k_round2<<<5120, 256>>>(hs, re);                                        /* 1 */
    k_transp2<<<dim3(32, 32, 6), 256>>>(w_in, w_pk, w_pq, w_o, 0);          /* 2 */
    gemm_all<<<896, 256, 65536>>>(0, qb, vb, b_pq, b_o, hs);                /* 3 */
    k_attn2<<<dim3(16, 64), 128, ATTN_SMEM>>>();                            /* 4: profiled */
    gemm_all<<<256, 256, 65536>>>(4, qb, vb, b_pq, b_o, hs);                /* 5 */
    k_ln<<<4096, 256>>>(lng, lnb, out);                                     /* 6 */
}

// round 10
// speedup vs baseline: 2.9432x; 1.0511x over previous
#include <cuda_runtime.h>
#include <cuda_fp16.h>
#include <math.h>
#include <stdint.h>

#define Bb 4
#define Ss 1024
#define Hh 1024
#define NHh 16
#define Dd 64
#define Pp 1024

#define INV_SCALE 0.07216878364870322f
#define L2E 1.4426950408889634f
#define QSCALE (0.07216878364870322f * 1.4426950408889634f)

/* ------------------------- scratch (fp16 operands) ------------------------- */
__device__ __half g_Q[(size_t)Bb * NHh * Ss * Dd];
__device__ __half g_K[(size_t)Bb * NHh * Ss * Dd];
__device__ __half g_VT[(size_t)Bb * NHh * Dd * Ss];
__device__ __half g_PK[(size_t)NHh * Pp * Dd];
__device__ __half g_PQ[(size_t)NHh * Pp * Dd];
__device__ __half g_CTX[(size_t)Bb * Ss * Hh];
__device__ float  g_Y[(size_t)Bb * Ss * Hh];
__device__ __half g_HS[(size_t)Bb * Ss * Hh];
__device__ __half g_RE[(size_t)Pp * Hh];
__device__ __half g_WINT[(size_t)3 * Hh * Hh];
__device__ __half g_WPKT[(size_t)Hh * Hh];
__device__ __half g_WPQT[(size_t)Hh * Hh];
__device__ __half g_WOT[(size_t)Hh * Hh];

/* ------------------------- helpers ------------------------- */
__device__ __forceinline__ void cp16(uint32_t dst, const void* src) {
    asm volatile("cp.async.cg.shared.global [%0], [%1], 16;" :: "r"(dst), "l"(src));
}
__device__ __forceinline__ void cp_commit() { asm volatile("cp.async.commit_group;"); }
template <int N> __device__ __forceinline__ void cp_wait() {
    asm volatile("cp.async.wait_group %0;" :: "n"(N));
}
__device__ __forceinline__ void ldsm4(uint32_t a[4], uint32_t addr) {
    asm volatile("ldmatrix.sync.aligned.m8n8.x4.shared.b16 {%0,%1,%2,%3}, [%4];"
                 : "=r"(a[0]), "=r"(a[1]), "=r"(a[2]), "=r"(a[3]) : "r"(addr));
}
__device__ __forceinline__ void ldsm2(uint32_t b[2], uint32_t addr) {
    asm volatile("ldmatrix.sync.aligned.m8n8.x2.shared.b16 {%0,%1}, [%2];"
                 : "=r"(b[0]), "=r"(b[1]) : "r"(addr));
}
__device__ __forceinline__ void mma16(float c[4], const uint32_t a[4], const uint32_t b[2]) {
    asm volatile(
        "mma.sync.aligned.m16n8k16.row.col.f32.f16.f16.f32 "
        "{%0,%1,%2,%3}, {%4,%5,%6,%7}, {%8,%9}, {%0,%1,%2,%3};"
        : "+f"(c[0]), "+f"(c[1]), "+f"(c[2]), "+f"(c[3])
        : "r"(a[0]), "r"(a[1]), "r"(a[2]), "r"(a[3]), "r"(b[0]), "r"(b[1]));
}
__device__ __forceinline__ uint32_t ex2h2(float e0, float e1) {
    __half2 h = __floats2half2_rn(e0, e1);
    uint32_t u = *(uint32_t*)&h, o;
    asm("ex2.approx.f16x2 %0, %1;" : "=r"(o) : "r"(u));
    return o;
}

#define SW_OFF(row, c) ((((row) << 3) + ((c) ^ ((row) & 7))) << 4)

/* ------------------------- prep kernels ------------------------- */
__global__ void __launch_bounds__(256) k_round2(const float* __restrict__ hs,
                                                const float* __restrict__ re) {
    int bx = blockIdx.x;
    const float* src;
    __half* dst;
    size_t i;
    if (bx < 4096) { src = hs; dst = g_HS; i = ((size_t)bx * 256 + threadIdx.x) * 4; }
    else { src = re; dst = g_RE; i = ((size_t)(bx - 4096) * 256 + threadIdx.x) * 4; }
    float4 v = *(const float4*)(src + i);
    *(__half2*)(dst + i) = __floats2half2_rn(v.x, v.y);
    *(__half2*)(dst + i + 2) = __floats2half2_rn(v.z, v.w);
}

__global__ void __launch_bounds__(256) k_transp2(const float* __restrict__ w_in,
                                                 const float* __restrict__ w_pk,
                                                 const float* __restrict__ w_pq,
                                                 const float* __restrict__ w_o, int z0) {
    int z = z0 + blockIdx.z;
    const float* src;
    __half* dst;
    int N, nbase;
    if (z < 3) { src = w_in; dst = g_WINT; N = 3072; nbase = z * 1024; }
    else if (z == 3) { src = w_pk; dst = g_WPKT; N = 1024; nbase = 0; }
    else if (z == 4) { src = w_pq; dst = g_WPQT; N = 1024; nbase = 0; }
    else { src = w_o; dst = g_WOT; N = 1024; nbase = 0; }
    __shared__ float s[32][33];
    int n0 = nbase + (blockIdx.x << 5), k0 = blockIdx.y << 5;
    int tx = threadIdx.x & 31, ty = threadIdx.x >> 5;
#pragma unroll
    for (int j = 0; j < 4; j++)
        s[ty + j * 8][tx] = src[(size_t)(k0 + ty + j * 8) * N + n0 + tx];
    __syncthreads();
#pragma unroll
    for (int j = 0; j < 4; j++)
        dst[(size_t)(n0 + ty + j * 8) * 1024 + k0 + tx] = __float2half_rn(s[tx][ty + j * 8]);
}

/* ------------------------- fp16 GEMM, 128x128 block, 2 CTAs/SM ------------------------- */
#define STAGE_B 32768u

__global__ void __launch_bounds__(256, 2) gemm_all(int which,
                                                   const float* __restrict__ qb,
                                                   const float* __restrict__ vb,
                                                   const float* __restrict__ bpq,
                                                   const float* __restrict__ bo,
                                                   const float* __restrict__ hs) {
    constexpr int NS = 16;
    int bx = blockIdx.x;
    int mode, z = 0, m0, n0;
    const __half *A, *B;
    if (which == 4) {
        mode = 4; A = g_CTX; B = g_WOT;
        n0 = (bx & 7) << 7; m0 = (bx >> 3) << 7;
    } else if (bx < 768) {
        mode = 0; A = g_HS; B = g_WINT;
        n0 = (bx % 24) << 7; m0 = (bx / 24) << 7;
    } else {
        mode = 1; int i = bx - 768; z = i >> 6; int j = i & 63;
        A = g_RE; B = z ? g_WPQT : g_WPKT;
        n0 = (j & 7) << 7; m0 = (j >> 3) << 7;
    }

    extern __shared__ char smemc[];
    uint32_t sbase = (uint32_t)__cvta_generic_to_shared(smemc);

    int tid = threadIdx.x;
    int lane = tid & 31, wid = tid >> 5;
    int wm = wid & 1, wn = wid >> 1;

    int kcopy = tid & 7, rsub = tid >> 3;
    const __half* asrc0 = A + (size_t)(m0 + rsub) * 1024 + kcopy * 8;
    const __half* bsrc0 = B + (size_t)(n0 + rsub) * 1024 + kcopy * 8;

    float c[4][4][4];
#pragma unroll
    for (int i = 0; i < 4; i++)
#pragma unroll
        for (int j = 0; j < 4; j++)
#pragma unroll
            for (int r = 0; r < 4; r++) c[i][j][r] = 0.f;

#define STAGE_COPY(slot, kofs)                                                       \
    {                                                                                \
        uint32_t sb = sbase + (slot) * STAGE_B;                                      \
        _Pragma("unroll") for (int it = 0; it < 4; it++) {                           \
            int row = it * 32 + rsub;                                                \
            cp16(sb + SW_OFF(row, kcopy), asrc0 + (size_t)it * 32 * 1024 + (kofs));  \
        }                                                                            \
        _Pragma("unroll") for (int it = 0; it < 4; it++) {                           \
            int row = it * 32 + rsub;                                                \
            cp16(sb + 16384u + SW_OFF(row, kcopy),                                   \
                 bsrc0 + (size_t)it * 32 * 1024 + (kofs));                           \
        }                                                                            \
        cp_commit();                                                                 \
    }

    STAGE_COPY(0, 0)

    int arow_l = wm * 64 + (lane & 15);
    int akhalf = lane >> 4;
    int brow_base = wn * 32 + (lane & 7);
    int bkhalf = (lane >> 3) & 1;

    for (int s = 0; s < NS; s++) {
        if (s + 1 < NS) { STAGE_COPY((s + 1) & 1, (s + 1) * 64) cp_wait<1>(); }
        else cp_wait<0>();
        __syncthreads();

        uint32_t sA = sbase + (s & 1) * STAGE_B;
        uint32_t sB = sA + 16384u;

#pragma unroll
        for (int kc = 0; kc < 4; kc++) {
            uint32_t bf[4][2];
#pragma unroll
            for (int nst = 0; nst < 4; nst++)
                ldsm2(bf[nst], sB + SW_OFF(brow_base + nst * 8, kc * 2 + bkhalf));
#pragma unroll
            for (int st = 0; st < 4; st++) {
                uint32_t af[4];
                ldsm4(af, sA + SW_OFF(arow_l + st * 16, kc * 2 + akhalf));
#pragma unroll
                for (int nst = 0; nst < 4; nst++) mma16(c[st][nst], af, bf[nst]);
            }
        }
        __syncthreads();
    }

    int g = lane >> 2, q2 = lane & 3;
    int mbt = m0 + wm * 64, nbt = n0 + wn * 32;
#pragma unroll
    for (int st = 0; st < 4; st++) {
#pragma unroll
        for (int nst = 0; nst < 4; nst++) {
#pragma unroll
            for (int half = 0; half < 2; half++) {
                int m = mbt + st * 16 + g + half * 8;
                int n = nbt + nst * 8 + q2 * 2;
                float v0 = c[st][nst][half * 2 + 0];
                float v1 = c[st][nst][half * 2 + 1];
                if (mode == 0) {
                    int h = n / 192, rem = n - h * 192;
                    int t = rem >> 6, d = rem & 63;
                    int bq = m >> 10, srow = m & 1023;
                    size_t idx = (((size_t)(bq * 16 + h)) * 1024 + srow) * 64 + d;
                    if (t == 0) {
                        *(__half2*)&g_Q[idx] = __floats2half2_rn(
                            (v0 + qb[h * 64 + d]) * QSCALE,
                            (v1 + qb[h * 64 + d + 1]) * QSCALE);
                    } else if (t == 1) {
                        *(__half2*)&g_K[idx] = __floats2half2_rn(v0, v1);
                    } else {
                        size_t vt = (((size_t)(bq * 16 + h)) * 64 + d) * 1024 + srow;
                        g_VT[vt] = __float2half_rn(v0 + vb[h * 64 + d]);
                        g_VT[vt + 1024] = __float2half_rn(v1 + vb[h * 64 + d + 1]);
                    }
                } else if (mode == 1) {
                    int h = n >> 6, d = n & 63;
                    size_t idx = ((size_t)h * 1024 + m) * 64 + d;
                    if (z == 0) {
                        *(__half2*)&g_PK[idx] = __floats2half2_rn(v0, v1);
                    } else {
                        *(__half2*)&g_PQ[idx] = __floats2half2_rn(
                            (v0 + bpq[n]) * QSCALE, (v1 + bpq[n + 1]) * QSCALE);
                    }
                } else {
                    size_t o = (size_t)m * 1024 + n;
                    g_Y[o] = v0 + bo[n] + hs[o];
                    g_Y[o + 1] = v1 + bo[n + 1] + hs[o + 1];
                }
            }
        }
    }
#undef STAGE_COPY
}

/* ---------------- fused attention: no-max softmax, register-resident P ----
 * SMEM: Q@0(8K) K0@8K K1@16K V0@24K V1@32K B1@40K(16K) B2@56K(16K)
 *       C2k@72K(64*136*2=17408) P2t@91136(64*72*2=9216). total 100352.
 * All score components pre-scaled by log2(e) (Q and PQ carry the factor).
 */
#define CW 72
#define CRW 136
#define OFF_K0 8192u
#define OFF_K1 16384u
#define OFF_V0 24576u
#define OFF_V1 32768u
#define OFF_B1 40960u
#define OFF_B2 57344u
#define OFF_C2 73728u
#define OFF_P2 91136u
#define ATTN_SMEM 100352

__global__ void __launch_bounds__(128, 2) k_attn2() {
    extern __shared__ char smc[];
    uint32_t sb = (uint32_t)__cvta_generic_to_shared(smc);
    const uint32_t uQ = sb;
    const uint32_t uB1 = sb + OFF_B1;
    const uint32_t uB2 = sb + OFF_B2;
    __half* C2k = (__half*)(smc + OFF_C2);
    __half* P2t = (__half*)(smc + OFF_P2);

    int tid = threadIdx.x, lane = tid & 31, wid = tid >> 5;
    int q0 = blockIdx.x << 6, bh = blockIdx.y;
    int b = bh >> 4, h = bh & 15;
    const __half* Qg = g_Q + (size_t)bh * 65536;
    const __half* Kg = g_K + (size_t)bh * 65536;
    const __half* Vg = g_VT + (size_t)bh * 65536;
    const __half* PKg = g_PK + (size_t)h * 65536;
    const __half* PQg = g_PQ + (size_t)h * 65536;

    int lc = tid & 7, lr = tid >> 3;
    int g = lane >> 2, q2 = lane & 3;
    int wq0 = wid << 4;
    int qiA = wq0 + g, qiB = qiA + 8;

    /* preload G0: Q + K0 + V0 */
#pragma unroll
    for (int i = 0; i < 4; i++) {
        int r = lr + 16 * i;
        cp16(uQ + SW_OFF(r, lc), Qg + (size_t)(q0 + r) * 64 + lc * 8);
        cp16(sb + OFF_K0 + SW_OFF(r, lc), Kg + (size_t)r * 64 + lc * 8);
        cp16(sb + OFF_V0 + SW_OFF(r, lc), Vg + (size_t)r * 1024 + lc * 8);
    }
    cp_commit();
    /* preload G1: both 128-row bands for kt=0 */
    {
        int w01 = q0 + 449, w02 = 449 - q0;
#pragma unroll
        for (int i = 0; i < 8; i++) {
            int r = lr + 16 * i;
            int pv = w01 + r;
            cp16(uB1 + SW_OFF(pv & 127, lc), PKg + (size_t)min(max(pv, 0), 1023) * 64 + lc * 8);
            int pv2 = w02 + r;
            cp16(uB2 + SW_OFF(pv2 & 127, lc), PQg + (size_t)min(max(pv2, 0), 1023) * 64 + lc * 8);
        }
    }
    cp_commit();

    float O[8][4];
#pragma unroll
    for (int i = 0; i < 8; i++)
#pragma unroll
        for (int j = 0; j < 4; j++) O[i][j] = 0.f;
    float lA = 0.f, lB = 0.f;

    for (int kt = 0; kt < 16; kt++) {
        int k0 = kt << 6;
        int w01 = q0 - k0 + 449;
        int w02 = k0 - q0 + 449;
        uint32_t uK = sb + ((kt & 1) ? OFF_K1 : OFF_K0);
        uint32_t uV = sb + ((kt & 1) ? OFF_V1 : OFF_V0);

        __syncthreads(); /* S0 */

        if (kt < 15) {
            uint32_t nK = sb + ((kt & 1) ? OFF_K0 : OFF_K1);
            uint32_t nV = sb + ((kt & 1) ? OFF_V0 : OFF_V1);
            int nk0 = k0 + 64;
#pragma unroll
            for (int i = 0; i < 4; i++) {
                int r = lr + 16 * i;
                cp16(nK + SW_OFF(r, lc), Kg + (size_t)(nk0 + r) * 64 + lc * 8);
                cp16(nV + SW_OFF(r, lc), Vg + (size_t)r * 1024 + nk0 + lc * 8);
            }
            cp_commit();
            cp_wait<1>();
        } else {
            cp_wait<0>();
        }
        __syncthreads(); /* S1 */

        /* ---- c2p band mma (64 new cols; 128 at kt==0), k-keyed stores ---- */
        if (kt == 0) {
            float acc[16][4];
#pragma unroll
            for (int i = 0; i < 16; i++)
#pragma unroll
                for (int j = 0; j < 4; j++) acc[i][j] = 0.f;
#pragma unroll
            for (int ks = 0; ks < 4; ks++) {
                uint32_t a[4];
                ldsm4(a, uQ + SW_OFF(wq0 + (lane & 15), ks * 2 + (lane >> 4)));
#pragma unroll
                for (int np = 0; np < 8; np++) {
                    uint32_t bq[4];
                    int srow = np * 16 + (((lane >> 4) & 1) << 3) + (lane & 7);
                    int slot = (w01 + srow) & 127;
                    ldsm4(bq, uB1 + SW_OFF(slot, ks * 2 + ((lane >> 3) & 1)));
                    mma16(acc[np * 2], a, bq);
                    mma16(acc[np * 2 + 1], a, bq + 2);
                }
            }
#pragma unroll
            for (int f = 0; f < 16; f++) {
                int col = f * 8 + q2 * 2;
                C2k[qiA * CRW + ((63 + qiA - col) & 127)] = __float2half_rn(acc[f][0]);
                C2k[qiA * CRW + ((62 + qiA - col) & 127)] = __float2half_rn(acc[f][1]);
                C2k[qiB * CRW + ((63 + qiB - col) & 127)] = __float2half_rn(acc[f][2]);
                C2k[qiB * CRW + ((62 + qiB - col) & 127)] = __float2half_rn(acc[f][3]);
            }
        } else {
            float acc[8][4];
#pragma unroll
            for (int i = 0; i < 8; i++)
#pragma unroll
                for (int j = 0; j < 4; j++) acc[i][j] = 0.f;
#pragma unroll
            for (int ks = 0; ks < 4; ks++) {
                uint32_t a[4];
                ldsm4(a, uQ + SW_OFF(wq0 + (lane & 15), ks * 2 + (lane >> 4)));
#pragma unroll
                for (int np = 0; np < 4; np++) {
                    uint32_t bq[4];
                    int srow = np * 16 + (((lane >> 4) & 1) << 3) + (lane & 7);
                    int slot = (w01 + srow) & 127;
                    ldsm4(bq, uB1 + SW_OFF(slot, ks * 2 + ((lane >> 3) & 1)));
                    mma16(acc[np * 2], a, bq);
                    mma16(acc[np * 2 + 1], a, bq + 2);
                }
            }
#pragma unroll
            for (int f = 0; f < 8; f++) {
                int col = f * 8 + q2 * 2;
                C2k[qiA * CRW + ((k0 + 63 + qiA - col) & 127)] = __float2half_rn(acc[f][0]);
                C2k[qiA * CRW + ((k0 + 62 + qiA - col) & 127)] = __float2half_rn(acc[f][1]);
                C2k[qiB * CRW + ((k0 + 63 + qiB - col) & 127)] = __float2half_rn(acc[f][2]);
                C2k[qiB * CRW + ((k0 + 62 + qiB - col) & 127)] = __float2half_rn(acc[f][3]);
            }
        }

        /* ---- p2c band mma: 5 needed ring groups; transposed store ---- */
        {
            float acc[10][4];
#pragma unroll
            for (int i = 0; i < 10; i++)
#pragma unroll
                for (int j = 0; j < 4; j++) acc[i][j] = 0.f;
#pragma unroll
            for (int ks = 0; ks < 4; ks++) {
                uint32_t a[4];
                ldsm4(a, uK + SW_OFF(wq0 + (lane & 15), ks * 2 + (lane >> 4)));
#pragma unroll
                for (int j = 0; j < 5; j++) {
                    uint32_t bq[4];
                    int srow = wq0 + j * 16 + (((lane >> 4) & 1) << 3) + (lane & 7);
                    int slot = (w02 + srow) & 127;
                    ldsm4(bq, uB2 + SW_OFF(slot, ks * 2 + ((lane >> 3) & 1)));
                    mma16(acc[j * 2], a, bq);
                    mma16(acc[j * 2 + 1], a, bq + 2);
                }
            }
#pragma unroll
            for (int f = 0; f < 10; f++) {
                int col = wq0 + (f >> 1) * 16 + (f & 1) * 8 + q2 * 2;
                int cA = col - qiA, cB = col - qiB;
                if ((unsigned)cA < 64u) P2t[cA * CW + qiA] = __float2half_rn(acc[f][0]);
                if ((unsigned)(cA + 1) < 64u) P2t[(cA + 1) * CW + qiA] = __float2half_rn(acc[f][1]);
                if ((unsigned)cB < 64u) P2t[cB * CW + qiB] = __float2half_rn(acc[f][2]);
                if ((unsigned)(cB + 1) < 64u) P2t[(cB + 1) * CW + qiB] = __float2half_rn(acc[f][3]);
            }
        }

        /* ---- QK mma ---- */
        float sS[8][4];
#pragma unroll
        for (int i = 0; i < 8; i++)
#pragma unroll
            for (int j = 0; j < 4; j++) sS[i][j] = 0.f;
#pragma unroll
        for (int ks = 0; ks < 4; ks++) {
            uint32_t a[4];
            ldsm4(a, uQ + SW_OFF(wq0 + (lane & 15), ks * 2 + (lane >> 4)));
#pragma unroll
            for (int np = 0; np < 4; np++) {
                uint32_t bq[4];
                int srow = np * 16 + (((lane >> 4) & 1) << 3) + (lane & 7);
                ldsm4(bq, uK + SW_OFF(srow, ks * 2 + ((lane >> 3) & 1)));
                mma16(sS[np * 2], a, bq);
                mma16(sS[np * 2 + 1], a, bq + 2);
            }
        }

        __syncthreads(); /* S2: ring reads + band stores visible */

        if (kt < 15) { /* refill 64 new ring rows per band */
            int nw01 = w01 - 64;
            int nw02b = w02 + 128;
#pragma unroll
            for (int i = 0; i < 4; i++) {
                int r = lr + 16 * i;
                int pv = nw01 + r;
                cp16(uB1 + SW_OFF(pv & 127, lc), PKg + (size_t)min(max(pv, 0), 1023) * 64 + lc * 8);
                int pv2 = nw02b + r;
                cp16(uB2 + SW_OFF(pv2 & 127, lc), PQg + (size_t)min(max(pv2, 0), 1023) * 64 + lc * 8);
            }
            cp_commit();
        }

        /* ---- fixup + direct exp into PV A fragments (no max, no P smem) ---- */
#pragma unroll
        for (int nst = 0; nst < 8; nst++) {
            int kj = nst * 8 + q2 * 2;
            float2 caf = __half22float2(*(__half2*)&C2k[qiA * CRW + ((k0 + kj) & 127)]);
            float2 cbf = __half22float2(*(__half2*)&C2k[qiB * CRW + ((k0 + kj) & 127)]);
            float2 paf = __half22float2(*(__half2*)&P2t[(63 - qiA) * CW + kj]);
            float2 pbf = __half22float2(*(__half2*)&P2t[(63 - qiB) * CW + kj]);
            sS[nst][0] += caf.x + paf.x;
            sS[nst][1] += caf.y + paf.y;
            sS[nst][2] += cbf.x + pbf.x;
            sS[nst][3] += cbf.y + pbf.y;
        }
        uint32_t e[4][4];
#pragma unroll
        for (int kc = 0; kc < 4; kc++) {
            e[kc][0] = ex2h2(sS[2 * kc][0], sS[2 * kc][1]);
            e[kc][1] = ex2h2(sS[2 * kc][2], sS[2 * kc][3]);
            e[kc][2] = ex2h2(sS[2 * kc + 1][0], sS[2 * kc + 1][1]);
            e[kc][3] = ex2h2(sS[2 * kc + 1][2], sS[2 * kc + 1][3]);
            float2 f0 = __half22float2(*(__half2*)&e[kc][0]);
            float2 f1 = __half22float2(*(__half2*)&e[kc][1]);
            float2 f2 = __half22float2(*(__half2*)&e[kc][2]);
            float2 f3 = __half22float2(*(__half2*)&e[kc][3]);
            lA += f0.x + f0.y + f2.x + f2.y;
            lB += f1.x + f1.y + f3.x + f3.y;
        }

        /* ---- PV mma: A fragments straight from registers ---- */
#pragma unroll
        for (int kc = 0; kc < 4; kc++) {
#pragma unroll
            for (int np = 0; np < 4; np++) {
                uint32_t bq[4];
                int srow = np * 16 + (((lane >> 4) & 1) << 3) + (lane & 7);
                ldsm4(bq, uV + SW_OFF(srow, kc * 2 + ((lane >> 3) & 1)));
                mma16(O[np * 2], e[kc], bq);
                mma16(O[np * 2 + 1], e[kc], bq + 2);
            }
        }
    }

    /* ---- deferred l reduction + epilogue ---- */
    lA += __shfl_xor_sync(0xffffffffu, lA, 1, 4);
    lA += __shfl_xor_sync(0xffffffffu, lA, 2, 4);
    lB += __shfl_xor_sync(0xffffffffu, lB, 1, 4);
    lB += __shfl_xor_sync(0xffffffffu, lB, 2, 4);
    float invA = 1.f / lA, invB = 1.f / lB;
    int qA = q0 + qiA, qB = q0 + qiB;
#pragma unroll
    for (int np = 0; np < 8; np++) {
        int d0 = h * 64 + np * 8 + q2 * 2;
        *(__half2*)&g_CTX[((size_t)(b * 1024) + qA) * 1024 + d0] =
            __floats2half2_rn(O[np][0] * invA, O[np][1] * invA);
        *(__half2*)&g_CTX[((size_t)(b * 1024) + qB) * 1024 + d0] =
            __floats2half2_rn(O[np][2] * invB, O[np][3] * invB);
    }
}

/* ---------------- LayerNorm ---------------- */
__global__ void __launch_bounds__(256) k_ln(const float* __restrict__ gam,
                                            const float* __restrict__ bet,
                                            float* __restrict__ out) {
    int m = blockIdx.x;
    int tid = threadIdx.x;
    const float* y = g_Y + (size_t)m * Hh;
    float4 v = *(const float4*)(y + (tid << 2));
    float s = v.x + v.y + v.z + v.w;
    float s2 = v.x * v.x + v.y * v.y + v.z * v.z + v.w * v.w;
#pragma unroll
    for (int o = 16; o; o >>= 1) {
        s += __shfl_xor_sync(0xffffffffu, s, o);
        s2 += __shfl_xor_sync(0xffffffffu, s2, o);
    }
    __shared__ float sh[8], sh2[8];
    int w = tid >> 5, ln = tid & 31;
    if (ln == 0) { sh[w] = s; sh2[w] = s2; }
    __syncthreads();
    s = 0.f; s2 = 0.f;
#pragma unroll
    for (int i = 0; i < 8; i++) { s += sh[i]; s2 += sh2[i]; }
    float mean = s * (1.0f / Hh);
    float var = s2 * (1.0f / Hh) - mean * mean;
    float inv = rsqrtf(var + 1e-7f);
    float4 g4 = *(const float4*)(gam + (tid << 2));
    float4 b4 = *(const float4*)(bet + (tid << 2));
    float4 o4;
    o4.x = g4.x * (v.x - mean) * inv + b4.x;
    o4.y = g4.y * (v.y - mean) * inv + b4.y;
    o4.z = g4.z * (v.z - mean) * inv + b4.z;
    o4.w = g4.w * (v.w - mean) * inv + b4.w;
    *(float4*)(out + (size_t)m * Hh + (tid << 2)) = o4;
}

/* ---------------- launch ---------------- */
extern "C" void kernel_launch(void* const* d_in, const int* in_sizes, int n_in,
                              void* d_out, int out_size) {
    const float* hs   = (const float*)d_in[0];
    const float* re   = (const float*)d_in[2];
    const float* w_in = (const float*)d_in[3];
    const float* qb   = (const float*)d_in[4];
    const float* vb   = (const float*)d_in[5];
    const float* w_pk = (const float*)d_in[6];
    const float* w_pq = (const float*)d_in[7];
    const float* b_pq = (const float*)d_in[8];
    const float* w_o  = (const float*)d_in[9];
    const float* b_o  = (const float*)d_in[10];
    const float* lng  = (const float*)d_in[11];
    const float* lnb  = (const float*)d_in[12];
    float* out = (float*)d_out;

    static int attr_set = 0;
    if (!attr_set) {
        cudaFuncSetAttribute(k_attn2, cudaFuncAttributeMaxDynamicSharedMemorySize, ATTN_SMEM);
        cudaFuncSetAttribute(gemm_all, cudaFuncAttributeMaxDynamicSharedMemorySize, 65536);
        attr_set = 1;
    }

    k_round2<<<5120, 256>>>(hs, re);                                        /* 1 */
    k_transp2<<<dim3(32, 32, 6), 256>>>(w_in, w_pk, w_pq, w_o, 0);          /* 2 */
    gemm_all<<<896, 256, 65536>>>(0, qb, vb, b_pq, b_o, hs);                /* 3 */
    k_attn2<<<dim3(16, 64), 128, ATTN_SMEM>>>();                            /* 4: profiled */
    gemm_all<<<256, 256, 65536>>>(4, qb, vb, b_pq, b_o, hs);                /* 5 */
    k_ln<<<4096, 256>>>(lng, lnb, out);                                     /* 6 */
}